// round 1
// baseline (speedup 1.0000x reference)
#include <cuda_runtime.h>
#include <cstdint>

// Problem constants
constexpr int NB   = 2;      // batch
constexpr int SEQ  = 2048;   // sequence
constexpr int HDIM = 2560;   // hidden
constexpr int NH   = 32;     // q heads
constexpr int NKV  = 8;      // kv heads
constexpr int HD   = 128;    // head dim
constexpr int GQ   = NH / NKV;

// Scratch (device globals -- no allocation allowed)
__device__ float g_q [(size_t)NB * SEQ * NH  * HD];  // (b,s,H,D)  64MB
__device__ float g_k [(size_t)NB * SEQ * NKV * HD];  // (b,s,KV,D) 16MB
__device__ float g_v [(size_t)NB * SEQ * NKV * HD];  // (b,s,KV,D) 16MB
__device__ float g_ao[(size_t)NB * SEQ * NH  * HD];  // (b,s,H,D)  64MB

// ---------------------------------------------------------------------------
// SGEMM: C[M,N] = A[M,K] @ B[N,K]^T   (A, B row-major; weights are (out,in))
// 128x128 tile, BK=8, 256 threads, 8x8 microtile.
// Requires M%128==0, N%128==0, K%8==0 (true for all four GEMMs here).
// ---------------------------------------------------------------------------
__global__ __launch_bounds__(256) void sgemm_nt(
    const float* __restrict__ A, const float* __restrict__ Bw,
    float* __restrict__ C, int M, int N, int K)
{
    __shared__ float As[8][128];
    __shared__ float Bs[8][128];

    const int tid = threadIdx.x;
    const int bm = blockIdx.y * 128;
    const int bn = blockIdx.x * 128;
    const int tx = tid & 15;
    const int ty = tid >> 4;
    const int lr = tid >> 1;           // 0..127
    const int lc = (tid & 1) * 4;      // 0 or 4

    const float* Ap = A  + (size_t)(bm + lr) * K + lc;
    const float* Bp = Bw + (size_t)(bn + lr) * K + lc;

    float acc[8][8];
#pragma unroll
    for (int i = 0; i < 8; i++)
#pragma unroll
        for (int j = 0; j < 8; j++) acc[i][j] = 0.f;

    for (int k0 = 0; k0 < K; k0 += 8) {
        float4 av = *(const float4*)(Ap + k0);
        float4 bv = *(const float4*)(Bp + k0);
        As[lc + 0][lr] = av.x; As[lc + 1][lr] = av.y;
        As[lc + 2][lr] = av.z; As[lc + 3][lr] = av.w;
        Bs[lc + 0][lr] = bv.x; Bs[lc + 1][lr] = bv.y;
        Bs[lc + 2][lr] = bv.z; Bs[lc + 3][lr] = bv.w;
        __syncthreads();

#pragma unroll
        for (int kk = 0; kk < 8; kk++) {
            float4 a0 = *(const float4*)&As[kk][ty * 8];
            float4 a1 = *(const float4*)&As[kk][ty * 8 + 4];
            float4 b0 = *(const float4*)&Bs[kk][tx * 8];
            float4 b1 = *(const float4*)&Bs[kk][tx * 8 + 4];
            float a[8] = {a0.x, a0.y, a0.z, a0.w, a1.x, a1.y, a1.z, a1.w};
            float b[8] = {b0.x, b0.y, b0.z, b0.w, b1.x, b1.y, b1.z, b1.w};
#pragma unroll
            for (int i = 0; i < 8; i++)
#pragma unroll
                for (int j = 0; j < 8; j++)
                    acc[i][j] += a[i] * b[j];
        }
        __syncthreads();
    }

#pragma unroll
    for (int i = 0; i < 8; i++) {
        float* cp = C + (size_t)(bm + ty * 8 + i) * N + bn + tx * 8;
        *(float4*)(cp)     = make_float4(acc[i][0], acc[i][1], acc[i][2], acc[i][3]);
        *(float4*)(cp + 4) = make_float4(acc[i][4], acc[i][5], acc[i][6], acc[i][7]);
    }
}

// ---------------------------------------------------------------------------
// Fused RMSNorm (over D=128) + RoPE (half-split). One warp per (b,s,head) row.
// in layout: (b, s, nh, D). out: same layout (transpose_out=0) or (b, nh, s, D).
// ---------------------------------------------------------------------------
__global__ __launch_bounds__(256) void norm_rope(
    const float* __restrict__ in, float* __restrict__ out,
    const float* __restrict__ cs, const float* __restrict__ sn,
    const float* __restrict__ gamma, int nh, int transpose_out)
{
    const int warp = (blockIdx.x * 256 + threadIdx.x) >> 5;
    const int lane = threadIdx.x & 31;
    const int h  = warp % nh;
    const int bs = warp / nh;          // bi*SEQ + sp
    const int sp = bs % SEQ;
    const int bi = bs / SEQ;

    const float* x = in + (size_t)warp * HD;
    float e0 = x[lane], e1 = x[lane + 32], e2 = x[lane + 64], e3 = x[lane + 96];

    float ssq = e0 * e0 + e1 * e1 + e2 * e2 + e3 * e3;
#pragma unroll
    for (int o = 16; o; o >>= 1) ssq += __shfl_xor_sync(0xffffffffu, ssq, o);
    const float r = rsqrtf(ssq * (1.0f / HD) + 1e-6f);

    e0 *= r * gamma[lane];      e1 *= r * gamma[lane + 32];
    e2 *= r * gamma[lane + 64]; e3 *= r * gamma[lane + 96];

    const float* cp = cs + (size_t)bs * HD;
    const float* sg = sn + (size_t)bs * HD;
    // d<64: x[d]*cos - x[d+64]*sin ;  d>=64: x[d]*cos + x[d-64]*sin
    const float o0 = e0 * cp[lane]      - e2 * sg[lane];
    const float o1 = e1 * cp[lane + 32] - e3 * sg[lane + 32];
    const float o2 = e2 * cp[lane + 64] + e0 * sg[lane + 64];
    const float o3 = e3 * cp[lane + 96] + e1 * sg[lane + 96];

    float* orow = transpose_out
        ? out + ((((size_t)bi * nh + h) * SEQ + sp) * HD)
        : out + (size_t)warp * HD;
    orow[lane] = o0; orow[lane + 32] = o1; orow[lane + 64] = o2; orow[lane + 96] = o3;
}

// ---------------------------------------------------------------------------
// V transpose: (b,s,KV,D) -> (b,KV,s,D), float4 granularity
// ---------------------------------------------------------------------------
__global__ __launch_bounds__(256) void v_transpose(
    const float4* __restrict__ in, float4* __restrict__ out)
{
    const size_t i = (size_t)blockIdx.x * 256 + threadIdx.x;  // quad index
    const int d4 = (int)(i & 31);
    const int kh = (int)((i >> 5) & (NKV - 1));
    const int sp = (int)((i >> 8) & (SEQ - 1));
    const int bi = (int)(i >> 19);
    float4 v = in[i];
    out[((((size_t)bi * NKV + kh) * SEQ + sp) << 5) + d4] = v;
}

// ---------------------------------------------------------------------------
// Causal flash attention (fp32).
// Q: (b,s,H,D) strided read; K,V: (b,KV,s,D); O: (b,s,H,D).
// BM=BN=64, 256 threads (16x16), 4x4 S microtile, 4x8 O accumulator.
// ---------------------------------------------------------------------------
constexpr int BM = 64;
constexpr int BN = 64;
constexpr int PQ = 132;   // smem pitch for Q/K/V tiles (floats)
constexpr int PP = 68;    // smem pitch for P tile
constexpr int ATTN_SMEM = (3 * BM * PQ + BM * PP) * 4;  // 118784 bytes

__global__ __launch_bounds__(256) void flash_attn(
    const float* __restrict__ Qp, const float* __restrict__ Kp,
    const float* __restrict__ Vp, float* __restrict__ Op)
{
    extern __shared__ float smx[];
    float* Qs = smx;
    float* Ks = smx +     BM * PQ;
    float* Vs = smx + 2 * BM * PQ;
    float* Ps = smx + 3 * BM * PQ;

    const int qtile = blockIdx.x;
    const int h     = blockIdx.y;
    const int bi    = blockIdx.z;
    const int kh    = h / GQ;
    const int tid   = threadIdx.x;
    const int tx    = tid & 15;
    const int ty    = tid >> 4;
    const int q0    = qtile * BM;

    const float* Qg = Qp + (((size_t)(bi * SEQ + q0) * NH + h) * HD);
    const float* Kg = Kp + (((size_t)(bi * NKV + kh) * SEQ) * HD);
    const float* Vg = Vp + (((size_t)(bi * NKV + kh) * SEQ) * HD);

    // load Q tile (64 x 128)
    for (int i = tid; i < BM * 32; i += 256) {
        int r = i >> 5, c4 = (i & 31) << 2;
        float4 v = *(const float4*)(Qg + (size_t)r * (NH * HD) + c4);
        *(float4*)&Qs[r * PQ + c4] = v;
    }

    float m[4], l[4], acc[4][8];
#pragma unroll
    for (int i = 0; i < 4; i++) {
        m[i] = -1e30f; l[i] = 0.f;
#pragma unroll
        for (int c = 0; c < 8; c++) acc[i][c] = 0.f;
    }

    const float scale = 0.08838834764831845f;  // 1/sqrt(128)
    const int ntiles = qtile + 1;               // causal: only tiles <= qtile

    for (int t = 0; t < ntiles; ++t) {
        const int k0 = t * BN;
        __syncthreads();
        for (int i = tid; i < BN * 32; i += 256) {
            int r = i >> 5, c4 = (i & 31) << 2;
            *(float4*)&Ks[r * PQ + c4] = *(const float4*)(Kg + (size_t)(k0 + r) * HD + c4);
            *(float4*)&Vs[r * PQ + c4] = *(const float4*)(Vg + (size_t)(k0 + r) * HD + c4);
        }
        __syncthreads();

        // S = Q @ K^T (4x4 per thread)
        float s[4][4];
#pragma unroll
        for (int i = 0; i < 4; i++)
#pragma unroll
            for (int j = 0; j < 4; j++) s[i][j] = 0.f;

#pragma unroll 4
        for (int k = 0; k < HD; k += 4) {
            float4 qv[4], kv[4];
#pragma unroll
            for (int i = 0; i < 4; i++) qv[i] = *(const float4*)&Qs[(ty * 4 + i) * PQ + k];
#pragma unroll
            for (int j = 0; j < 4; j++) kv[j] = *(const float4*)&Ks[(tx * 4 + j) * PQ + k];
#pragma unroll
            for (int i = 0; i < 4; i++)
#pragma unroll
                for (int j = 0; j < 4; j++)
                    s[i][j] += qv[i].x * kv[j].x + qv[i].y * kv[j].y
                             + qv[i].z * kv[j].z + qv[i].w * kv[j].w;
        }

#pragma unroll
        for (int i = 0; i < 4; i++)
#pragma unroll
            for (int j = 0; j < 4; j++) s[i][j] *= scale;

        if (t == qtile) {  // diagonal tile: causal mask
#pragma unroll
            for (int i = 0; i < 4; i++)
#pragma unroll
                for (int j = 0; j < 4; j++)
                    if (k0 + tx * 4 + j > q0 + ty * 4 + i) s[i][j] = -1e30f;
        }

        // online softmax
        float mx[4], al[4], rs[4];
#pragma unroll
        for (int i = 0; i < 4; i++)
            mx[i] = fmaxf(fmaxf(s[i][0], s[i][1]), fmaxf(s[i][2], s[i][3]));
#pragma unroll
        for (int o = 8; o; o >>= 1)
#pragma unroll
            for (int i = 0; i < 4; i++)
                mx[i] = fmaxf(mx[i], __shfl_xor_sync(0xffffffffu, mx[i], o));

#pragma unroll
        for (int i = 0; i < 4; i++) {
            float nm = fmaxf(m[i], mx[i]);
            al[i] = __expf(m[i] - nm);
            m[i] = nm;
        }

#pragma unroll
        for (int i = 0; i < 4; i++) {
            float e0 = __expf(s[i][0] - m[i]);
            float e1 = __expf(s[i][1] - m[i]);
            float e2 = __expf(s[i][2] - m[i]);
            float e3 = __expf(s[i][3] - m[i]);
            Ps[(ty * 4 + i) * PP + tx * 4 + 0] = e0;
            Ps[(ty * 4 + i) * PP + tx * 4 + 1] = e1;
            Ps[(ty * 4 + i) * PP + tx * 4 + 2] = e2;
            Ps[(ty * 4 + i) * PP + tx * 4 + 3] = e3;
            rs[i] = e0 + e1 + e2 + e3;
        }
#pragma unroll
        for (int o = 8; o; o >>= 1)
#pragma unroll
            for (int i = 0; i < 4; i++)
                rs[i] += __shfl_xor_sync(0xffffffffu, rs[i], o);

#pragma unroll
        for (int i = 0; i < 4; i++) {
            l[i] = l[i] * al[i] + rs[i];
#pragma unroll
            for (int c = 0; c < 8; c++) acc[i][c] *= al[i];
        }
        __syncthreads();

        // O += P @ V  (rows 4*ty.., cols tx*8..)
#pragma unroll 2
        for (int j = 0; j < BN; j++) {
            float p0 = Ps[(ty * 4 + 0) * PP + j];
            float p1 = Ps[(ty * 4 + 1) * PP + j];
            float p2 = Ps[(ty * 4 + 2) * PP + j];
            float p3 = Ps[(ty * 4 + 3) * PP + j];
            float4 v0 = *(const float4*)&Vs[j * PQ + tx * 8];
            float4 v1 = *(const float4*)&Vs[j * PQ + tx * 8 + 4];
            acc[0][0] += p0 * v0.x; acc[0][1] += p0 * v0.y; acc[0][2] += p0 * v0.z; acc[0][3] += p0 * v0.w;
            acc[0][4] += p0 * v1.x; acc[0][5] += p0 * v1.y; acc[0][6] += p0 * v1.z; acc[0][7] += p0 * v1.w;
            acc[1][0] += p1 * v0.x; acc[1][1] += p1 * v0.y; acc[1][2] += p1 * v0.z; acc[1][3] += p1 * v0.w;
            acc[1][4] += p1 * v1.x; acc[1][5] += p1 * v1.y; acc[1][6] += p1 * v1.z; acc[1][7] += p1 * v1.w;
            acc[2][0] += p2 * v0.x; acc[2][1] += p2 * v0.y; acc[2][2] += p2 * v0.z; acc[2][3] += p2 * v0.w;
            acc[2][4] += p2 * v1.x; acc[2][5] += p2 * v1.y; acc[2][6] += p2 * v1.z; acc[2][7] += p2 * v1.w;
            acc[3][0] += p3 * v0.x; acc[3][1] += p3 * v0.y; acc[3][2] += p3 * v0.z; acc[3][3] += p3 * v0.w;
            acc[3][4] += p3 * v1.x; acc[3][5] += p3 * v1.y; acc[3][6] += p3 * v1.z; acc[3][7] += p3 * v1.w;
        }
    }

    float* Og = Op + (((size_t)(bi * SEQ + q0) * NH + h) * HD);
#pragma unroll
    for (int i = 0; i < 4; i++) {
        const float inv = 1.0f / l[i];
        float4 o0 = make_float4(acc[i][0] * inv, acc[i][1] * inv, acc[i][2] * inv, acc[i][3] * inv);
        float4 o1 = make_float4(acc[i][4] * inv, acc[i][5] * inv, acc[i][6] * inv, acc[i][7] * inv);
        float* op = Og + (size_t)(ty * 4 + i) * (NH * HD) + tx * 8;
        *(float4*)(op)     = o0;
        *(float4*)(op + 4) = o1;
    }
}

// ---------------------------------------------------------------------------
// kernel_launch
// Output layout in d_out (fp32): [out (b,s,HID)] [new_k (b,KV,s,D)] [new_v ...]
// ---------------------------------------------------------------------------
extern "C" void kernel_launch(void* const* d_in, const int* in_sizes, int n_in,
                              void* d_out, int out_size)
{
    const float* hidden = (const float*)d_in[0];
    const float* cosb   = (const float*)d_in[1];
    const float* sinb   = (const float*)d_in[2];
    const float* wq     = (const float*)d_in[3];
    const float* wk     = (const float*)d_in[4];
    const float* wv     = (const float*)d_in[5];
    const float* wo     = (const float*)d_in[6];
    const float* qg     = (const float*)d_in[7];
    const float* kg     = (const float*)d_in[8];

    float* out  = (float*)d_out;
    float* kout = out  + (size_t)NB * SEQ * HDIM;
    float* vout = kout + (size_t)NB * NKV * SEQ * HD;

    float *qp, *kp, *vp, *aop;
    cudaGetSymbolAddress((void**)&qp,  g_q);
    cudaGetSymbolAddress((void**)&kp,  g_k);
    cudaGetSymbolAddress((void**)&vp,  g_v);
    cudaGetSymbolAddress((void**)&aop, g_ao);

    cudaFuncSetAttribute(flash_attn, cudaFuncAttributeMaxDynamicSharedMemorySize, ATTN_SMEM);

    // Projections: (b*s, HID) @ W^T
    sgemm_nt<<<dim3((NH  * HD) / 128, (NB * SEQ) / 128), 256>>>(hidden, wq, qp, NB * SEQ, NH  * HD, HDIM);
    sgemm_nt<<<dim3((NKV * HD) / 128, (NB * SEQ) / 128), 256>>>(hidden, wk, kp, NB * SEQ, NKV * HD, HDIM);
    sgemm_nt<<<dim3((NKV * HD) / 128, (NB * SEQ) / 128), 256>>>(hidden, wv, vp, NB * SEQ, NKV * HD, HDIM);

    // RMSNorm + RoPE (Q in place; K transposed straight into d_out's new_k)
    norm_rope<<<(NB * SEQ * NH ) / 8, 256>>>(qp, qp,   cosb, sinb, qg, NH,  0);
    norm_rope<<<(NB * SEQ * NKV) / 8, 256>>>(kp, kout, cosb, sinb, kg, NKV, 1);

    // V transpose into d_out's new_v
    v_transpose<<<(NB * SEQ * NKV * HD / 4) / 256, 256>>>((const float4*)vp, (float4*)vout);

    // Causal GQA flash attention; K/V read from d_out (already final)
    flash_attn<<<dim3(SEQ / BM, NH, NB), 256, ATTN_SMEM>>>(qp, kout, vout, aop);

    // Output projection
    sgemm_nt<<<dim3(HDIM / 128, (NB * SEQ) / 128), 256>>>(aop, wo, out, NB * SEQ, HDIM, NH * HD);
}

// round 2
// speedup vs baseline: 1.4503x; 1.4503x over previous
#include <cuda_runtime.h>
#include <cuda_bf16.h>
#include <cstdint>

// Problem constants
constexpr int NB   = 2;      // batch
constexpr int SEQ  = 2048;   // sequence
constexpr int HDIM = 2560;   // hidden
constexpr int NH   = 32;     // q heads
constexpr int NKV  = 8;      // kv heads
constexpr int HD   = 128;    // head dim
constexpr int GQ   = NH / NKV;
constexpr int MROWS = NB * SEQ;          // 4096
constexpr int NQKV  = (NH + 2 * NKV) * HD; // 6144
constexpr int QOFF  = 0;
constexpr int KOFF  = NH * HD;           // 4096
constexpr int VOFF  = (NH + NKV) * HD;   // 5120

// ---------------- device scratch (no allocation allowed) ----------------
__device__ __nv_bfloat16 g_hid_h [(size_t)MROWS * HDIM];
__device__ __nv_bfloat16 g_hid_l [(size_t)MROWS * HDIM];
__device__ __nv_bfloat16 g_wqkv_h[(size_t)NQKV * HDIM];
__device__ __nv_bfloat16 g_wqkv_l[(size_t)NQKV * HDIM];
__device__ __nv_bfloat16 g_wo_h  [(size_t)HDIM * NH * HD];
__device__ __nv_bfloat16 g_wo_l  [(size_t)HDIM * NH * HD];
__device__ __nv_bfloat16 g_ao_h  [(size_t)MROWS * NH * HD];
__device__ __nv_bfloat16 g_ao_l  [(size_t)MROWS * NH * HD];
__device__ float g_qkv[(size_t)MROWS * NQKV];       // 96MB
__device__ float g_ao [(size_t)MROWS * NH * HD];    // 64MB

// ---------------------------------------------------------------------------
// fp32 -> bf16 hi/lo split (x = hi + lo, error ~2^-18 |x|). 4 elems/thread.
// ---------------------------------------------------------------------------
__global__ __launch_bounds__(256) void split_bf16(
    const float4* __restrict__ in, __nv_bfloat16* __restrict__ hi,
    __nv_bfloat16* __restrict__ lo)
{
    const size_t i = (size_t)blockIdx.x * 256 + threadIdx.x;
    float4 x = in[i];
    __nv_bfloat16 h[4], l[4];
    float xs[4] = {x.x, x.y, x.z, x.w};
#pragma unroll
    for (int j = 0; j < 4; j++) {
        h[j] = __float2bfloat16(xs[j]);
        l[j] = __float2bfloat16(xs[j] - __bfloat162float(h[j]));
    }
    *(uint2*)&hi[i * 4] = *(uint2*)h;
    *(uint2*)&lo[i * 4] = *(uint2*)l;
}

// ---------------------------------------------------------------------------
// bf16-split tensor-core GEMM: C[M,N] = A[M,K] @ B[N,K]^T   (fp32 accurate)
// A,B given as hi/lo bf16 pairs. 3 MMAs per tile: Ah*Bh + Ah*Bl + Al*Bh.
// Block 128x128, BK=32, 256 threads = 8 warps (4 in M x 2 in N; 32x64 each).
// ---------------------------------------------------------------------------
constexpr int GPAD = 40;   // smem row pitch in bf16 (80B: 8-row LDS conflict-free)

__device__ __forceinline__ void mma16816(float* c, const uint32_t* a, const uint32_t* b)
{
    asm volatile(
        "mma.sync.aligned.m16n8k16.row.col.f32.bf16.bf16.f32 "
        "{%0,%1,%2,%3}, {%4,%5,%6,%7}, {%8,%9}, {%0,%1,%2,%3};"
        : "+f"(c[0]), "+f"(c[1]), "+f"(c[2]), "+f"(c[3])
        : "r"(a[0]), "r"(a[1]), "r"(a[2]), "r"(a[3]), "r"(b[0]), "r"(b[1]));
}

__global__ __launch_bounds__(256) void gemm_bf16x2(
    const __nv_bfloat16* __restrict__ Ah, const __nv_bfloat16* __restrict__ Al,
    const __nv_bfloat16* __restrict__ Bh, const __nv_bfloat16* __restrict__ Bl,
    float* __restrict__ C, int M, int N, int K)
{
    __shared__ __nv_bfloat16 sAh[128 * GPAD];
    __shared__ __nv_bfloat16 sAl[128 * GPAD];
    __shared__ __nv_bfloat16 sBh[128 * GPAD];
    __shared__ __nv_bfloat16 sBl[128 * GPAD];

    const int tid = threadIdx.x;
    const int bm = blockIdx.y * 128;
    const int bn = blockIdx.x * 128;
    const int lane = tid & 31;
    const int wid  = tid >> 5;
    const int wm = (wid & 3) * 32;   // warp M offset in tile
    const int wn = (wid >> 2) * 64;  // warp N offset in tile
    const int grp = lane >> 2;       // 0..7
    const int tig = lane & 3;        // 0..3

    // 16-byte chunks for global->smem: 512 chunks/tile, 2 per thread
    const int r0 = tid >> 2,          o0 = (tid & 3) * 8;
    const int r1 = (tid + 256) >> 2,  o1 = (tid & 3) * 8;

    float acc[2][8][4];
#pragma unroll
    for (int mt = 0; mt < 2; mt++)
#pragma unroll
        for (int nt = 0; nt < 8; nt++)
#pragma unroll
            for (int e = 0; e < 4; e++) acc[mt][nt][e] = 0.f;

    for (int k0 = 0; k0 < K; k0 += 32) {
        *(uint4*)&sAh[r0 * GPAD + o0] = *(const uint4*)&Ah[(size_t)(bm + r0) * K + k0 + o0];
        *(uint4*)&sAh[r1 * GPAD + o1] = *(const uint4*)&Ah[(size_t)(bm + r1) * K + k0 + o1];
        *(uint4*)&sAl[r0 * GPAD + o0] = *(const uint4*)&Al[(size_t)(bm + r0) * K + k0 + o0];
        *(uint4*)&sAl[r1 * GPAD + o1] = *(const uint4*)&Al[(size_t)(bm + r1) * K + k0 + o1];
        *(uint4*)&sBh[r0 * GPAD + o0] = *(const uint4*)&Bh[(size_t)(bn + r0) * K + k0 + o0];
        *(uint4*)&sBh[r1 * GPAD + o1] = *(const uint4*)&Bh[(size_t)(bn + r1) * K + k0 + o1];
        *(uint4*)&sBl[r0 * GPAD + o0] = *(const uint4*)&Bl[(size_t)(bn + r0) * K + k0 + o0];
        *(uint4*)&sBl[r1 * GPAD + o1] = *(const uint4*)&Bl[(size_t)(bn + r1) * K + k0 + o1];
        __syncthreads();

#pragma unroll
        for (int kk = 0; kk < 32; kk += 16) {
            uint32_t afh[2][4], afl[2][4];
#pragma unroll
            for (int mt = 0; mt < 2; mt++) {
                const int ra = wm + mt * 16 + grp;
                const int ca = kk + tig * 2;
                afh[mt][0] = *(const uint32_t*)&sAh[(ra    ) * GPAD + ca    ];
                afh[mt][1] = *(const uint32_t*)&sAh[(ra + 8) * GPAD + ca    ];
                afh[mt][2] = *(const uint32_t*)&sAh[(ra    ) * GPAD + ca + 8];
                afh[mt][3] = *(const uint32_t*)&sAh[(ra + 8) * GPAD + ca + 8];
                afl[mt][0] = *(const uint32_t*)&sAl[(ra    ) * GPAD + ca    ];
                afl[mt][1] = *(const uint32_t*)&sAl[(ra + 8) * GPAD + ca    ];
                afl[mt][2] = *(const uint32_t*)&sAl[(ra    ) * GPAD + ca + 8];
                afl[mt][3] = *(const uint32_t*)&sAl[(ra + 8) * GPAD + ca + 8];
            }
#pragma unroll
            for (int nt = 0; nt < 8; nt++) {
                const int rb = wn + nt * 8 + grp;
                const int cb = kk + tig * 2;
                uint32_t bh[2], bl[2];
                bh[0] = *(const uint32_t*)&sBh[rb * GPAD + cb    ];
                bh[1] = *(const uint32_t*)&sBh[rb * GPAD + cb + 8];
                bl[0] = *(const uint32_t*)&sBl[rb * GPAD + cb    ];
                bl[1] = *(const uint32_t*)&sBl[rb * GPAD + cb + 8];
#pragma unroll
                for (int mt = 0; mt < 2; mt++) {
                    mma16816(acc[mt][nt], afh[mt], bh);
                    mma16816(acc[mt][nt], afh[mt], bl);
                    mma16816(acc[mt][nt], afl[mt], bh);
                }
            }
        }
        __syncthreads();
    }

#pragma unroll
    for (int mt = 0; mt < 2; mt++) {
        const int row = bm + wm + mt * 16 + grp;
#pragma unroll
        for (int nt = 0; nt < 8; nt++) {
            const int col = bn + wn + nt * 8 + tig * 2;
            *(float2*)&C[(size_t)row * N + col]       = make_float2(acc[mt][nt][0], acc[mt][nt][1]);
            *(float2*)&C[(size_t)(row + 8) * N + col] = make_float2(acc[mt][nt][2], acc[mt][nt][3]);
        }
    }
}

// ---------------------------------------------------------------------------
// Fused RMSNorm (over D=128) + RoPE (half-split). One warp per (b,s,head) row.
// in: row bs at in + bs*ldin + col0 + h*HD.  out: in-place (transpose_out=0)
// or transposed to (b, nh, s, D).
// ---------------------------------------------------------------------------
__global__ __launch_bounds__(256) void norm_rope(
    const float* __restrict__ in, float* __restrict__ out,
    const float* __restrict__ cs, const float* __restrict__ sn,
    const float* __restrict__ gamma, int nh, int ldin, int col0, int transpose_out)
{
    const int warp = (blockIdx.x * 256 + threadIdx.x) >> 5;
    const int lane = threadIdx.x & 31;
    const int h  = warp % nh;
    const int bs = warp / nh;          // bi*SEQ + sp
    const int sp = bs % SEQ;
    const int bi = bs / SEQ;

    const float* x = in + (size_t)bs * ldin + col0 + h * HD;
    float e0 = x[lane], e1 = x[lane + 32], e2 = x[lane + 64], e3 = x[lane + 96];

    float ssq = e0 * e0 + e1 * e1 + e2 * e2 + e3 * e3;
#pragma unroll
    for (int o = 16; o; o >>= 1) ssq += __shfl_xor_sync(0xffffffffu, ssq, o);
    const float r = rsqrtf(ssq * (1.0f / HD) + 1e-6f);

    e0 *= r * gamma[lane];      e1 *= r * gamma[lane + 32];
    e2 *= r * gamma[lane + 64]; e3 *= r * gamma[lane + 96];

    const float* cp = cs + (size_t)bs * HD;
    const float* sg = sn + (size_t)bs * HD;
    const float o0 = e0 * cp[lane]      - e2 * sg[lane];
    const float o1 = e1 * cp[lane + 32] - e3 * sg[lane + 32];
    const float o2 = e2 * cp[lane + 64] + e0 * sg[lane + 64];
    const float o3 = e3 * cp[lane + 96] + e1 * sg[lane + 96];

    float* orow = transpose_out
        ? out + ((((size_t)bi * nh + h) * SEQ + sp) * HD)
        : out + ((size_t)bs * ldin + col0 + h * HD);
    orow[lane] = o0; orow[lane + 32] = o1; orow[lane + 64] = o2; orow[lane + 96] = o3;
}

// ---------------------------------------------------------------------------
// V transpose out of qkv: (b,s)[VOFF + kv*D] -> (b,KV,s,D), float4 granularity
// ---------------------------------------------------------------------------
__global__ __launch_bounds__(256) void v_transpose(
    const float4* __restrict__ qkv4, float4* __restrict__ out)
{
    const size_t i = (size_t)blockIdx.x * 256 + threadIdx.x;  // quad index
    const int d4 = (int)(i & 31);
    const int kh = (int)((i >> 5) & (NKV - 1));
    const int sp = (int)((i >> 8) & (SEQ - 1));
    const int bi = (int)(i >> 19);
    const size_t src = ((size_t)(bi * SEQ + sp) * NQKV + VOFF + kh * HD) / 4 + d4;
    const size_t dst = (((size_t)(bi * NKV + kh) * SEQ + sp) << 5) + d4;
    out[dst] = qkv4[src];
}

// ---------------------------------------------------------------------------
// Causal flash attention (fp32).
// Q rows at Qp + (bi*SEQ+q)*ldq + h*HD; K,V: (b,KV,s,D); O: (b,s,H,D).
// BM=BN=64, 256 threads (16x16), 4x4 S microtile, 4x8 O accumulator.
// ---------------------------------------------------------------------------
constexpr int BM = 64;
constexpr int BN = 64;
constexpr int PQ = 132;   // smem pitch for Q/K/V tiles (floats)
constexpr int PP = 68;    // smem pitch for P tile
constexpr int ATTN_SMEM = (3 * BM * PQ + BM * PP) * 4;  // 118784 bytes

__global__ __launch_bounds__(256) void flash_attn(
    const float* __restrict__ Qp, const float* __restrict__ Kp,
    const float* __restrict__ Vp, float* __restrict__ Op, int ldq)
{
    extern __shared__ float smx[];
    float* Qs = smx;
    float* Ks = smx +     BM * PQ;
    float* Vs = smx + 2 * BM * PQ;
    float* Ps = smx + 3 * BM * PQ;

    const int qtile = blockIdx.x;
    const int h     = blockIdx.y;
    const int bi    = blockIdx.z;
    const int kh    = h / GQ;
    const int tid   = threadIdx.x;
    const int tx    = tid & 15;
    const int ty    = tid >> 4;
    const int q0    = qtile * BM;

    const float* Qg = Qp + ((size_t)(bi * SEQ + q0) * ldq + h * HD);
    const float* Kg = Kp + (((size_t)(bi * NKV + kh) * SEQ) * HD);
    const float* Vg = Vp + (((size_t)(bi * NKV + kh) * SEQ) * HD);

    for (int i = tid; i < BM * 32; i += 256) {
        int r = i >> 5, c4 = (i & 31) << 2;
        float4 v = *(const float4*)(Qg + (size_t)r * ldq + c4);
        *(float4*)&Qs[r * PQ + c4] = v;
    }

    float m[4], l[4], acc[4][8];
#pragma unroll
    for (int i = 0; i < 4; i++) {
        m[i] = -1e30f; l[i] = 0.f;
#pragma unroll
        for (int c = 0; c < 8; c++) acc[i][c] = 0.f;
    }

    const float scale = 0.08838834764831845f;  // 1/sqrt(128)
    const int ntiles = qtile + 1;               // causal

    for (int t = 0; t < ntiles; ++t) {
        const int k0 = t * BN;
        __syncthreads();
        for (int i = tid; i < BN * 32; i += 256) {
            int r = i >> 5, c4 = (i & 31) << 2;
            *(float4*)&Ks[r * PQ + c4] = *(const float4*)(Kg + (size_t)(k0 + r) * HD + c4);
            *(float4*)&Vs[r * PQ + c4] = *(const float4*)(Vg + (size_t)(k0 + r) * HD + c4);
        }
        __syncthreads();

        float s[4][4];
#pragma unroll
        for (int i = 0; i < 4; i++)
#pragma unroll
            for (int j = 0; j < 4; j++) s[i][j] = 0.f;

#pragma unroll 4
        for (int k = 0; k < HD; k += 4) {
            float4 qv[4], kv[4];
#pragma unroll
            for (int i = 0; i < 4; i++) qv[i] = *(const float4*)&Qs[(ty * 4 + i) * PQ + k];
#pragma unroll
            for (int j = 0; j < 4; j++) kv[j] = *(const float4*)&Ks[(tx * 4 + j) * PQ + k];
#pragma unroll
            for (int i = 0; i < 4; i++)
#pragma unroll
                for (int j = 0; j < 4; j++)
                    s[i][j] += qv[i].x * kv[j].x + qv[i].y * kv[j].y
                             + qv[i].z * kv[j].z + qv[i].w * kv[j].w;
        }

#pragma unroll
        for (int i = 0; i < 4; i++)
#pragma unroll
            for (int j = 0; j < 4; j++) s[i][j] *= scale;

        if (t == qtile) {
#pragma unroll
            for (int i = 0; i < 4; i++)
#pragma unroll
                for (int j = 0; j < 4; j++)
                    if (k0 + tx * 4 + j > q0 + ty * 4 + i) s[i][j] = -1e30f;
        }

        float mx[4], al[4], rs[4];
#pragma unroll
        for (int i = 0; i < 4; i++)
            mx[i] = fmaxf(fmaxf(s[i][0], s[i][1]), fmaxf(s[i][2], s[i][3]));
#pragma unroll
        for (int o = 8; o; o >>= 1)
#pragma unroll
            for (int i = 0; i < 4; i++)
                mx[i] = fmaxf(mx[i], __shfl_xor_sync(0xffffffffu, mx[i], o));

#pragma unroll
        for (int i = 0; i < 4; i++) {
            float nm = fmaxf(m[i], mx[i]);
            al[i] = __expf(m[i] - nm);
            m[i] = nm;
        }

#pragma unroll
        for (int i = 0; i < 4; i++) {
            float e0 = __expf(s[i][0] - m[i]);
            float e1 = __expf(s[i][1] - m[i]);
            float e2 = __expf(s[i][2] - m[i]);
            float e3 = __expf(s[i][3] - m[i]);
            Ps[(ty * 4 + i) * PP + tx * 4 + 0] = e0;
            Ps[(ty * 4 + i) * PP + tx * 4 + 1] = e1;
            Ps[(ty * 4 + i) * PP + tx * 4 + 2] = e2;
            Ps[(ty * 4 + i) * PP + tx * 4 + 3] = e3;
            rs[i] = e0 + e1 + e2 + e3;
        }
#pragma unroll
        for (int o = 8; o; o >>= 1)
#pragma unroll
            for (int i = 0; i < 4; i++)
                rs[i] += __shfl_xor_sync(0xffffffffu, rs[i], o);

#pragma unroll
        for (int i = 0; i < 4; i++) {
            l[i] = l[i] * al[i] + rs[i];
#pragma unroll
            for (int c = 0; c < 8; c++) acc[i][c] *= al[i];
        }
        __syncthreads();

#pragma unroll 2
        for (int j = 0; j < BN; j++) {
            float p0 = Ps[(ty * 4 + 0) * PP + j];
            float p1 = Ps[(ty * 4 + 1) * PP + j];
            float p2 = Ps[(ty * 4 + 2) * PP + j];
            float p3 = Ps[(ty * 4 + 3) * PP + j];
            float4 v0 = *(const float4*)&Vs[j * PQ + tx * 8];
            float4 v1 = *(const float4*)&Vs[j * PQ + tx * 8 + 4];
            acc[0][0] += p0 * v0.x; acc[0][1] += p0 * v0.y; acc[0][2] += p0 * v0.z; acc[0][3] += p0 * v0.w;
            acc[0][4] += p0 * v1.x; acc[0][5] += p0 * v1.y; acc[0][6] += p0 * v1.z; acc[0][7] += p0 * v1.w;
            acc[1][0] += p1 * v0.x; acc[1][1] += p1 * v0.y; acc[1][2] += p1 * v0.z; acc[1][3] += p1 * v0.w;
            acc[1][4] += p1 * v1.x; acc[1][5] += p1 * v1.y; acc[1][6] += p1 * v1.z; acc[1][7] += p1 * v1.w;
            acc[2][0] += p2 * v0.x; acc[2][1] += p2 * v0.y; acc[2][2] += p2 * v0.z; acc[2][3] += p2 * v0.w;
            acc[2][4] += p2 * v1.x; acc[2][5] += p2 * v1.y; acc[2][6] += p2 * v1.z; acc[2][7] += p2 * v1.w;
            acc[3][0] += p3 * v0.x; acc[3][1] += p3 * v0.y; acc[3][2] += p3 * v0.z; acc[3][3] += p3 * v0.w;
            acc[3][4] += p3 * v1.x; acc[3][5] += p3 * v1.y; acc[3][6] += p3 * v1.z; acc[3][7] += p3 * v1.w;
        }
    }

    float* Og = Op + (((size_t)(bi * SEQ + q0) * NH + h) * HD);
#pragma unroll
    for (int i = 0; i < 4; i++) {
        const float inv = 1.0f / l[i];
        float4 o0 = make_float4(acc[i][0] * inv, acc[i][1] * inv, acc[i][2] * inv, acc[i][3] * inv);
        float4 o1 = make_float4(acc[i][4] * inv, acc[i][5] * inv, acc[i][6] * inv, acc[i][7] * inv);
        float* op = Og + (size_t)(ty * 4 + i) * (NH * HD) + tx * 8;
        *(float4*)(op)     = o0;
        *(float4*)(op + 4) = o1;
    }
}

// ---------------------------------------------------------------------------
// kernel_launch
// Output layout in d_out (fp32): [out (b,s,HID)] [new_k (b,KV,s,D)] [new_v ...]
// ---------------------------------------------------------------------------
extern "C" void kernel_launch(void* const* d_in, const int* in_sizes, int n_in,
                              void* d_out, int out_size)
{
    const float* hidden = (const float*)d_in[0];
    const float* cosb   = (const float*)d_in[1];
    const float* sinb   = (const float*)d_in[2];
    const float* wq     = (const float*)d_in[3];
    const float* wk     = (const float*)d_in[4];
    const float* wv     = (const float*)d_in[5];
    const float* wo     = (const float*)d_in[6];
    const float* qg     = (const float*)d_in[7];
    const float* kg     = (const float*)d_in[8];

    float* out  = (float*)d_out;
    float* kout = out  + (size_t)NB * SEQ * HDIM;
    float* vout = kout + (size_t)NB * NKV * SEQ * HD;

    __nv_bfloat16 *hidh, *hidl, *wqkvh, *wqkvl, *woh, *wol, *aoh, *aol;
    float *qkv, *ao;
    cudaGetSymbolAddress((void**)&hidh,  g_hid_h);
    cudaGetSymbolAddress((void**)&hidl,  g_hid_l);
    cudaGetSymbolAddress((void**)&wqkvh, g_wqkv_h);
    cudaGetSymbolAddress((void**)&wqkvl, g_wqkv_l);
    cudaGetSymbolAddress((void**)&woh,   g_wo_h);
    cudaGetSymbolAddress((void**)&wol,   g_wo_l);
    cudaGetSymbolAddress((void**)&aoh,   g_ao_h);
    cudaGetSymbolAddress((void**)&aol,   g_ao_l);
    cudaGetSymbolAddress((void**)&qkv,   g_qkv);
    cudaGetSymbolAddress((void**)&ao,    g_ao);

    cudaFuncSetAttribute(flash_attn, cudaFuncAttributeMaxDynamicSharedMemorySize, ATTN_SMEM);

    // fp32 -> bf16 hi/lo splits
    const size_t nHid = (size_t)MROWS * HDIM;        // 10485760
    const size_t nWq  = (size_t)NH  * HD * HDIM;     // 10485760
    const size_t nWk  = (size_t)NKV * HD * HDIM;     // 2621440
    split_bf16<<<(int)(nHid / 1024), 256>>>((const float4*)hidden, hidh, hidl);
    split_bf16<<<(int)(nWq  / 1024), 256>>>((const float4*)wq, wqkvh, wqkvl);
    split_bf16<<<(int)(nWk  / 1024), 256>>>((const float4*)wk, wqkvh + nWq, wqkvl + nWq);
    split_bf16<<<(int)(nWk  / 1024), 256>>>((const float4*)wv, wqkvh + nWq + nWk, wqkvl + nWq + nWk);
    split_bf16<<<(int)(nWq  / 1024), 256>>>((const float4*)wo, woh, wol);

    // Fused QKV projection: (4096 x 2560) @ (6144 x 2560)^T -> qkv (4096 x 6144)
    gemm_bf16x2<<<dim3(NQKV / 128, MROWS / 128), 256>>>(
        hidh, hidl, wqkvh, wqkvl, qkv, MROWS, NQKV, HDIM);

    // RMSNorm + RoPE (Q in place inside qkv; K transposed into d_out's new_k)
    norm_rope<<<(MROWS * NH ) / 8, 256>>>(qkv, qkv,  cosb, sinb, qg, NH,  NQKV, QOFF, 0);
    norm_rope<<<(MROWS * NKV) / 8, 256>>>(qkv, kout, cosb, sinb, kg, NKV, NQKV, KOFF, 1);

    // V transpose into d_out's new_v
    v_transpose<<<(NB * SEQ * NKV * HD / 4) / 256, 256>>>((const float4*)qkv, (float4*)vout);

    // Causal GQA flash attention; Q strided inside qkv; K/V from d_out
    flash_attn<<<dim3(SEQ / BM, NH, NB), 256, ATTN_SMEM>>>(qkv, kout, vout, ao, NQKV);

    // Output projection: split ao, then (4096 x 4096) @ (2560 x 4096)^T
    split_bf16<<<(int)(((size_t)MROWS * NH * HD) / 1024), 256>>>((const float4*)ao, aoh, aol);
    gemm_bf16x2<<<dim3(HDIM / 128, MROWS / 128), 256>>>(
        aoh, aol, woh, wol, out, MROWS, HDIM, NH * HD);
}

// round 3
// speedup vs baseline: 2.7176x; 1.8738x over previous
#include <cuda_runtime.h>
#include <cuda_bf16.h>
#include <cstdint>

// Problem constants
constexpr int NB   = 2;      // batch
constexpr int SEQ  = 2048;   // sequence
constexpr int HDIM = 2560;   // hidden
constexpr int NH   = 32;     // q heads
constexpr int NKV  = 8;      // kv heads
constexpr int HD   = 128;    // head dim
constexpr int GQ   = NH / NKV;
constexpr int MROWS = NB * SEQ;            // 4096
constexpr int NQKV  = (NH + 2 * NKV) * HD; // 6144
constexpr int KOFF  = NH * HD;             // 4096
constexpr int VOFF  = (NH + NKV) * HD;     // 5120
constexpr float SM_SCALE = 0.08838834764831845f;  // 1/sqrt(128)

// ---------------- device scratch (no allocation allowed) ----------------
__device__ __nv_bfloat16 g_hid_h [(size_t)MROWS * HDIM];
__device__ __nv_bfloat16 g_hid_l [(size_t)MROWS * HDIM];
__device__ __nv_bfloat16 g_wqkv_h[(size_t)NQKV * HDIM];
__device__ __nv_bfloat16 g_wqkv_l[(size_t)NQKV * HDIM];
__device__ __nv_bfloat16 g_wo_h  [(size_t)HDIM * NH * HD];
__device__ __nv_bfloat16 g_wo_l  [(size_t)HDIM * NH * HD];
__device__ __nv_bfloat16 g_ao_h  [(size_t)MROWS * NH * HD];
__device__ __nv_bfloat16 g_ao_l  [(size_t)MROWS * NH * HD];
__device__ float g_qkv[(size_t)MROWS * NQKV];       // 96MB
// bf16 hi/lo attention operands
__device__ __nv_bfloat16 g_qh[(size_t)NB * NH  * SEQ * HD];  // (b,H,s,D), pre-scaled
__device__ __nv_bfloat16 g_ql[(size_t)NB * NH  * SEQ * HD];
__device__ __nv_bfloat16 g_kh[(size_t)NB * NKV * SEQ * HD];  // (b,KV,s,D)
__device__ __nv_bfloat16 g_kl[(size_t)NB * NKV * SEQ * HD];
__device__ __nv_bfloat16 g_vh[(size_t)NB * NKV * HD * SEQ];  // (b,KV,D,s) transposed
__device__ __nv_bfloat16 g_vl[(size_t)NB * NKV * HD * SEQ];

// ---------------------------------------------------------------------------
// fp32 -> bf16 hi/lo split
// ---------------------------------------------------------------------------
__global__ __launch_bounds__(256) void split_bf16(
    const float4* __restrict__ in, __nv_bfloat16* __restrict__ hi,
    __nv_bfloat16* __restrict__ lo)
{
    const size_t i = (size_t)blockIdx.x * 256 + threadIdx.x;
    float4 x = in[i];
    __nv_bfloat16 h[4], l[4];
    float xs[4] = {x.x, x.y, x.z, x.w};
#pragma unroll
    for (int j = 0; j < 4; j++) {
        h[j] = __float2bfloat16(xs[j]);
        l[j] = __float2bfloat16(xs[j] - __bfloat162float(h[j]));
    }
    *(uint2*)&hi[i * 4] = *(uint2*)h;
    *(uint2*)&lo[i * 4] = *(uint2*)l;
}

// ---------------------------------------------------------------------------
// mma.m16n8k16 bf16 wrapper
// ---------------------------------------------------------------------------
__device__ __forceinline__ void mma16816(float* c, const uint32_t* a, const uint32_t* b)
{
    asm volatile(
        "mma.sync.aligned.m16n8k16.row.col.f32.bf16.bf16.f32 "
        "{%0,%1,%2,%3}, {%4,%5,%6,%7}, {%8,%9}, {%0,%1,%2,%3};"
        : "+f"(c[0]), "+f"(c[1]), "+f"(c[2]), "+f"(c[3])
        : "r"(a[0]), "r"(a[1]), "r"(a[2]), "r"(a[3]), "r"(b[0]), "r"(b[1]));
}

__device__ __forceinline__ uint32_t pack_hilo(float x, float y, uint32_t& lo)
{
    __nv_bfloat162 h = __float22bfloat162_rn(make_float2(x, y));
    float rx = x - __bfloat162float(h.x);
    float ry = y - __bfloat162float(h.y);
    __nv_bfloat162 l = __float22bfloat162_rn(make_float2(rx, ry));
    lo = *(uint32_t*)&l;
    return *(uint32_t*)&h;
}

// ---------------------------------------------------------------------------
// bf16-split tensor-core GEMM: C[M,N] = A[M,K] @ B[N,K]^T   (fp32 accurate)
// ---------------------------------------------------------------------------
constexpr int GPAD = 40;

__global__ __launch_bounds__(256) void gemm_bf16x2(
    const __nv_bfloat16* __restrict__ Ah, const __nv_bfloat16* __restrict__ Al,
    const __nv_bfloat16* __restrict__ Bh, const __nv_bfloat16* __restrict__ Bl,
    float* __restrict__ C, int M, int N, int K)
{
    __shared__ __nv_bfloat16 sAh[128 * GPAD];
    __shared__ __nv_bfloat16 sAl[128 * GPAD];
    __shared__ __nv_bfloat16 sBh[128 * GPAD];
    __shared__ __nv_bfloat16 sBl[128 * GPAD];

    const int tid = threadIdx.x;
    const int bm = blockIdx.y * 128;
    const int bn = blockIdx.x * 128;
    const int lane = tid & 31;
    const int wid  = tid >> 5;
    const int wm = (wid & 3) * 32;
    const int wn = (wid >> 2) * 64;
    const int grp = lane >> 2;
    const int tig = lane & 3;

    const int r0 = tid >> 2,          o0 = (tid & 3) * 8;
    const int r1 = (tid + 256) >> 2,  o1 = (tid & 3) * 8;

    float acc[2][8][4];
#pragma unroll
    for (int mt = 0; mt < 2; mt++)
#pragma unroll
        for (int nt = 0; nt < 8; nt++)
#pragma unroll
            for (int e = 0; e < 4; e++) acc[mt][nt][e] = 0.f;

    for (int k0 = 0; k0 < K; k0 += 32) {
        *(uint4*)&sAh[r0 * GPAD + o0] = *(const uint4*)&Ah[(size_t)(bm + r0) * K + k0 + o0];
        *(uint4*)&sAh[r1 * GPAD + o1] = *(const uint4*)&Ah[(size_t)(bm + r1) * K + k0 + o1];
        *(uint4*)&sAl[r0 * GPAD + o0] = *(const uint4*)&Al[(size_t)(bm + r0) * K + k0 + o0];
        *(uint4*)&sAl[r1 * GPAD + o1] = *(const uint4*)&Al[(size_t)(bm + r1) * K + k0 + o1];
        *(uint4*)&sBh[r0 * GPAD + o0] = *(const uint4*)&Bh[(size_t)(bn + r0) * K + k0 + o0];
        *(uint4*)&sBh[r1 * GPAD + o1] = *(const uint4*)&Bh[(size_t)(bn + r1) * K + k0 + o1];
        *(uint4*)&sBl[r0 * GPAD + o0] = *(const uint4*)&Bl[(size_t)(bn + r0) * K + k0 + o0];
        *(uint4*)&sBl[r1 * GPAD + o1] = *(const uint4*)&Bl[(size_t)(bn + r1) * K + k0 + o1];
        __syncthreads();

#pragma unroll
        for (int kk = 0; kk < 32; kk += 16) {
            uint32_t afh[2][4], afl[2][4];
#pragma unroll
            for (int mt = 0; mt < 2; mt++) {
                const int ra = wm + mt * 16 + grp;
                const int ca = kk + tig * 2;
                afh[mt][0] = *(const uint32_t*)&sAh[(ra    ) * GPAD + ca    ];
                afh[mt][1] = *(const uint32_t*)&sAh[(ra + 8) * GPAD + ca    ];
                afh[mt][2] = *(const uint32_t*)&sAh[(ra    ) * GPAD + ca + 8];
                afh[mt][3] = *(const uint32_t*)&sAh[(ra + 8) * GPAD + ca + 8];
                afl[mt][0] = *(const uint32_t*)&sAl[(ra    ) * GPAD + ca    ];
                afl[mt][1] = *(const uint32_t*)&sAl[(ra + 8) * GPAD + ca    ];
                afl[mt][2] = *(const uint32_t*)&sAl[(ra    ) * GPAD + ca + 8];
                afl[mt][3] = *(const uint32_t*)&sAl[(ra + 8) * GPAD + ca + 8];
            }
#pragma unroll
            for (int nt = 0; nt < 8; nt++) {
                const int rb = wn + nt * 8 + grp;
                const int cb = kk + tig * 2;
                uint32_t bh[2], bl[2];
                bh[0] = *(const uint32_t*)&sBh[rb * GPAD + cb    ];
                bh[1] = *(const uint32_t*)&sBh[rb * GPAD + cb + 8];
                bl[0] = *(const uint32_t*)&sBl[rb * GPAD + cb    ];
                bl[1] = *(const uint32_t*)&sBl[rb * GPAD + cb + 8];
#pragma unroll
                for (int mt = 0; mt < 2; mt++) {
                    mma16816(acc[mt][nt], afh[mt], bh);
                    mma16816(acc[mt][nt], afh[mt], bl);
                    mma16816(acc[mt][nt], afl[mt], bh);
                }
            }
        }
        __syncthreads();
    }

#pragma unroll
    for (int mt = 0; mt < 2; mt++) {
        const int row = bm + wm + mt * 16 + grp;
#pragma unroll
        for (int nt = 0; nt < 8; nt++) {
            const int col = bn + wn + nt * 8 + tig * 2;
            *(float2*)&C[(size_t)row * N + col]       = make_float2(acc[mt][nt][0], acc[mt][nt][1]);
            *(float2*)&C[(size_t)(row + 8) * N + col] = make_float2(acc[mt][nt][2], acc[mt][nt][3]);
        }
    }
}

// ---------------------------------------------------------------------------
// RMSNorm + RoPE for Q: reads qkv fp32, writes bf16 hi/lo to (b,H,s,D),
// pre-scaled by 1/sqrt(D). One warp per row.
// ---------------------------------------------------------------------------
__global__ __launch_bounds__(256) void norm_rope_q(
    const float* __restrict__ qkv,
    __nv_bfloat16* __restrict__ oh, __nv_bfloat16* __restrict__ ol,
    const float* __restrict__ cs, const float* __restrict__ sn,
    const float* __restrict__ gamma)
{
    const int warp = (blockIdx.x * 256 + threadIdx.x) >> 5;
    const int lane = threadIdx.x & 31;
    const int h  = warp % NH;
    const int bs = warp / NH;
    const int sp = bs % SEQ;
    const int bi = bs / SEQ;

    const float* x = qkv + (size_t)bs * NQKV + h * HD;
    float e0 = x[lane], e1 = x[lane + 32], e2 = x[lane + 64], e3 = x[lane + 96];

    float ssq = e0 * e0 + e1 * e1 + e2 * e2 + e3 * e3;
#pragma unroll
    for (int o = 16; o; o >>= 1) ssq += __shfl_xor_sync(0xffffffffu, ssq, o);
    const float r = rsqrtf(ssq * (1.0f / HD) + 1e-6f);

    e0 *= r * gamma[lane];      e1 *= r * gamma[lane + 32];
    e2 *= r * gamma[lane + 64]; e3 *= r * gamma[lane + 96];

    const float* cp = cs + (size_t)bs * HD;
    const float* sg = sn + (size_t)bs * HD;
    float o4[4];
    o4[0] = (e0 * cp[lane]      - e2 * sg[lane])      * SM_SCALE;
    o4[1] = (e1 * cp[lane + 32] - e3 * sg[lane + 32]) * SM_SCALE;
    o4[2] = (e2 * cp[lane + 64] + e0 * sg[lane + 64]) * SM_SCALE;
    o4[3] = (e3 * cp[lane + 96] + e1 * sg[lane + 96]) * SM_SCALE;

    const size_t ob = (((size_t)bi * NH + h) * SEQ + sp) * HD;
#pragma unroll
    for (int j = 0; j < 4; j++) {
        __nv_bfloat16 hv = __float2bfloat16(o4[j]);
        oh[ob + lane + 32 * j] = hv;
        ol[ob + lane + 32 * j] = __float2bfloat16(o4[j] - __bfloat162float(hv));
    }
}

// ---------------------------------------------------------------------------
// RMSNorm + RoPE for K: writes fp32 (b,KV,s,D) into d_out AND bf16 hi/lo.
// ---------------------------------------------------------------------------
__global__ __launch_bounds__(256) void norm_rope_k(
    const float* __restrict__ qkv, float* __restrict__ kout,
    __nv_bfloat16* __restrict__ oh, __nv_bfloat16* __restrict__ ol,
    const float* __restrict__ cs, const float* __restrict__ sn,
    const float* __restrict__ gamma)
{
    const int warp = (blockIdx.x * 256 + threadIdx.x) >> 5;
    const int lane = threadIdx.x & 31;
    const int h  = warp % NKV;
    const int bs = warp / NKV;
    const int sp = bs % SEQ;
    const int bi = bs / SEQ;

    const float* x = qkv + (size_t)bs * NQKV + KOFF + h * HD;
    float e0 = x[lane], e1 = x[lane + 32], e2 = x[lane + 64], e3 = x[lane + 96];

    float ssq = e0 * e0 + e1 * e1 + e2 * e2 + e3 * e3;
#pragma unroll
    for (int o = 16; o; o >>= 1) ssq += __shfl_xor_sync(0xffffffffu, ssq, o);
    const float r = rsqrtf(ssq * (1.0f / HD) + 1e-6f);

    e0 *= r * gamma[lane];      e1 *= r * gamma[lane + 32];
    e2 *= r * gamma[lane + 64]; e3 *= r * gamma[lane + 96];

    const float* cp = cs + (size_t)bs * HD;
    const float* sg = sn + (size_t)bs * HD;
    float o4[4];
    o4[0] = e0 * cp[lane]      - e2 * sg[lane];
    o4[1] = e1 * cp[lane + 32] - e3 * sg[lane + 32];
    o4[2] = e2 * cp[lane + 64] + e0 * sg[lane + 64];
    o4[3] = e3 * cp[lane + 96] + e1 * sg[lane + 96];

    const size_t ob = (((size_t)bi * NKV + h) * SEQ + sp) * HD;
#pragma unroll
    for (int j = 0; j < 4; j++) {
        kout[ob + lane + 32 * j] = o4[j];
        __nv_bfloat16 hv = __float2bfloat16(o4[j]);
        oh[ob + lane + 32 * j] = hv;
        ol[ob + lane + 32 * j] = __float2bfloat16(o4[j] - __bfloat162float(hv));
    }
}

// ---------------------------------------------------------------------------
// V transpose (fp32): qkv V region -> (b,KV,s,D) in d_out
// ---------------------------------------------------------------------------
__global__ __launch_bounds__(256) void v_transpose(
    const float4* __restrict__ qkv4, float4* __restrict__ out)
{
    const size_t i = (size_t)blockIdx.x * 256 + threadIdx.x;
    const int d4 = (int)(i & 31);
    const int kh = (int)((i >> 5) & (NKV - 1));
    const int sp = (int)((i >> 8) & (SEQ - 1));
    const int bi = (int)(i >> 19);
    const size_t src = ((size_t)(bi * SEQ + sp) * NQKV + VOFF + kh * HD) / 4 + d4;
    const size_t dst = (((size_t)bi * NKV + kh) * SEQ + sp) * 32 + d4;
    out[dst] = qkv4[src];
}

// ---------------------------------------------------------------------------
// V transpose + split (bf16): qkv V region -> (b,KV,D,s) hi/lo
// grid (SEQ/32, HD/32, NB*NKV), block (32,8); smem 32x33 tile.
// ---------------------------------------------------------------------------
__global__ void vtrans_split(
    const float* __restrict__ qkv,
    __nv_bfloat16* __restrict__ vh, __nv_bfloat16* __restrict__ vl)
{
    __shared__ float t[32][33];
    const int s0 = blockIdx.x * 32, d0 = blockIdx.y * 32;
    const int bz = blockIdx.z;                 // bi*NKV + kh
    const int bi = bz / NKV, kh = bz % NKV;
    const int tx = threadIdx.x, ty = threadIdx.y;

#pragma unroll
    for (int j = 0; j < 4; j++) {
        int s = s0 + ty + j * 8;
        t[ty + j * 8][tx] =
            qkv[(size_t)(bi * SEQ + s) * NQKV + VOFF + kh * HD + d0 + tx];
    }
    __syncthreads();
#pragma unroll
    for (int j = 0; j < 4; j++) {
        int d = d0 + ty + j * 8;
        float v = t[tx][ty + j * 8];
        __nv_bfloat16 hv = __float2bfloat16(v);
        size_t idx = ((size_t)bz * HD + d) * SEQ + s0 + tx;
        vh[idx] = hv;
        vl[idx] = __float2bfloat16(v - __bfloat162float(hv));
    }
}

// ---------------------------------------------------------------------------
// Tensor-core causal flash attention, bf16 hi/lo split.
// Q: (b,H,s,D) hi/lo pre-scaled; K: (b,KV,s,D) hi/lo; V: (b,KV,D,s) hi/lo.
// Output: bf16 hi/lo straight into O-proj A buffers, (b*s, H*D).
// BM=BN=64, 128 threads (4 warps, 16 Q rows each).
// ---------------------------------------------------------------------------
constexpr int FQP = 136;  // pitch (bf16) for Q/K tiles: 272B, conflict-free
constexpr int FVP = 72;   // pitch (bf16) for Vt tiles: 144B, conflict-free
constexpr int FLASH_SMEM = (4 * 64 * FQP + 2 * 128 * FVP) * 2;  // 106496 B

__global__ __launch_bounds__(128, 2) void flash_mma(
    const __nv_bfloat16* __restrict__ Qh, const __nv_bfloat16* __restrict__ Ql,
    const __nv_bfloat16* __restrict__ Kh, const __nv_bfloat16* __restrict__ Kl,
    const __nv_bfloat16* __restrict__ Vh, const __nv_bfloat16* __restrict__ Vl,
    __nv_bfloat16* __restrict__ Oh, __nv_bfloat16* __restrict__ Ol)
{
    extern __shared__ __nv_bfloat16 sm[];
    __nv_bfloat16* sQh = sm;
    __nv_bfloat16* sQl = sQh + 64 * FQP;
    __nv_bfloat16* sKh = sQl + 64 * FQP;
    __nv_bfloat16* sKl = sKh + 64 * FQP;
    __nv_bfloat16* sVh = sKl + 64 * FQP;
    __nv_bfloat16* sVl = sVh + 128 * FVP;

    const int qtile = blockIdx.x;
    const int h     = blockIdx.y;
    const int bi    = blockIdx.z;
    const int kh    = h / GQ;
    const int tid   = threadIdx.x;
    const int lane  = tid & 31;
    const int wid   = tid >> 5;
    const int grp   = lane >> 2;
    const int tig   = lane & 3;
    const int q0    = qtile * 64;

    // Load Q tile (64 x 128, hi+lo)
    {
        const __nv_bfloat16* qgh = Qh + (((size_t)bi * NH + h) * SEQ + q0) * HD;
        const __nv_bfloat16* qgl = Ql + (((size_t)bi * NH + h) * SEQ + q0) * HD;
        for (int i = tid; i < 64 * 16; i += 128) {
            int r = i >> 4, c = (i & 15) * 8;
            *(uint4*)&sQh[r * FQP + c] = *(const uint4*)&qgh[(size_t)r * HD + c];
            *(uint4*)&sQl[r * FQP + c] = *(const uint4*)&qgl[(size_t)r * HD + c];
        }
    }

    const __nv_bfloat16* kgh = Kh + (((size_t)bi * NKV + kh) * SEQ) * HD;
    const __nv_bfloat16* kgl = Kl + (((size_t)bi * NKV + kh) * SEQ) * HD;
    const __nv_bfloat16* vgh = Vh + (((size_t)bi * NKV + kh) * HD) * SEQ;
    const __nv_bfloat16* vgl = Vl + (((size_t)bi * NKV + kh) * HD) * SEQ;

    float o[16][4];
#pragma unroll
    for (int nt = 0; nt < 16; nt++)
#pragma unroll
        for (int e = 0; e < 4; e++) o[nt][e] = 0.f;
    float m0 = -1e30f, m1 = -1e30f, l0 = 0.f, l1 = 0.f;

    const int ntiles = qtile + 1;
    for (int t = 0; t < ntiles; ++t) {
        const int k0 = t * 64;
        __syncthreads();
        // K tile (64 x 128) + Vt tile (128 x 64), hi+lo
        for (int i = tid; i < 64 * 16; i += 128) {
            int r = i >> 4, c = (i & 15) * 8;
            *(uint4*)&sKh[r * FQP + c] = *(const uint4*)&kgh[(size_t)(k0 + r) * HD + c];
            *(uint4*)&sKl[r * FQP + c] = *(const uint4*)&kgl[(size_t)(k0 + r) * HD + c];
        }
        for (int i = tid; i < 128 * 8; i += 128) {
            int r = i >> 3, c = (i & 7) * 8;
            *(uint4*)&sVh[r * FVP + c] = *(const uint4*)&vgh[(size_t)r * SEQ + k0 + c];
            *(uint4*)&sVl[r * FVP + c] = *(const uint4*)&vgl[(size_t)r * SEQ + k0 + c];
        }
        __syncthreads();

        // S = Qh*Kh + Ql*Kh + Qh*Kl  (16 x 64 per warp)
        float s[8][4];
#pragma unroll
        for (int nt = 0; nt < 8; nt++)
#pragma unroll
            for (int e = 0; e < 4; e++) s[nt][e] = 0.f;

#pragma unroll
        for (int kk = 0; kk < 128; kk += 16) {
            uint32_t ah[4], al[4];
            const int ra = wid * 16 + grp;
            const int ca = kk + tig * 2;
            ah[0] = *(const uint32_t*)&sQh[(ra    ) * FQP + ca    ];
            ah[1] = *(const uint32_t*)&sQh[(ra + 8) * FQP + ca    ];
            ah[2] = *(const uint32_t*)&sQh[(ra    ) * FQP + ca + 8];
            ah[3] = *(const uint32_t*)&sQh[(ra + 8) * FQP + ca + 8];
            al[0] = *(const uint32_t*)&sQl[(ra    ) * FQP + ca    ];
            al[1] = *(const uint32_t*)&sQl[(ra + 8) * FQP + ca    ];
            al[2] = *(const uint32_t*)&sQl[(ra    ) * FQP + ca + 8];
            al[3] = *(const uint32_t*)&sQl[(ra + 8) * FQP + ca + 8];
#pragma unroll
            for (int nt = 0; nt < 8; nt++) {
                const int rb = nt * 8 + grp;
                uint32_t bh[2], bl[2];
                bh[0] = *(const uint32_t*)&sKh[rb * FQP + ca    ];
                bh[1] = *(const uint32_t*)&sKh[rb * FQP + ca + 8];
                bl[0] = *(const uint32_t*)&sKl[rb * FQP + ca    ];
                bl[1] = *(const uint32_t*)&sKl[rb * FQP + ca + 8];
                mma16816(s[nt], ah, bh);
                mma16816(s[nt], al, bh);
                mma16816(s[nt], ah, bl);
            }
        }

        // causal mask on diagonal tile
        if (t == qtile) {
            const int r0 = q0 + wid * 16 + grp;
#pragma unroll
            for (int nt = 0; nt < 8; nt++) {
                const int c = k0 + nt * 8 + tig * 2;
                if (c     > r0)     s[nt][0] = -1e30f;
                if (c + 1 > r0)     s[nt][1] = -1e30f;
                if (c     > r0 + 8) s[nt][2] = -1e30f;
                if (c + 1 > r0 + 8) s[nt][3] = -1e30f;
            }
        }

        // online softmax (rows grp and grp+8)
        float mx0 = -1e30f, mx1 = -1e30f;
#pragma unroll
        for (int nt = 0; nt < 8; nt++) {
            mx0 = fmaxf(mx0, fmaxf(s[nt][0], s[nt][1]));
            mx1 = fmaxf(mx1, fmaxf(s[nt][2], s[nt][3]));
        }
        mx0 = fmaxf(mx0, __shfl_xor_sync(0xffffffffu, mx0, 1));
        mx0 = fmaxf(mx0, __shfl_xor_sync(0xffffffffu, mx0, 2));
        mx1 = fmaxf(mx1, __shfl_xor_sync(0xffffffffu, mx1, 1));
        mx1 = fmaxf(mx1, __shfl_xor_sync(0xffffffffu, mx1, 2));

        const float nm0 = fmaxf(m0, mx0);
        const float nm1 = fmaxf(m1, mx1);
        const float a0 = __expf(m0 - nm0);
        const float a1 = __expf(m1 - nm1);
        m0 = nm0; m1 = nm1;

        float rs0 = 0.f, rs1 = 0.f;
#pragma unroll
        for (int nt = 0; nt < 8; nt++) {
            s[nt][0] = __expf(s[nt][0] - m0);
            s[nt][1] = __expf(s[nt][1] - m0);
            s[nt][2] = __expf(s[nt][2] - m1);
            s[nt][3] = __expf(s[nt][3] - m1);
            rs0 += s[nt][0] + s[nt][1];
            rs1 += s[nt][2] + s[nt][3];
        }
        rs0 += __shfl_xor_sync(0xffffffffu, rs0, 1);
        rs0 += __shfl_xor_sync(0xffffffffu, rs0, 2);
        rs1 += __shfl_xor_sync(0xffffffffu, rs1, 1);
        rs1 += __shfl_xor_sync(0xffffffffu, rs1, 2);
        l0 = l0 * a0 + rs0;
        l1 = l1 * a1 + rs1;

#pragma unroll
        for (int nt = 0; nt < 16; nt++) {
            o[nt][0] *= a0; o[nt][1] *= a0;
            o[nt][2] *= a1; o[nt][3] *= a1;
        }

        // O += Ph*Vh + Pl*Vh + Ph*Vl  (16 x 128 per warp)
#pragma unroll
        for (int ks = 0; ks < 4; ks++) {
            uint32_t ph[4], pl[4];
            ph[0] = pack_hilo(s[2 * ks][0],     s[2 * ks][1],     pl[0]);
            ph[1] = pack_hilo(s[2 * ks][2],     s[2 * ks][3],     pl[1]);
            ph[2] = pack_hilo(s[2 * ks + 1][0], s[2 * ks + 1][1], pl[2]);
            ph[3] = pack_hilo(s[2 * ks + 1][2], s[2 * ks + 1][3], pl[3]);
            const int cb = ks * 16 + tig * 2;
#pragma unroll
            for (int nt = 0; nt < 16; nt++) {
                const int rb = nt * 8 + grp;
                uint32_t bh[2], bl[2];
                bh[0] = *(const uint32_t*)&sVh[rb * FVP + cb    ];
                bh[1] = *(const uint32_t*)&sVh[rb * FVP + cb + 8];
                bl[0] = *(const uint32_t*)&sVl[rb * FVP + cb    ];
                bl[1] = *(const uint32_t*)&sVl[rb * FVP + cb + 8];
                mma16816(o[nt], ph, bh);
                mma16816(o[nt], pl, bh);
                mma16816(o[nt], ph, bl);
            }
        }
    }

    // epilogue: normalize and write bf16 hi/lo (b*s, H*D)
    const float i0 = 1.0f / l0;
    const float i1 = 1.0f / l1;
    const size_t row0 = (size_t)bi * SEQ + q0 + wid * 16 + grp;
    const size_t row1 = row0 + 8;
    const int colb = h * HD + tig * 2;
#pragma unroll
    for (int nt = 0; nt < 16; nt++) {
        uint32_t lo;
        uint32_t hi = pack_hilo(o[nt][0] * i0, o[nt][1] * i0, lo);
        *(uint32_t*)&Oh[row0 * (NH * HD) + colb + nt * 8] = hi;
        *(uint32_t*)&Ol[row0 * (NH * HD) + colb + nt * 8] = lo;
        hi = pack_hilo(o[nt][2] * i1, o[nt][3] * i1, lo);
        *(uint32_t*)&Oh[row1 * (NH * HD) + colb + nt * 8] = hi;
        *(uint32_t*)&Ol[row1 * (NH * HD) + colb + nt * 8] = lo;
    }
}

// ---------------------------------------------------------------------------
// kernel_launch
// ---------------------------------------------------------------------------
extern "C" void kernel_launch(void* const* d_in, const int* in_sizes, int n_in,
                              void* d_out, int out_size)
{
    const float* hidden = (const float*)d_in[0];
    const float* cosb   = (const float*)d_in[1];
    const float* sinb   = (const float*)d_in[2];
    const float* wq     = (const float*)d_in[3];
    const float* wk     = (const float*)d_in[4];
    const float* wv     = (const float*)d_in[5];
    const float* wo     = (const float*)d_in[6];
    const float* qg     = (const float*)d_in[7];
    const float* kg     = (const float*)d_in[8];

    float* out  = (float*)d_out;
    float* kout = out  + (size_t)NB * SEQ * HDIM;
    float* vout = kout + (size_t)NB * NKV * SEQ * HD;

    __nv_bfloat16 *hidh, *hidl, *wqkvh, *wqkvl, *woh, *wol, *aoh, *aol;
    __nv_bfloat16 *qh, *ql, *kh, *kl, *vh, *vl;
    float *qkv;
    cudaGetSymbolAddress((void**)&hidh,  g_hid_h);
    cudaGetSymbolAddress((void**)&hidl,  g_hid_l);
    cudaGetSymbolAddress((void**)&wqkvh, g_wqkv_h);
    cudaGetSymbolAddress((void**)&wqkvl, g_wqkv_l);
    cudaGetSymbolAddress((void**)&woh,   g_wo_h);
    cudaGetSymbolAddress((void**)&wol,   g_wo_l);
    cudaGetSymbolAddress((void**)&aoh,   g_ao_h);
    cudaGetSymbolAddress((void**)&aol,   g_ao_l);
    cudaGetSymbolAddress((void**)&qkv,   g_qkv);
    cudaGetSymbolAddress((void**)&qh,    g_qh);
    cudaGetSymbolAddress((void**)&ql,    g_ql);
    cudaGetSymbolAddress((void**)&kh,    g_kh);
    cudaGetSymbolAddress((void**)&kl,    g_kl);
    cudaGetSymbolAddress((void**)&vh,    g_vh);
    cudaGetSymbolAddress((void**)&vl,    g_vl);

    cudaFuncSetAttribute(flash_mma, cudaFuncAttributeMaxDynamicSharedMemorySize, FLASH_SMEM);

    // fp32 -> bf16 hi/lo splits
    const size_t nHid = (size_t)MROWS * HDIM;
    const size_t nWq  = (size_t)NH  * HD * HDIM;
    const size_t nWk  = (size_t)NKV * HD * HDIM;
    split_bf16<<<(int)(nHid / 1024), 256>>>((const float4*)hidden, hidh, hidl);
    split_bf16<<<(int)(nWq  / 1024), 256>>>((const float4*)wq, wqkvh, wqkvl);
    split_bf16<<<(int)(nWk  / 1024), 256>>>((const float4*)wk, wqkvh + nWq, wqkvl + nWq);
    split_bf16<<<(int)(nWk  / 1024), 256>>>((const float4*)wv, wqkvh + nWq + nWk, wqkvl + nWq + nWk);
    split_bf16<<<(int)(nWq  / 1024), 256>>>((const float4*)wo, woh, wol);

    // Fused QKV projection
    gemm_bf16x2<<<dim3(NQKV / 128, MROWS / 128), 256>>>(
        hidh, hidl, wqkvh, wqkvl, qkv, MROWS, NQKV, HDIM);

    // RMSNorm + RoPE -> bf16 hi/lo operands (+ fp32 K into d_out)
    norm_rope_q<<<(MROWS * NH ) / 8, 256>>>(qkv, qh, ql, cosb, sinb, qg);
    norm_rope_k<<<(MROWS * NKV) / 8, 256>>>(qkv, kout, kh, kl, cosb, sinb, kg);

    // V: fp32 into d_out's new_v; bf16 hi/lo transposed (b,KV,D,s)
    v_transpose<<<(NB * SEQ * NKV * HD / 4) / 256, 256>>>((const float4*)qkv, (float4*)vout);
    vtrans_split<<<dim3(SEQ / 32, HD / 32, NB * NKV), dim3(32, 8)>>>(qkv, vh, vl);

    // Tensor-core causal GQA flash attention -> bf16 hi/lo O
    flash_mma<<<dim3(SEQ / 64, NH, NB), 128, FLASH_SMEM>>>(
        qh, ql, kh, kl, vh, vl, aoh, aol);

    // Output projection
    gemm_bf16x2<<<dim3(HDIM / 128, MROWS / 128), 256>>>(
        aoh, aol, woh, wol, out, MROWS, HDIM, NH * HD);
}

// round 4
// speedup vs baseline: 3.4325x; 1.2631x over previous
#include <cuda_runtime.h>
#include <cuda_bf16.h>
#include <cstdint>

// Problem constants
constexpr int NB   = 2;      // batch
constexpr int SEQ  = 2048;   // sequence
constexpr int HDIM = 2560;   // hidden
constexpr int NH   = 32;     // q heads
constexpr int NKV  = 8;      // kv heads
constexpr int HD   = 128;    // head dim
constexpr int GQ   = NH / NKV;
constexpr int MROWS = NB * SEQ;            // 4096
constexpr int NQKV  = (NH + 2 * NKV) * HD; // 6144
constexpr int KOFF  = NH * HD;             // 4096
constexpr int VOFF  = (NH + NKV) * HD;     // 5120
constexpr float SM_SCALE = 0.08838834764831845f;  // 1/sqrt(128)

// ---------------- device scratch (no allocation allowed) ----------------
__device__ __nv_bfloat16 g_hid_h [(size_t)MROWS * HDIM];
__device__ __nv_bfloat16 g_hid_l [(size_t)MROWS * HDIM];
__device__ __nv_bfloat16 g_wqkv_h[(size_t)NQKV * HDIM];
__device__ __nv_bfloat16 g_wqkv_l[(size_t)NQKV * HDIM];
__device__ __nv_bfloat16 g_wo_h  [(size_t)HDIM * NH * HD];
__device__ __nv_bfloat16 g_wo_l  [(size_t)HDIM * NH * HD];
__device__ __nv_bfloat16 g_ao_h  [(size_t)MROWS * NH * HD];
__device__ __nv_bfloat16 g_ao_l  [(size_t)MROWS * NH * HD];
__device__ float g_qkv[(size_t)MROWS * NQKV];       // 96MB
// bf16 hi/lo attention operands
__device__ __nv_bfloat16 g_qh[(size_t)NB * NH  * SEQ * HD];  // (b,H,s,D), pre-scaled
__device__ __nv_bfloat16 g_ql[(size_t)NB * NH  * SEQ * HD];
__device__ __nv_bfloat16 g_kh[(size_t)NB * NKV * SEQ * HD];  // (b,KV,s,D)
__device__ __nv_bfloat16 g_kl[(size_t)NB * NKV * SEQ * HD];
__device__ __nv_bfloat16 g_vh[(size_t)NB * NKV * HD * SEQ];  // (b,KV,D,s) transposed
__device__ __nv_bfloat16 g_vl[(size_t)NB * NKV * HD * SEQ];

// ---------------------------------------------------------------------------
// cp.async helpers
// ---------------------------------------------------------------------------
__device__ __forceinline__ void cp16(__nv_bfloat16* smem, const __nv_bfloat16* gmem)
{
    uint32_t s = (uint32_t)__cvta_generic_to_shared(smem);
    asm volatile("cp.async.cg.shared.global [%0], [%1], 16;\n" :: "r"(s), "l"(gmem));
}
#define CP_COMMIT() asm volatile("cp.async.commit_group;\n" ::: "memory")
#define CP_WAIT(n)  asm volatile("cp.async.wait_group %0;\n" :: "n"(n) : "memory")

// ---------------------------------------------------------------------------
// fp32 -> bf16 hi/lo split
// ---------------------------------------------------------------------------
__global__ __launch_bounds__(256) void split_bf16(
    const float4* __restrict__ in, __nv_bfloat16* __restrict__ hi,
    __nv_bfloat16* __restrict__ lo)
{
    const size_t i = (size_t)blockIdx.x * 256 + threadIdx.x;
    float4 x = in[i];
    __nv_bfloat16 h[4], l[4];
    float xs[4] = {x.x, x.y, x.z, x.w};
#pragma unroll
    for (int j = 0; j < 4; j++) {
        h[j] = __float2bfloat16(xs[j]);
        l[j] = __float2bfloat16(xs[j] - __bfloat162float(h[j]));
    }
    *(uint2*)&hi[i * 4] = *(uint2*)h;
    *(uint2*)&lo[i * 4] = *(uint2*)l;
}

// ---------------------------------------------------------------------------
// mma.m16n8k16 bf16 wrapper
// ---------------------------------------------------------------------------
__device__ __forceinline__ void mma16816(float* c, const uint32_t* a, const uint32_t* b)
{
    asm volatile(
        "mma.sync.aligned.m16n8k16.row.col.f32.bf16.bf16.f32 "
        "{%0,%1,%2,%3}, {%4,%5,%6,%7}, {%8,%9}, {%0,%1,%2,%3};"
        : "+f"(c[0]), "+f"(c[1]), "+f"(c[2]), "+f"(c[3])
        : "r"(a[0]), "r"(a[1]), "r"(a[2]), "r"(a[3]), "r"(b[0]), "r"(b[1]));
}

__device__ __forceinline__ uint32_t pack_hilo(float x, float y, uint32_t& lo)
{
    __nv_bfloat162 h = __float22bfloat162_rn(make_float2(x, y));
    float rx = x - __bfloat162float(h.x);
    float ry = y - __bfloat162float(h.y);
    __nv_bfloat162 l = __float22bfloat162_rn(make_float2(rx, ry));
    lo = *(uint32_t*)&l;
    return *(uint32_t*)&h;
}

// ---------------------------------------------------------------------------
// bf16-split tensor-core GEMM: C[M,N] = A[M,K] @ B[N,K]^T   (fp32 accurate)
// 2-stage cp.async pipeline. Block 128x128, BK=32, 256 threads (8 warps).
// ---------------------------------------------------------------------------
constexpr int GPAD = 40;                 // smem row pitch in bf16 (80B, 16B-aligned)
constexpr int GSTG = 128 * GPAD;         // bf16 per matrix per stage (5120)
constexpr int GEMM_SMEM = 2 * 4 * GSTG * 2;  // 81920 bytes

__global__ __launch_bounds__(256, 2) void gemm_bf16x2(
    const __nv_bfloat16* __restrict__ Ah, const __nv_bfloat16* __restrict__ Al,
    const __nv_bfloat16* __restrict__ Bh, const __nv_bfloat16* __restrict__ Bl,
    float* __restrict__ C, int M, int N, int K)
{
    extern __shared__ __nv_bfloat16 sb[];

    const int tid = threadIdx.x;
    const int bm = blockIdx.y * 128;
    const int bn = blockIdx.x * 128;
    const int lane = tid & 31;
    const int wid  = tid >> 5;
    const int wm = (wid & 3) * 32;
    const int wn = (wid >> 2) * 64;
    const int grp = lane >> 2;
    const int tig = lane & 3;

    // copy geometry: each thread does rows r0, r0+64 with one 16B chunk each,
    // for each of the 4 matrices (8 cp.async / thread / stage).
    const int r0 = tid >> 2;
    const int oc = (tid & 3) * 8;

    const __nv_bfloat16* gA0h = Ah + (size_t)(bm + r0) * K + oc;
    const __nv_bfloat16* gA1h = Ah + (size_t)(bm + r0 + 64) * K + oc;
    const __nv_bfloat16* gA0l = Al + (size_t)(bm + r0) * K + oc;
    const __nv_bfloat16* gA1l = Al + (size_t)(bm + r0 + 64) * K + oc;
    const __nv_bfloat16* gB0h = Bh + (size_t)(bn + r0) * K + oc;
    const __nv_bfloat16* gB1h = Bh + (size_t)(bn + r0 + 64) * K + oc;
    const __nv_bfloat16* gB0l = Bl + (size_t)(bn + r0) * K + oc;
    const __nv_bfloat16* gB1l = Bl + (size_t)(bn + r0 + 64) * K + oc;

    const int s0 = r0 * GPAD + oc;
    const int s1 = (r0 + 64) * GPAD + oc;

    float acc[2][8][4];
#pragma unroll
    for (int mt = 0; mt < 2; mt++)
#pragma unroll
        for (int nt = 0; nt < 8; nt++)
#pragma unroll
            for (int e = 0; e < 4; e++) acc[mt][nt][e] = 0.f;

    const int nk = K / 32;

    // prefetch stage 0
    {
        __nv_bfloat16* st = sb;
        cp16(st + 0 * GSTG + s0, gA0h); cp16(st + 0 * GSTG + s1, gA1h);
        cp16(st + 1 * GSTG + s0, gA0l); cp16(st + 1 * GSTG + s1, gA1l);
        cp16(st + 2 * GSTG + s0, gB0h); cp16(st + 2 * GSTG + s1, gB1h);
        cp16(st + 3 * GSTG + s0, gB0l); cp16(st + 3 * GSTG + s1, gB1l);
        CP_COMMIT();
    }

    for (int i = 0; i < nk; i++) {
        __nv_bfloat16* cur = sb + (size_t)(i & 1) * 4 * GSTG;
        if (i + 1 < nk) {
            __nv_bfloat16* nxt = sb + (size_t)((i + 1) & 1) * 4 * GSTG;
            const int ko = (i + 1) * 32;
            cp16(nxt + 0 * GSTG + s0, gA0h + ko); cp16(nxt + 0 * GSTG + s1, gA1h + ko);
            cp16(nxt + 1 * GSTG + s0, gA0l + ko); cp16(nxt + 1 * GSTG + s1, gA1l + ko);
            cp16(nxt + 2 * GSTG + s0, gB0h + ko); cp16(nxt + 2 * GSTG + s1, gB1h + ko);
            cp16(nxt + 3 * GSTG + s0, gB0l + ko); cp16(nxt + 3 * GSTG + s1, gB1l + ko);
            CP_COMMIT();
            CP_WAIT(1);
        } else {
            CP_WAIT(0);
        }
        __syncthreads();

        const __nv_bfloat16* sAh = cur;
        const __nv_bfloat16* sAl = cur + 1 * GSTG;
        const __nv_bfloat16* sBh = cur + 2 * GSTG;
        const __nv_bfloat16* sBl = cur + 3 * GSTG;

#pragma unroll
        for (int kk = 0; kk < 32; kk += 16) {
            uint32_t afh[2][4], afl[2][4];
#pragma unroll
            for (int mt = 0; mt < 2; mt++) {
                const int ra = wm + mt * 16 + grp;
                const int ca = kk + tig * 2;
                afh[mt][0] = *(const uint32_t*)&sAh[(ra    ) * GPAD + ca    ];
                afh[mt][1] = *(const uint32_t*)&sAh[(ra + 8) * GPAD + ca    ];
                afh[mt][2] = *(const uint32_t*)&sAh[(ra    ) * GPAD + ca + 8];
                afh[mt][3] = *(const uint32_t*)&sAh[(ra + 8) * GPAD + ca + 8];
                afl[mt][0] = *(const uint32_t*)&sAl[(ra    ) * GPAD + ca    ];
                afl[mt][1] = *(const uint32_t*)&sAl[(ra + 8) * GPAD + ca    ];
                afl[mt][2] = *(const uint32_t*)&sAl[(ra    ) * GPAD + ca + 8];
                afl[mt][3] = *(const uint32_t*)&sAl[(ra + 8) * GPAD + ca + 8];
            }
#pragma unroll
            for (int nt = 0; nt < 8; nt++) {
                const int rb = wn + nt * 8 + grp;
                const int cb = kk + tig * 2;
                uint32_t bh[2], bl[2];
                bh[0] = *(const uint32_t*)&sBh[rb * GPAD + cb    ];
                bh[1] = *(const uint32_t*)&sBh[rb * GPAD + cb + 8];
                bl[0] = *(const uint32_t*)&sBl[rb * GPAD + cb    ];
                bl[1] = *(const uint32_t*)&sBl[rb * GPAD + cb + 8];
#pragma unroll
                for (int mt = 0; mt < 2; mt++) {
                    mma16816(acc[mt][nt], afh[mt], bh);
                    mma16816(acc[mt][nt], afh[mt], bl);
                    mma16816(acc[mt][nt], afl[mt], bh);
                }
            }
        }
        __syncthreads();
    }

#pragma unroll
    for (int mt = 0; mt < 2; mt++) {
        const int row = bm + wm + mt * 16 + grp;
#pragma unroll
        for (int nt = 0; nt < 8; nt++) {
            const int col = bn + wn + nt * 8 + tig * 2;
            *(float2*)&C[(size_t)row * N + col]       = make_float2(acc[mt][nt][0], acc[mt][nt][1]);
            *(float2*)&C[(size_t)(row + 8) * N + col] = make_float2(acc[mt][nt][2], acc[mt][nt][3]);
        }
    }
}

// ---------------------------------------------------------------------------
// RMSNorm + RoPE for Q: reads qkv fp32, writes bf16 hi/lo to (b,H,s,D),
// pre-scaled by 1/sqrt(D). One warp per row.
// ---------------------------------------------------------------------------
__global__ __launch_bounds__(256) void norm_rope_q(
    const float* __restrict__ qkv,
    __nv_bfloat16* __restrict__ oh, __nv_bfloat16* __restrict__ ol,
    const float* __restrict__ cs, const float* __restrict__ sn,
    const float* __restrict__ gamma)
{
    const int warp = (blockIdx.x * 256 + threadIdx.x) >> 5;
    const int lane = threadIdx.x & 31;
    const int h  = warp % NH;
    const int bs = warp / NH;
    const int sp = bs % SEQ;
    const int bi = bs / SEQ;

    const float* x = qkv + (size_t)bs * NQKV + h * HD;
    float e0 = x[lane], e1 = x[lane + 32], e2 = x[lane + 64], e3 = x[lane + 96];

    float ssq = e0 * e0 + e1 * e1 + e2 * e2 + e3 * e3;
#pragma unroll
    for (int o = 16; o; o >>= 1) ssq += __shfl_xor_sync(0xffffffffu, ssq, o);
    const float r = rsqrtf(ssq * (1.0f / HD) + 1e-6f);

    e0 *= r * gamma[lane];      e1 *= r * gamma[lane + 32];
    e2 *= r * gamma[lane + 64]; e3 *= r * gamma[lane + 96];

    const float* cp = cs + (size_t)bs * HD;
    const float* sg = sn + (size_t)bs * HD;
    float o4[4];
    o4[0] = (e0 * cp[lane]      - e2 * sg[lane])      * SM_SCALE;
    o4[1] = (e1 * cp[lane + 32] - e3 * sg[lane + 32]) * SM_SCALE;
    o4[2] = (e2 * cp[lane + 64] + e0 * sg[lane + 64]) * SM_SCALE;
    o4[3] = (e3 * cp[lane + 96] + e1 * sg[lane + 96]) * SM_SCALE;

    const size_t ob = (((size_t)bi * NH + h) * SEQ + sp) * HD;
#pragma unroll
    for (int j = 0; j < 4; j++) {
        __nv_bfloat16 hv = __float2bfloat16(o4[j]);
        oh[ob + lane + 32 * j] = hv;
        ol[ob + lane + 32 * j] = __float2bfloat16(o4[j] - __bfloat162float(hv));
    }
}

// ---------------------------------------------------------------------------
// RMSNorm + RoPE for K: writes fp32 (b,KV,s,D) into d_out AND bf16 hi/lo.
// ---------------------------------------------------------------------------
__global__ __launch_bounds__(256) void norm_rope_k(
    const float* __restrict__ qkv, float* __restrict__ kout,
    __nv_bfloat16* __restrict__ oh, __nv_bfloat16* __restrict__ ol,
    const float* __restrict__ cs, const float* __restrict__ sn,
    const float* __restrict__ gamma)
{
    const int warp = (blockIdx.x * 256 + threadIdx.x) >> 5;
    const int lane = threadIdx.x & 31;
    const int h  = warp % NKV;
    const int bs = warp / NKV;
    const int sp = bs % SEQ;
    const int bi = bs / SEQ;

    const float* x = qkv + (size_t)bs * NQKV + KOFF + h * HD;
    float e0 = x[lane], e1 = x[lane + 32], e2 = x[lane + 64], e3 = x[lane + 96];

    float ssq = e0 * e0 + e1 * e1 + e2 * e2 + e3 * e3;
#pragma unroll
    for (int o = 16; o; o >>= 1) ssq += __shfl_xor_sync(0xffffffffu, ssq, o);
    const float r = rsqrtf(ssq * (1.0f / HD) + 1e-6f);

    e0 *= r * gamma[lane];      e1 *= r * gamma[lane + 32];
    e2 *= r * gamma[lane + 64]; e3 *= r * gamma[lane + 96];

    const float* cp = cs + (size_t)bs * HD;
    const float* sg = sn + (size_t)bs * HD;
    float o4[4];
    o4[0] = e0 * cp[lane]      - e2 * sg[lane];
    o4[1] = e1 * cp[lane + 32] - e3 * sg[lane + 32];
    o4[2] = e2 * cp[lane + 64] + e0 * sg[lane + 64];
    o4[3] = e3 * cp[lane + 96] + e1 * sg[lane + 96];

    const size_t ob = (((size_t)bi * NKV + h) * SEQ + sp) * HD;
#pragma unroll
    for (int j = 0; j < 4; j++) {
        kout[ob + lane + 32 * j] = o4[j];
        __nv_bfloat16 hv = __float2bfloat16(o4[j]);
        oh[ob + lane + 32 * j] = hv;
        ol[ob + lane + 32 * j] = __float2bfloat16(o4[j] - __bfloat162float(hv));
    }
}

// ---------------------------------------------------------------------------
// V transpose (fp32): qkv V region -> (b,KV,s,D) in d_out
// ---------------------------------------------------------------------------
__global__ __launch_bounds__(256) void v_transpose(
    const float4* __restrict__ qkv4, float4* __restrict__ out)
{
    const size_t i = (size_t)blockIdx.x * 256 + threadIdx.x;
    const int d4 = (int)(i & 31);
    const int kh = (int)((i >> 5) & (NKV - 1));
    const int sp = (int)((i >> 8) & (SEQ - 1));
    const int bi = (int)(i >> 19);
    const size_t src = ((size_t)(bi * SEQ + sp) * NQKV + VOFF + kh * HD) / 4 + d4;
    const size_t dst = (((size_t)bi * NKV + kh) * SEQ + sp) * 32 + d4;
    out[dst] = qkv4[src];
}

// ---------------------------------------------------------------------------
// V transpose + split (bf16): qkv V region -> (b,KV,D,s) hi/lo
// ---------------------------------------------------------------------------
__global__ void vtrans_split(
    const float* __restrict__ qkv,
    __nv_bfloat16* __restrict__ vh, __nv_bfloat16* __restrict__ vl)
{
    __shared__ float t[32][33];
    const int s0 = blockIdx.x * 32, d0 = blockIdx.y * 32;
    const int bz = blockIdx.z;                 // bi*NKV + kh
    const int bi = bz / NKV, kh = bz % NKV;
    const int tx = threadIdx.x, ty = threadIdx.y;

#pragma unroll
    for (int j = 0; j < 4; j++) {
        int s = s0 + ty + j * 8;
        t[ty + j * 8][tx] =
            qkv[(size_t)(bi * SEQ + s) * NQKV + VOFF + kh * HD + d0 + tx];
    }
    __syncthreads();
#pragma unroll
    for (int j = 0; j < 4; j++) {
        int d = d0 + ty + j * 8;
        float v = t[tx][ty + j * 8];
        __nv_bfloat16 hv = __float2bfloat16(v);
        size_t idx = ((size_t)bz * HD + d) * SEQ + s0 + tx;
        vh[idx] = hv;
        vl[idx] = __float2bfloat16(v - __bfloat162float(hv));
    }
}

// ---------------------------------------------------------------------------
// Tensor-core causal flash attention, bf16 hi/lo split.
// BM=BN=64, 128 threads (4 warps, 16 Q rows each).
// ---------------------------------------------------------------------------
constexpr int FQP = 136;  // pitch (bf16) for Q/K tiles
constexpr int FVP = 72;   // pitch (bf16) for Vt tiles
constexpr int FLASH_SMEM = (4 * 64 * FQP + 2 * 128 * FVP) * 2;  // 106496 B

__global__ __launch_bounds__(128, 2) void flash_mma(
    const __nv_bfloat16* __restrict__ Qh, const __nv_bfloat16* __restrict__ Ql,
    const __nv_bfloat16* __restrict__ Kh, const __nv_bfloat16* __restrict__ Kl,
    const __nv_bfloat16* __restrict__ Vh, const __nv_bfloat16* __restrict__ Vl,
    __nv_bfloat16* __restrict__ Oh, __nv_bfloat16* __restrict__ Ol)
{
    extern __shared__ __nv_bfloat16 sm[];
    __nv_bfloat16* sQh = sm;
    __nv_bfloat16* sQl = sQh + 64 * FQP;
    __nv_bfloat16* sKh = sQl + 64 * FQP;
    __nv_bfloat16* sKl = sKh + 64 * FQP;
    __nv_bfloat16* sVh = sKl + 64 * FQP;
    __nv_bfloat16* sVl = sVh + 128 * FVP;

    const int qtile = blockIdx.x;
    const int h     = blockIdx.y;
    const int bi    = blockIdx.z;
    const int kh    = h / GQ;
    const int tid   = threadIdx.x;
    const int lane  = tid & 31;
    const int wid   = tid >> 5;
    const int grp   = lane >> 2;
    const int tig   = lane & 3;
    const int q0    = qtile * 64;

    {
        const __nv_bfloat16* qgh = Qh + (((size_t)bi * NH + h) * SEQ + q0) * HD;
        const __nv_bfloat16* qgl = Ql + (((size_t)bi * NH + h) * SEQ + q0) * HD;
        for (int i = tid; i < 64 * 16; i += 128) {
            int r = i >> 4, c = (i & 15) * 8;
            *(uint4*)&sQh[r * FQP + c] = *(const uint4*)&qgh[(size_t)r * HD + c];
            *(uint4*)&sQl[r * FQP + c] = *(const uint4*)&qgl[(size_t)r * HD + c];
        }
    }

    const __nv_bfloat16* kgh = Kh + (((size_t)bi * NKV + kh) * SEQ) * HD;
    const __nv_bfloat16* kgl = Kl + (((size_t)bi * NKV + kh) * SEQ) * HD;
    const __nv_bfloat16* vgh = Vh + (((size_t)bi * NKV + kh) * HD) * SEQ;
    const __nv_bfloat16* vgl = Vl + (((size_t)bi * NKV + kh) * HD) * SEQ;

    float o[16][4];
#pragma unroll
    for (int nt = 0; nt < 16; nt++)
#pragma unroll
        for (int e = 0; e < 4; e++) o[nt][e] = 0.f;
    float m0 = -1e30f, m1 = -1e30f, l0 = 0.f, l1 = 0.f;

    const int ntiles = qtile + 1;
    for (int t = 0; t < ntiles; ++t) {
        const int k0 = t * 64;
        __syncthreads();
        for (int i = tid; i < 64 * 16; i += 128) {
            int r = i >> 4, c = (i & 15) * 8;
            *(uint4*)&sKh[r * FQP + c] = *(const uint4*)&kgh[(size_t)(k0 + r) * HD + c];
            *(uint4*)&sKl[r * FQP + c] = *(const uint4*)&kgl[(size_t)(k0 + r) * HD + c];
        }
        for (int i = tid; i < 128 * 8; i += 128) {
            int r = i >> 3, c = (i & 7) * 8;
            *(uint4*)&sVh[r * FVP + c] = *(const uint4*)&vgh[(size_t)r * SEQ + k0 + c];
            *(uint4*)&sVl[r * FVP + c] = *(const uint4*)&vgl[(size_t)r * SEQ + k0 + c];
        }
        __syncthreads();

        float s[8][4];
#pragma unroll
        for (int nt = 0; nt < 8; nt++)
#pragma unroll
            for (int e = 0; e < 4; e++) s[nt][e] = 0.f;

#pragma unroll
        for (int kk = 0; kk < 128; kk += 16) {
            uint32_t ah[4], al[4];
            const int ra = wid * 16 + grp;
            const int ca = kk + tig * 2;
            ah[0] = *(const uint32_t*)&sQh[(ra    ) * FQP + ca    ];
            ah[1] = *(const uint32_t*)&sQh[(ra + 8) * FQP + ca    ];
            ah[2] = *(const uint32_t*)&sQh[(ra    ) * FQP + ca + 8];
            ah[3] = *(const uint32_t*)&sQh[(ra + 8) * FQP + ca + 8];
            al[0] = *(const uint32_t*)&sQl[(ra    ) * FQP + ca    ];
            al[1] = *(const uint32_t*)&sQl[(ra + 8) * FQP + ca    ];
            al[2] = *(const uint32_t*)&sQl[(ra    ) * FQP + ca + 8];
            al[3] = *(const uint32_t*)&sQl[(ra + 8) * FQP + ca + 8];
#pragma unroll
            for (int nt = 0; nt < 8; nt++) {
                const int rb = nt * 8 + grp;
                uint32_t bh[2], bl[2];
                bh[0] = *(const uint32_t*)&sKh[rb * FQP + ca    ];
                bh[1] = *(const uint32_t*)&sKh[rb * FQP + ca + 8];
                bl[0] = *(const uint32_t*)&sKl[rb * FQP + ca    ];
                bl[1] = *(const uint32_t*)&sKl[rb * FQP + ca + 8];
                mma16816(s[nt], ah, bh);
                mma16816(s[nt], al, bh);
                mma16816(s[nt], ah, bl);
            }
        }

        if (t == qtile) {
            const int r0 = q0 + wid * 16 + grp;
#pragma unroll
            for (int nt = 0; nt < 8; nt++) {
                const int c = k0 + nt * 8 + tig * 2;
                if (c     > r0)     s[nt][0] = -1e30f;
                if (c + 1 > r0)     s[nt][1] = -1e30f;
                if (c     > r0 + 8) s[nt][2] = -1e30f;
                if (c + 1 > r0 + 8) s[nt][3] = -1e30f;
            }
        }

        float mx0 = -1e30f, mx1 = -1e30f;
#pragma unroll
        for (int nt = 0; nt < 8; nt++) {
            mx0 = fmaxf(mx0, fmaxf(s[nt][0], s[nt][1]));
            mx1 = fmaxf(mx1, fmaxf(s[nt][2], s[nt][3]));
        }
        mx0 = fmaxf(mx0, __shfl_xor_sync(0xffffffffu, mx0, 1));
        mx0 = fmaxf(mx0, __shfl_xor_sync(0xffffffffu, mx0, 2));
        mx1 = fmaxf(mx1, __shfl_xor_sync(0xffffffffu, mx1, 1));
        mx1 = fmaxf(mx1, __shfl_xor_sync(0xffffffffu, mx1, 2));

        const float nm0 = fmaxf(m0, mx0);
        const float nm1 = fmaxf(m1, mx1);
        const float a0 = __expf(m0 - nm0);
        const float a1 = __expf(m1 - nm1);
        m0 = nm0; m1 = nm1;

        float rs0 = 0.f, rs1 = 0.f;
#pragma unroll
        for (int nt = 0; nt < 8; nt++) {
            s[nt][0] = __expf(s[nt][0] - m0);
            s[nt][1] = __expf(s[nt][1] - m0);
            s[nt][2] = __expf(s[nt][2] - m1);
            s[nt][3] = __expf(s[nt][3] - m1);
            rs0 += s[nt][0] + s[nt][1];
            rs1 += s[nt][2] + s[nt][3];
        }
        rs0 += __shfl_xor_sync(0xffffffffu, rs0, 1);
        rs0 += __shfl_xor_sync(0xffffffffu, rs0, 2);
        rs1 += __shfl_xor_sync(0xffffffffu, rs1, 1);
        rs1 += __shfl_xor_sync(0xffffffffu, rs1, 2);
        l0 = l0 * a0 + rs0;
        l1 = l1 * a1 + rs1;

#pragma unroll
        for (int nt = 0; nt < 16; nt++) {
            o[nt][0] *= a0; o[nt][1] *= a0;
            o[nt][2] *= a1; o[nt][3] *= a1;
        }

#pragma unroll
        for (int ks = 0; ks < 4; ks++) {
            uint32_t ph[4], pl[4];
            ph[0] = pack_hilo(s[2 * ks][0],     s[2 * ks][1],     pl[0]);
            ph[1] = pack_hilo(s[2 * ks][2],     s[2 * ks][3],     pl[1]);
            ph[2] = pack_hilo(s[2 * ks + 1][0], s[2 * ks + 1][1], pl[2]);
            ph[3] = pack_hilo(s[2 * ks + 1][2], s[2 * ks + 1][3], pl[3]);
            const int cb = ks * 16 + tig * 2;
#pragma unroll
            for (int nt = 0; nt < 16; nt++) {
                const int rb = nt * 8 + grp;
                uint32_t bh[2], bl[2];
                bh[0] = *(const uint32_t*)&sVh[rb * FVP + cb    ];
                bh[1] = *(const uint32_t*)&sVh[rb * FVP + cb + 8];
                bl[0] = *(const uint32_t*)&sVl[rb * FVP + cb    ];
                bl[1] = *(const uint32_t*)&sVl[rb * FVP + cb + 8];
                mma16816(o[nt], ph, bh);
                mma16816(o[nt], pl, bh);
                mma16816(o[nt], ph, bl);
            }
        }
    }

    const float i0 = 1.0f / l0;
    const float i1 = 1.0f / l1;
    const size_t row0 = (size_t)bi * SEQ + q0 + wid * 16 + grp;
    const size_t row1 = row0 + 8;
    const int colb = h * HD + tig * 2;
#pragma unroll
    for (int nt = 0; nt < 16; nt++) {
        uint32_t lo;
        uint32_t hi = pack_hilo(o[nt][0] * i0, o[nt][1] * i0, lo);
        *(uint32_t*)&Oh[row0 * (NH * HD) + colb + nt * 8] = hi;
        *(uint32_t*)&Ol[row0 * (NH * HD) + colb + nt * 8] = lo;
        hi = pack_hilo(o[nt][2] * i1, o[nt][3] * i1, lo);
        *(uint32_t*)&Oh[row1 * (NH * HD) + colb + nt * 8] = hi;
        *(uint32_t*)&Ol[row1 * (NH * HD) + colb + nt * 8] = lo;
    }
}

// ---------------------------------------------------------------------------
// kernel_launch
// ---------------------------------------------------------------------------
extern "C" void kernel_launch(void* const* d_in, const int* in_sizes, int n_in,
                              void* d_out, int out_size)
{
    const float* hidden = (const float*)d_in[0];
    const float* cosb   = (const float*)d_in[1];
    const float* sinb   = (const float*)d_in[2];
    const float* wq     = (const float*)d_in[3];
    const float* wk     = (const float*)d_in[4];
    const float* wv     = (const float*)d_in[5];
    const float* wo     = (const float*)d_in[6];
    const float* qg     = (const float*)d_in[7];
    const float* kg     = (const float*)d_in[8];

    float* out  = (float*)d_out;
    float* kout = out  + (size_t)NB * SEQ * HDIM;
    float* vout = kout + (size_t)NB * NKV * SEQ * HD;

    __nv_bfloat16 *hidh, *hidl, *wqkvh, *wqkvl, *woh, *wol, *aoh, *aol;
    __nv_bfloat16 *qh, *ql, *kh, *kl, *vh, *vl;
    float *qkv;
    cudaGetSymbolAddress((void**)&hidh,  g_hid_h);
    cudaGetSymbolAddress((void**)&hidl,  g_hid_l);
    cudaGetSymbolAddress((void**)&wqkvh, g_wqkv_h);
    cudaGetSymbolAddress((void**)&wqkvl, g_wqkv_l);
    cudaGetSymbolAddress((void**)&woh,   g_wo_h);
    cudaGetSymbolAddress((void**)&wol,   g_wo_l);
    cudaGetSymbolAddress((void**)&aoh,   g_ao_h);
    cudaGetSymbolAddress((void**)&aol,   g_ao_l);
    cudaGetSymbolAddress((void**)&qkv,   g_qkv);
    cudaGetSymbolAddress((void**)&qh,    g_qh);
    cudaGetSymbolAddress((void**)&ql,    g_ql);
    cudaGetSymbolAddress((void**)&kh,    g_kh);
    cudaGetSymbolAddress((void**)&kl,    g_kl);
    cudaGetSymbolAddress((void**)&vh,    g_vh);
    cudaGetSymbolAddress((void**)&vl,    g_vl);

    cudaFuncSetAttribute(flash_mma, cudaFuncAttributeMaxDynamicSharedMemorySize, FLASH_SMEM);
    cudaFuncSetAttribute(gemm_bf16x2, cudaFuncAttributeMaxDynamicSharedMemorySize, GEMM_SMEM);

    // fp32 -> bf16 hi/lo splits
    const size_t nHid = (size_t)MROWS * HDIM;
    const size_t nWq  = (size_t)NH  * HD * HDIM;
    const size_t nWk  = (size_t)NKV * HD * HDIM;
    split_bf16<<<(int)(nHid / 1024), 256>>>((const float4*)hidden, hidh, hidl);
    split_bf16<<<(int)(nWq  / 1024), 256>>>((const float4*)wq, wqkvh, wqkvl);
    split_bf16<<<(int)(nWk  / 1024), 256>>>((const float4*)wk, wqkvh + nWq, wqkvl + nWq);
    split_bf16<<<(int)(nWk  / 1024), 256>>>((const float4*)wv, wqkvh + nWq + nWk, wqkvl + nWq + nWk);
    split_bf16<<<(int)(nWq  / 1024), 256>>>((const float4*)wo, woh, wol);

    // Fused QKV projection
    gemm_bf16x2<<<dim3(NQKV / 128, MROWS / 128), 256, GEMM_SMEM>>>(
        hidh, hidl, wqkvh, wqkvl, qkv, MROWS, NQKV, HDIM);

    // RMSNorm + RoPE -> bf16 hi/lo operands (+ fp32 K into d_out)
    norm_rope_q<<<(MROWS * NH ) / 8, 256>>>(qkv, qh, ql, cosb, sinb, qg);
    norm_rope_k<<<(MROWS * NKV) / 8, 256>>>(qkv, kout, kh, kl, cosb, sinb, kg);

    // V: fp32 into d_out's new_v; bf16 hi/lo transposed (b,KV,D,s)
    v_transpose<<<(NB * SEQ * NKV * HD / 4) / 256, 256>>>((const float4*)qkv, (float4*)vout);
    vtrans_split<<<dim3(SEQ / 32, HD / 32, NB * NKV), dim3(32, 8)>>>(qkv, vh, vl);

    // Tensor-core causal GQA flash attention -> bf16 hi/lo O
    flash_mma<<<dim3(SEQ / 64, NH, NB), 128, FLASH_SMEM>>>(
        qh, ql, kh, kl, vh, vl, aoh, aol);

    // Output projection
    gemm_bf16x2<<<dim3(HDIM / 128, MROWS / 128), 256, GEMM_SMEM>>>(
        aoh, aol, woh, wol, out, MROWS, HDIM, NH * HD);
}

// round 5
// speedup vs baseline: 3.6345x; 1.0588x over previous
#include <cuda_runtime.h>
#include <cuda_bf16.h>
#include <cstdint>

// Problem constants
constexpr int NB   = 2;      // batch
constexpr int SEQ  = 2048;   // sequence
constexpr int HDIM = 2560;   // hidden
constexpr int NH   = 32;     // q heads
constexpr int NKV  = 8;      // kv heads
constexpr int HD   = 128;    // head dim
constexpr int GQ   = NH / NKV;
constexpr int MROWS = NB * SEQ;            // 4096
constexpr int NQKV  = (NH + 2 * NKV) * HD; // 6144
constexpr int KOFF  = NH * HD;             // 4096
constexpr int VOFF  = (NH + NKV) * HD;     // 5120
constexpr float SM_SCALE = 0.08838834764831845f;  // 1/sqrt(128)

// ---------------- device scratch (no allocation allowed) ----------------
__device__ __nv_bfloat16 g_hid_h [(size_t)MROWS * HDIM];
__device__ __nv_bfloat16 g_hid_l [(size_t)MROWS * HDIM];
__device__ __nv_bfloat16 g_wqkv_h[(size_t)NQKV * HDIM];
__device__ __nv_bfloat16 g_wqkv_l[(size_t)NQKV * HDIM];
__device__ __nv_bfloat16 g_wo_h  [(size_t)HDIM * NH * HD];
__device__ __nv_bfloat16 g_wo_l  [(size_t)HDIM * NH * HD];
__device__ __nv_bfloat16 g_ao_h  [(size_t)MROWS * NH * HD];
__device__ __nv_bfloat16 g_ao_l  [(size_t)MROWS * NH * HD];
__device__ float g_qkv[(size_t)MROWS * NQKV];       // 96MB
// bf16 hi/lo attention operands
__device__ __nv_bfloat16 g_qh[(size_t)NB * NH  * SEQ * HD];  // (b,H,s,D), pre-scaled
__device__ __nv_bfloat16 g_ql[(size_t)NB * NH  * SEQ * HD];
__device__ __nv_bfloat16 g_kh[(size_t)NB * NKV * SEQ * HD];  // (b,KV,s,D)
__device__ __nv_bfloat16 g_kl[(size_t)NB * NKV * SEQ * HD];
__device__ __nv_bfloat16 g_vh[(size_t)NB * NKV * HD * SEQ];  // (b,KV,D,s) transposed
__device__ __nv_bfloat16 g_vl[(size_t)NB * NKV * HD * SEQ];

// ---------------------------------------------------------------------------
// cp.async / ldmatrix helpers
// ---------------------------------------------------------------------------
__device__ __forceinline__ void cp16(__nv_bfloat16* smem, const __nv_bfloat16* gmem)
{
    uint32_t s = (uint32_t)__cvta_generic_to_shared(smem);
    asm volatile("cp.async.cg.shared.global [%0], [%1], 16;\n" :: "r"(s), "l"(gmem));
}
#define CP_COMMIT() asm volatile("cp.async.commit_group;\n" ::: "memory")
#define CP_WAIT(n)  asm volatile("cp.async.wait_group %0;\n" :: "n"(n) : "memory")

__device__ __forceinline__ void ldsm4(uint32_t* r, const __nv_bfloat16* p)
{
    uint32_t a = (uint32_t)__cvta_generic_to_shared(p);
    asm volatile("ldmatrix.sync.aligned.m8n8.x4.shared.b16 {%0,%1,%2,%3}, [%4];"
        : "=r"(r[0]), "=r"(r[1]), "=r"(r[2]), "=r"(r[3]) : "r"(a));
}

// ---------------------------------------------------------------------------
// fp32 -> bf16 hi/lo split
// ---------------------------------------------------------------------------
__global__ __launch_bounds__(256) void split_bf16(
    const float4* __restrict__ in, __nv_bfloat16* __restrict__ hi,
    __nv_bfloat16* __restrict__ lo)
{
    const size_t i = (size_t)blockIdx.x * 256 + threadIdx.x;
    float4 x = in[i];
    __nv_bfloat16 h[4], l[4];
    float xs[4] = {x.x, x.y, x.z, x.w};
#pragma unroll
    for (int j = 0; j < 4; j++) {
        h[j] = __float2bfloat16(xs[j]);
        l[j] = __float2bfloat16(xs[j] - __bfloat162float(h[j]));
    }
    *(uint2*)&hi[i * 4] = *(uint2*)h;
    *(uint2*)&lo[i * 4] = *(uint2*)l;
}

// ---------------------------------------------------------------------------
// mma.m16n8k16 bf16 wrapper
// ---------------------------------------------------------------------------
__device__ __forceinline__ void mma16816(float* c, const uint32_t* a, const uint32_t* b)
{
    asm volatile(
        "mma.sync.aligned.m16n8k16.row.col.f32.bf16.bf16.f32 "
        "{%0,%1,%2,%3}, {%4,%5,%6,%7}, {%8,%9}, {%0,%1,%2,%3};"
        : "+f"(c[0]), "+f"(c[1]), "+f"(c[2]), "+f"(c[3])
        : "r"(a[0]), "r"(a[1]), "r"(a[2]), "r"(a[3]), "r"(b[0]), "r"(b[1]));
}

__device__ __forceinline__ uint32_t pack_hilo(float x, float y, uint32_t& lo)
{
    __nv_bfloat162 h = __float22bfloat162_rn(make_float2(x, y));
    float rx = x - __bfloat162float(h.x);
    float ry = y - __bfloat162float(h.y);
    __nv_bfloat162 l = __float22bfloat162_rn(make_float2(rx, ry));
    lo = *(uint32_t*)&l;
    return *(uint32_t*)&h;
}

// ---------------------------------------------------------------------------
// bf16-split tensor-core GEMM: C[M,N] = A[M,K] @ B[N,K]^T   (fp32 accurate)
// 2-stage cp.async pipeline + ldmatrix fragment loads.
// Block 128x128, BK=32, 256 threads (8 warps, 32x64 warp tile).
// ---------------------------------------------------------------------------
constexpr int GPAD = 40;                 // smem row pitch in bf16 (80B)
constexpr int GSTG = 128 * GPAD;         // bf16 per matrix per stage (5120)
constexpr int GEMM_SMEM = 2 * 4 * GSTG * 2;  // 81920 bytes

__global__ __launch_bounds__(256, 2) void gemm_bf16x2(
    const __nv_bfloat16* __restrict__ Ah, const __nv_bfloat16* __restrict__ Al,
    const __nv_bfloat16* __restrict__ Bh, const __nv_bfloat16* __restrict__ Bl,
    float* __restrict__ C, int M, int N, int K)
{
    extern __shared__ __nv_bfloat16 sb[];

    const int tid = threadIdx.x;
    const int bm = blockIdx.y * 128;
    const int bn = blockIdx.x * 128;
    const int lane = tid & 31;
    const int wid  = tid >> 5;
    const int wm = (wid & 3) * 32;
    const int wn = (wid >> 2) * 64;
    const int grp = lane >> 2;
    const int tig = lane & 3;

    // ldmatrix lane->address components
    const int lrow  = lane & 15;            // A: row within m16
    const int lcoff = (lane >> 4) * 8;      // A: col offset (k half)
    const int brow  = (lane & 7) + ((lane >> 4) << 3);  // B: row within n16
    const int bcoff = ((lane >> 3) & 1) * 8;            // B: col offset

    // copy geometry: each thread: rows r0, r0+64, one 16B chunk, 4 matrices
    const int r0 = tid >> 2;
    const int oc = (tid & 3) * 8;

    const __nv_bfloat16* gA0h = Ah + (size_t)(bm + r0) * K + oc;
    const __nv_bfloat16* gA1h = Ah + (size_t)(bm + r0 + 64) * K + oc;
    const __nv_bfloat16* gA0l = Al + (size_t)(bm + r0) * K + oc;
    const __nv_bfloat16* gA1l = Al + (size_t)(bm + r0 + 64) * K + oc;
    const __nv_bfloat16* gB0h = Bh + (size_t)(bn + r0) * K + oc;
    const __nv_bfloat16* gB1h = Bh + (size_t)(bn + r0 + 64) * K + oc;
    const __nv_bfloat16* gB0l = Bl + (size_t)(bn + r0) * K + oc;
    const __nv_bfloat16* gB1l = Bl + (size_t)(bn + r0 + 64) * K + oc;

    const int s0 = r0 * GPAD + oc;
    const int s1 = (r0 + 64) * GPAD + oc;

    float acc[2][8][4];
#pragma unroll
    for (int mt = 0; mt < 2; mt++)
#pragma unroll
        for (int nt = 0; nt < 8; nt++)
#pragma unroll
            for (int e = 0; e < 4; e++) acc[mt][nt][e] = 0.f;

    const int nk = K / 32;

    // prefetch stage 0
    {
        __nv_bfloat16* st = sb;
        cp16(st + 0 * GSTG + s0, gA0h); cp16(st + 0 * GSTG + s1, gA1h);
        cp16(st + 1 * GSTG + s0, gA0l); cp16(st + 1 * GSTG + s1, gA1l);
        cp16(st + 2 * GSTG + s0, gB0h); cp16(st + 2 * GSTG + s1, gB1h);
        cp16(st + 3 * GSTG + s0, gB0l); cp16(st + 3 * GSTG + s1, gB1l);
        CP_COMMIT();
    }

    for (int i = 0; i < nk; i++) {
        __nv_bfloat16* cur = sb + (size_t)(i & 1) * 4 * GSTG;
        if (i + 1 < nk) {
            __nv_bfloat16* nxt = sb + (size_t)((i + 1) & 1) * 4 * GSTG;
            const int ko = (i + 1) * 32;
            cp16(nxt + 0 * GSTG + s0, gA0h + ko); cp16(nxt + 0 * GSTG + s1, gA1h + ko);
            cp16(nxt + 1 * GSTG + s0, gA0l + ko); cp16(nxt + 1 * GSTG + s1, gA1l + ko);
            cp16(nxt + 2 * GSTG + s0, gB0h + ko); cp16(nxt + 2 * GSTG + s1, gB1h + ko);
            cp16(nxt + 3 * GSTG + s0, gB0l + ko); cp16(nxt + 3 * GSTG + s1, gB1l + ko);
            CP_COMMIT();
            CP_WAIT(1);
        } else {
            CP_WAIT(0);
        }
        __syncthreads();

        const __nv_bfloat16* sAh = cur;
        const __nv_bfloat16* sAl = cur + 1 * GSTG;
        const __nv_bfloat16* sBh = cur + 2 * GSTG;
        const __nv_bfloat16* sBl = cur + 3 * GSTG;

#pragma unroll
        for (int kk = 0; kk < 32; kk += 16) {
            uint32_t afh[2][4], afl[2][4];
            const int acol = kk + lcoff;
            ldsm4(afh[0], &sAh[(wm + lrow     ) * GPAD + acol]);
            ldsm4(afh[1], &sAh[(wm + 16 + lrow) * GPAD + acol]);
            ldsm4(afl[0], &sAl[(wm + lrow     ) * GPAD + acol]);
            ldsm4(afl[1], &sAl[(wm + 16 + lrow) * GPAD + acol]);
#pragma unroll
            for (int np = 0; np < 4; np++) {
                const int br = wn + np * 16 + brow;
                const int bc = kk + bcoff;
                uint32_t bh[4], bl[4];
                ldsm4(bh, &sBh[br * GPAD + bc]);
                ldsm4(bl, &sBl[br * GPAD + bc]);
#pragma unroll
                for (int mt = 0; mt < 2; mt++) {
                    mma16816(acc[mt][2 * np    ], afh[mt], bh);
                    mma16816(acc[mt][2 * np    ], afh[mt], bl);
                    mma16816(acc[mt][2 * np    ], afl[mt], bh);
                    mma16816(acc[mt][2 * np + 1], afh[mt], bh + 2);
                    mma16816(acc[mt][2 * np + 1], afh[mt], bl + 2);
                    mma16816(acc[mt][2 * np + 1], afl[mt], bh + 2);
                }
            }
        }
        __syncthreads();
    }

#pragma unroll
    for (int mt = 0; mt < 2; mt++) {
        const int row = bm + wm + mt * 16 + grp;
#pragma unroll
        for (int nt = 0; nt < 8; nt++) {
            const int col = bn + wn + nt * 8 + tig * 2;
            *(float2*)&C[(size_t)row * N + col]       = make_float2(acc[mt][nt][0], acc[mt][nt][1]);
            *(float2*)&C[(size_t)(row + 8) * N + col] = make_float2(acc[mt][nt][2], acc[mt][nt][3]);
        }
    }
}

// ---------------------------------------------------------------------------
// RMSNorm + RoPE for Q: reads qkv fp32, writes bf16 hi/lo to (b,H,s,D),
// pre-scaled by 1/sqrt(D). One warp per row.
// ---------------------------------------------------------------------------
__global__ __launch_bounds__(256) void norm_rope_q(
    const float* __restrict__ qkv,
    __nv_bfloat16* __restrict__ oh, __nv_bfloat16* __restrict__ ol,
    const float* __restrict__ cs, const float* __restrict__ sn,
    const float* __restrict__ gamma)
{
    const int warp = (blockIdx.x * 256 + threadIdx.x) >> 5;
    const int lane = threadIdx.x & 31;
    const int h  = warp % NH;
    const int bs = warp / NH;
    const int sp = bs % SEQ;
    const int bi = bs / SEQ;

    const float* x = qkv + (size_t)bs * NQKV + h * HD;
    float e0 = x[lane], e1 = x[lane + 32], e2 = x[lane + 64], e3 = x[lane + 96];

    float ssq = e0 * e0 + e1 * e1 + e2 * e2 + e3 * e3;
#pragma unroll
    for (int o = 16; o; o >>= 1) ssq += __shfl_xor_sync(0xffffffffu, ssq, o);
    const float r = rsqrtf(ssq * (1.0f / HD) + 1e-6f);

    e0 *= r * gamma[lane];      e1 *= r * gamma[lane + 32];
    e2 *= r * gamma[lane + 64]; e3 *= r * gamma[lane + 96];

    const float* cp = cs + (size_t)bs * HD;
    const float* sg = sn + (size_t)bs * HD;
    float o4[4];
    o4[0] = (e0 * cp[lane]      - e2 * sg[lane])      * SM_SCALE;
    o4[1] = (e1 * cp[lane + 32] - e3 * sg[lane + 32]) * SM_SCALE;
    o4[2] = (e2 * cp[lane + 64] + e0 * sg[lane + 64]) * SM_SCALE;
    o4[3] = (e3 * cp[lane + 96] + e1 * sg[lane + 96]) * SM_SCALE;

    const size_t ob = (((size_t)bi * NH + h) * SEQ + sp) * HD;
#pragma unroll
    for (int j = 0; j < 4; j++) {
        __nv_bfloat16 hv = __float2bfloat16(o4[j]);
        oh[ob + lane + 32 * j] = hv;
        ol[ob + lane + 32 * j] = __float2bfloat16(o4[j] - __bfloat162float(hv));
    }
}

// ---------------------------------------------------------------------------
// RMSNorm + RoPE for K: writes fp32 (b,KV,s,D) into d_out AND bf16 hi/lo.
// ---------------------------------------------------------------------------
__global__ __launch_bounds__(256) void norm_rope_k(
    const float* __restrict__ qkv, float* __restrict__ kout,
    __nv_bfloat16* __restrict__ oh, __nv_bfloat16* __restrict__ ol,
    const float* __restrict__ cs, const float* __restrict__ sn,
    const float* __restrict__ gamma)
{
    const int warp = (blockIdx.x * 256 + threadIdx.x) >> 5;
    const int lane = threadIdx.x & 31;
    const int h  = warp % NKV;
    const int bs = warp / NKV;
    const int sp = bs % SEQ;
    const int bi = bs / SEQ;

    const float* x = qkv + (size_t)bs * NQKV + KOFF + h * HD;
    float e0 = x[lane], e1 = x[lane + 32], e2 = x[lane + 64], e3 = x[lane + 96];

    float ssq = e0 * e0 + e1 * e1 + e2 * e2 + e3 * e3;
#pragma unroll
    for (int o = 16; o; o >>= 1) ssq += __shfl_xor_sync(0xffffffffu, ssq, o);
    const float r = rsqrtf(ssq * (1.0f / HD) + 1e-6f);

    e0 *= r * gamma[lane];      e1 *= r * gamma[lane + 32];
    e2 *= r * gamma[lane + 64]; e3 *= r * gamma[lane + 96];

    const float* cp = cs + (size_t)bs * HD;
    const float* sg = sn + (size_t)bs * HD;
    float o4[4];
    o4[0] = e0 * cp[lane]      - e2 * sg[lane];
    o4[1] = e1 * cp[lane + 32] - e3 * sg[lane + 32];
    o4[2] = e2 * cp[lane + 64] + e0 * sg[lane + 64];
    o4[3] = e3 * cp[lane + 96] + e1 * sg[lane + 96];

    const size_t ob = (((size_t)bi * NKV + h) * SEQ + sp) * HD;
#pragma unroll
    for (int j = 0; j < 4; j++) {
        kout[ob + lane + 32 * j] = o4[j];
        __nv_bfloat16 hv = __float2bfloat16(o4[j]);
        oh[ob + lane + 32 * j] = hv;
        ol[ob + lane + 32 * j] = __float2bfloat16(o4[j] - __bfloat162float(hv));
    }
}

// ---------------------------------------------------------------------------
// V transpose (fp32): qkv V region -> (b,KV,s,D) in d_out
// ---------------------------------------------------------------------------
__global__ __launch_bounds__(256) void v_transpose(
    const float4* __restrict__ qkv4, float4* __restrict__ out)
{
    const size_t i = (size_t)blockIdx.x * 256 + threadIdx.x;
    const int d4 = (int)(i & 31);
    const int kh = (int)((i >> 5) & (NKV - 1));
    const int sp = (int)((i >> 8) & (SEQ - 1));
    const int bi = (int)(i >> 19);
    const size_t src = ((size_t)(bi * SEQ + sp) * NQKV + VOFF + kh * HD) / 4 + d4;
    const size_t dst = (((size_t)bi * NKV + kh) * SEQ + sp) * 32 + d4;
    out[dst] = qkv4[src];
}

// ---------------------------------------------------------------------------
// V transpose + split (bf16): qkv V region -> (b,KV,D,s) hi/lo
// ---------------------------------------------------------------------------
__global__ void vtrans_split(
    const float* __restrict__ qkv,
    __nv_bfloat16* __restrict__ vh, __nv_bfloat16* __restrict__ vl)
{
    __shared__ float t[32][33];
    const int s0 = blockIdx.x * 32, d0 = blockIdx.y * 32;
    const int bz = blockIdx.z;                 // bi*NKV + kh
    const int bi = bz / NKV, kh = bz % NKV;
    const int tx = threadIdx.x, ty = threadIdx.y;

#pragma unroll
    for (int j = 0; j < 4; j++) {
        int s = s0 + ty + j * 8;
        t[ty + j * 8][tx] =
            qkv[(size_t)(bi * SEQ + s) * NQKV + VOFF + kh * HD + d0 + tx];
    }
    __syncthreads();
#pragma unroll
    for (int j = 0; j < 4; j++) {
        int d = d0 + ty + j * 8;
        float v = t[tx][ty + j * 8];
        __nv_bfloat16 hv = __float2bfloat16(v);
        size_t idx = ((size_t)bz * HD + d) * SEQ + s0 + tx;
        vh[idx] = hv;
        vl[idx] = __float2bfloat16(v - __bfloat162float(hv));
    }
}

// ---------------------------------------------------------------------------
// Tensor-core causal flash attention, bf16 hi/lo split, ldmatrix loads.
// BM=BN=64, 128 threads (4 warps, 16 Q rows each).
// ---------------------------------------------------------------------------
constexpr int FQP = 136;  // pitch (bf16) for Q/K tiles
constexpr int FVP = 72;   // pitch (bf16) for Vt tiles
constexpr int FLASH_SMEM = (4 * 64 * FQP + 2 * 128 * FVP) * 2;  // 106496 B

__global__ __launch_bounds__(128, 2) void flash_mma(
    const __nv_bfloat16* __restrict__ Qh, const __nv_bfloat16* __restrict__ Ql,
    const __nv_bfloat16* __restrict__ Kh, const __nv_bfloat16* __restrict__ Kl,
    const __nv_bfloat16* __restrict__ Vh, const __nv_bfloat16* __restrict__ Vl,
    __nv_bfloat16* __restrict__ Oh, __nv_bfloat16* __restrict__ Ol)
{
    extern __shared__ __nv_bfloat16 sm[];
    __nv_bfloat16* sQh = sm;
    __nv_bfloat16* sQl = sQh + 64 * FQP;
    __nv_bfloat16* sKh = sQl + 64 * FQP;
    __nv_bfloat16* sKl = sKh + 64 * FQP;
    __nv_bfloat16* sVh = sKl + 64 * FQP;
    __nv_bfloat16* sVl = sVh + 128 * FVP;

    const int qtile = blockIdx.x;
    const int h     = blockIdx.y;
    const int bi    = blockIdx.z;
    const int kh    = h / GQ;
    const int tid   = threadIdx.x;
    const int lane  = tid & 31;
    const int wid   = tid >> 5;
    const int grp   = lane >> 2;
    const int tig   = lane & 3;
    const int q0    = qtile * 64;

    // ldmatrix lane->address components
    const int lrow  = lane & 15;
    const int lcoff = (lane >> 4) * 8;
    const int brow  = (lane & 7) + ((lane >> 4) << 3);
    const int bcoff = ((lane >> 3) & 1) * 8;

    {
        const __nv_bfloat16* qgh = Qh + (((size_t)bi * NH + h) * SEQ + q0) * HD;
        const __nv_bfloat16* qgl = Ql + (((size_t)bi * NH + h) * SEQ + q0) * HD;
        for (int i = tid; i < 64 * 16; i += 128) {
            int r = i >> 4, c = (i & 15) * 8;
            *(uint4*)&sQh[r * FQP + c] = *(const uint4*)&qgh[(size_t)r * HD + c];
            *(uint4*)&sQl[r * FQP + c] = *(const uint4*)&qgl[(size_t)r * HD + c];
        }
    }

    const __nv_bfloat16* kgh = Kh + (((size_t)bi * NKV + kh) * SEQ) * HD;
    const __nv_bfloat16* kgl = Kl + (((size_t)bi * NKV + kh) * SEQ) * HD;
    const __nv_bfloat16* vgh = Vh + (((size_t)bi * NKV + kh) * HD) * SEQ;
    const __nv_bfloat16* vgl = Vl + (((size_t)bi * NKV + kh) * HD) * SEQ;

    float o[16][4];
#pragma unroll
    for (int nt = 0; nt < 16; nt++)
#pragma unroll
        for (int e = 0; e < 4; e++) o[nt][e] = 0.f;
    float m0 = -1e30f, m1 = -1e30f, l0 = 0.f, l1 = 0.f;

    const int ntiles = qtile + 1;
    for (int t = 0; t < ntiles; ++t) {
        const int k0 = t * 64;
        __syncthreads();
        for (int i = tid; i < 64 * 16; i += 128) {
            int r = i >> 4, c = (i & 15) * 8;
            *(uint4*)&sKh[r * FQP + c] = *(const uint4*)&kgh[(size_t)(k0 + r) * HD + c];
            *(uint4*)&sKl[r * FQP + c] = *(const uint4*)&kgl[(size_t)(k0 + r) * HD + c];
        }
        for (int i = tid; i < 128 * 8; i += 128) {
            int r = i >> 3, c = (i & 7) * 8;
            *(uint4*)&sVh[r * FVP + c] = *(const uint4*)&vgh[(size_t)r * SEQ + k0 + c];
            *(uint4*)&sVl[r * FVP + c] = *(const uint4*)&vgl[(size_t)r * SEQ + k0 + c];
        }
        __syncthreads();

        float s[8][4];
#pragma unroll
        for (int nt = 0; nt < 8; nt++)
#pragma unroll
            for (int e = 0; e < 4; e++) s[nt][e] = 0.f;

#pragma unroll
        for (int kk = 0; kk < 128; kk += 16) {
            uint32_t ah[4], al[4];
            const int acol = kk + lcoff;
            ldsm4(ah, &sQh[(wid * 16 + lrow) * FQP + acol]);
            ldsm4(al, &sQl[(wid * 16 + lrow) * FQP + acol]);
#pragma unroll
            for (int np = 0; np < 4; np++) {
                const int br = np * 16 + brow;
                const int bc = kk + bcoff;
                uint32_t bh[4], bl[4];
                ldsm4(bh, &sKh[br * FQP + bc]);
                ldsm4(bl, &sKl[br * FQP + bc]);
                mma16816(s[2 * np    ], ah, bh);
                mma16816(s[2 * np    ], al, bh);
                mma16816(s[2 * np    ], ah, bl);
                mma16816(s[2 * np + 1], ah, bh + 2);
                mma16816(s[2 * np + 1], al, bh + 2);
                mma16816(s[2 * np + 1], ah, bl + 2);
            }
        }

        if (t == qtile) {
            const int r0 = q0 + wid * 16 + grp;
#pragma unroll
            for (int nt = 0; nt < 8; nt++) {
                const int c = k0 + nt * 8 + tig * 2;
                if (c     > r0)     s[nt][0] = -1e30f;
                if (c + 1 > r0)     s[nt][1] = -1e30f;
                if (c     > r0 + 8) s[nt][2] = -1e30f;
                if (c + 1 > r0 + 8) s[nt][3] = -1e30f;
            }
        }

        float mx0 = -1e30f, mx1 = -1e30f;
#pragma unroll
        for (int nt = 0; nt < 8; nt++) {
            mx0 = fmaxf(mx0, fmaxf(s[nt][0], s[nt][1]));
            mx1 = fmaxf(mx1, fmaxf(s[nt][2], s[nt][3]));
        }
        mx0 = fmaxf(mx0, __shfl_xor_sync(0xffffffffu, mx0, 1));
        mx0 = fmaxf(mx0, __shfl_xor_sync(0xffffffffu, mx0, 2));
        mx1 = fmaxf(mx1, __shfl_xor_sync(0xffffffffu, mx1, 1));
        mx1 = fmaxf(mx1, __shfl_xor_sync(0xffffffffu, mx1, 2));

        const float nm0 = fmaxf(m0, mx0);
        const float nm1 = fmaxf(m1, mx1);
        const float a0 = __expf(m0 - nm0);
        const float a1 = __expf(m1 - nm1);
        m0 = nm0; m1 = nm1;

        float rs0 = 0.f, rs1 = 0.f;
#pragma unroll
        for (int nt = 0; nt < 8; nt++) {
            s[nt][0] = __expf(s[nt][0] - m0);
            s[nt][1] = __expf(s[nt][1] - m0);
            s[nt][2] = __expf(s[nt][2] - m1);
            s[nt][3] = __expf(s[nt][3] - m1);
            rs0 += s[nt][0] + s[nt][1];
            rs1 += s[nt][2] + s[nt][3];
        }
        rs0 += __shfl_xor_sync(0xffffffffu, rs0, 1);
        rs0 += __shfl_xor_sync(0xffffffffu, rs0, 2);
        rs1 += __shfl_xor_sync(0xffffffffu, rs1, 1);
        rs1 += __shfl_xor_sync(0xffffffffu, rs1, 2);
        l0 = l0 * a0 + rs0;
        l1 = l1 * a1 + rs1;

#pragma unroll
        for (int nt = 0; nt < 16; nt++) {
            o[nt][0] *= a0; o[nt][1] *= a0;
            o[nt][2] *= a1; o[nt][3] *= a1;
        }

#pragma unroll
        for (int ks = 0; ks < 4; ks++) {
            uint32_t ph[4], pl[4];
            ph[0] = pack_hilo(s[2 * ks][0],     s[2 * ks][1],     pl[0]);
            ph[1] = pack_hilo(s[2 * ks][2],     s[2 * ks][3],     pl[1]);
            ph[2] = pack_hilo(s[2 * ks + 1][0], s[2 * ks + 1][1], pl[2]);
            ph[3] = pack_hilo(s[2 * ks + 1][2], s[2 * ks + 1][3], pl[3]);
            const int bc = ks * 16 + bcoff;
#pragma unroll
            for (int np = 0; np < 8; np++) {
                const int br = np * 16 + brow;
                uint32_t vh4[4], vl4[4];
                ldsm4(vh4, &sVh[br * FVP + bc]);
                ldsm4(vl4, &sVl[br * FVP + bc]);
                mma16816(o[2 * np    ], ph, vh4);
                mma16816(o[2 * np    ], pl, vh4);
                mma16816(o[2 * np    ], ph, vl4);
                mma16816(o[2 * np + 1], ph, vh4 + 2);
                mma16816(o[2 * np + 1], pl, vh4 + 2);
                mma16816(o[2 * np + 1], ph, vl4 + 2);
            }
        }
    }

    const float i0 = 1.0f / l0;
    const float i1 = 1.0f / l1;
    const size_t row0 = (size_t)bi * SEQ + q0 + wid * 16 + grp;
    const size_t row1 = row0 + 8;
    const int colb = h * HD + tig * 2;
#pragma unroll
    for (int nt = 0; nt < 16; nt++) {
        uint32_t lo;
        uint32_t hi = pack_hilo(o[nt][0] * i0, o[nt][1] * i0, lo);
        *(uint32_t*)&Oh[row0 * (NH * HD) + colb + nt * 8] = hi;
        *(uint32_t*)&Ol[row0 * (NH * HD) + colb + nt * 8] = lo;
        hi = pack_hilo(o[nt][2] * i1, o[nt][3] * i1, lo);
        *(uint32_t*)&Oh[row1 * (NH * HD) + colb + nt * 8] = hi;
        *(uint32_t*)&Ol[row1 * (NH * HD) + colb + nt * 8] = lo;
    }
}

// ---------------------------------------------------------------------------
// kernel_launch
// ---------------------------------------------------------------------------
extern "C" void kernel_launch(void* const* d_in, const int* in_sizes, int n_in,
                              void* d_out, int out_size)
{
    const float* hidden = (const float*)d_in[0];
    const float* cosb   = (const float*)d_in[1];
    const float* sinb   = (const float*)d_in[2];
    const float* wq     = (const float*)d_in[3];
    const float* wk     = (const float*)d_in[4];
    const float* wv     = (const float*)d_in[5];
    const float* wo     = (const float*)d_in[6];
    const float* qg     = (const float*)d_in[7];
    const float* kg     = (const float*)d_in[8];

    float* out  = (float*)d_out;
    float* kout = out  + (size_t)NB * SEQ * HDIM;
    float* vout = kout + (size_t)NB * NKV * SEQ * HD;

    __nv_bfloat16 *hidh, *hidl, *wqkvh, *wqkvl, *woh, *wol, *aoh, *aol;
    __nv_bfloat16 *qh, *ql, *kh, *kl, *vh, *vl;
    float *qkv;
    cudaGetSymbolAddress((void**)&hidh,  g_hid_h);
    cudaGetSymbolAddress((void**)&hidl,  g_hid_l);
    cudaGetSymbolAddress((void**)&wqkvh, g_wqkv_h);
    cudaGetSymbolAddress((void**)&wqkvl, g_wqkv_l);
    cudaGetSymbolAddress((void**)&woh,   g_wo_h);
    cudaGetSymbolAddress((void**)&wol,   g_wo_l);
    cudaGetSymbolAddress((void**)&aoh,   g_ao_h);
    cudaGetSymbolAddress((void**)&aol,   g_ao_l);
    cudaGetSymbolAddress((void**)&qkv,   g_qkv);
    cudaGetSymbolAddress((void**)&qh,    g_qh);
    cudaGetSymbolAddress((void**)&ql,    g_ql);
    cudaGetSymbolAddress((void**)&kh,    g_kh);
    cudaGetSymbolAddress((void**)&kl,    g_kl);
    cudaGetSymbolAddress((void**)&vh,    g_vh);
    cudaGetSymbolAddress((void**)&vl,    g_vl);

    cudaFuncSetAttribute(flash_mma, cudaFuncAttributeMaxDynamicSharedMemorySize, FLASH_SMEM);
    cudaFuncSetAttribute(gemm_bf16x2, cudaFuncAttributeMaxDynamicSharedMemorySize, GEMM_SMEM);

    // fp32 -> bf16 hi/lo splits
    const size_t nHid = (size_t)MROWS * HDIM;
    const size_t nWq  = (size_t)NH  * HD * HDIM;
    const size_t nWk  = (size_t)NKV * HD * HDIM;
    split_bf16<<<(int)(nHid / 1024), 256>>>((const float4*)hidden, hidh, hidl);
    split_bf16<<<(int)(nWq  / 1024), 256>>>((const float4*)wq, wqkvh, wqkvl);
    split_bf16<<<(int)(nWk  / 1024), 256>>>((const float4*)wk, wqkvh + nWq, wqkvl + nWq);
    split_bf16<<<(int)(nWk  / 1024), 256>>>((const float4*)wv, wqkvh + nWq + nWk, wqkvl + nWq + nWk);
    split_bf16<<<(int)(nWq  / 1024), 256>>>((const float4*)wo, woh, wol);

    // Fused QKV projection
    gemm_bf16x2<<<dim3(NQKV / 128, MROWS / 128), 256, GEMM_SMEM>>>(
        hidh, hidl, wqkvh, wqkvl, qkv, MROWS, NQKV, HDIM);

    // RMSNorm + RoPE -> bf16 hi/lo operands (+ fp32 K into d_out)
    norm_rope_q<<<(MROWS * NH ) / 8, 256>>>(qkv, qh, ql, cosb, sinb, qg);
    norm_rope_k<<<(MROWS * NKV) / 8, 256>>>(qkv, kout, kh, kl, cosb, sinb, kg);

    // V: fp32 into d_out's new_v; bf16 hi/lo transposed (b,KV,D,s)
    v_transpose<<<(NB * SEQ * NKV * HD / 4) / 256, 256>>>((const float4*)qkv, (float4*)vout);
    vtrans_split<<<dim3(SEQ / 32, HD / 32, NB * NKV), dim3(32, 8)>>>(qkv, vh, vl);

    // Tensor-core causal GQA flash attention -> bf16 hi/lo O
    flash_mma<<<dim3(SEQ / 64, NH, NB), 128, FLASH_SMEM>>>(
        qh, ql, kh, kl, vh, vl, aoh, aol);

    // Output projection
    gemm_bf16x2<<<dim3(HDIM / 128, MROWS / 128), 256, GEMM_SMEM>>>(
        aoh, aol, woh, wol, out, MROWS, HDIM, NH * HD);
}

// round 7
// speedup vs baseline: 3.8005x; 1.0457x over previous
#include <cuda_runtime.h>
#include <cuda_bf16.h>
#include <cstdint>

// Problem constants
constexpr int NB   = 2;      // batch
constexpr int SEQ  = 2048;   // sequence
constexpr int HDIM = 2560;   // hidden
constexpr int NH   = 32;     // q heads
constexpr int NKV  = 8;      // kv heads
constexpr int HD   = 128;    // head dim
constexpr int GQ   = NH / NKV;
constexpr int MROWS = NB * SEQ;            // 4096
constexpr int NQKV  = (NH + 2 * NKV) * HD; // 6144
constexpr int KOFF  = NH * HD;             // 4096
constexpr int VOFF  = (NH + NKV) * HD;     // 5120
constexpr float SM_SCALE = 0.08838834764831845f;  // 1/sqrt(128)

// ---------------- device scratch (no allocation allowed) ----------------
__device__ __nv_bfloat16 g_hid_h [(size_t)MROWS * HDIM];
__device__ __nv_bfloat16 g_hid_l [(size_t)MROWS * HDIM];
__device__ __nv_bfloat16 g_wqkv_h[(size_t)NQKV * HDIM];
__device__ __nv_bfloat16 g_wqkv_l[(size_t)NQKV * HDIM];
__device__ __nv_bfloat16 g_wo_h  [(size_t)HDIM * NH * HD];
__device__ __nv_bfloat16 g_wo_l  [(size_t)HDIM * NH * HD];
__device__ __nv_bfloat16 g_ao_h  [(size_t)MROWS * NH * HD];
__device__ __nv_bfloat16 g_ao_l  [(size_t)MROWS * NH * HD];
__device__ float g_qkv[(size_t)MROWS * NQKV];       // 96MB
// bf16 hi/lo attention operands
__device__ __nv_bfloat16 g_qh[(size_t)NB * NH  * SEQ * HD];  // (b,H,s,D), pre-scaled
__device__ __nv_bfloat16 g_ql[(size_t)NB * NH  * SEQ * HD];
__device__ __nv_bfloat16 g_kh[(size_t)NB * NKV * SEQ * HD];  // (b,KV,s,D)
__device__ __nv_bfloat16 g_kl[(size_t)NB * NKV * SEQ * HD];
__device__ __nv_bfloat16 g_vh[(size_t)NB * NKV * HD * SEQ];  // (b,KV,D,s) transposed
__device__ __nv_bfloat16 g_vl[(size_t)NB * NKV * HD * SEQ];

// ---------------------------------------------------------------------------
// cp.async / ldmatrix helpers
// ---------------------------------------------------------------------------
__device__ __forceinline__ void cp16(uint32_t smem, const __nv_bfloat16* gmem)
{
    asm volatile("cp.async.cg.shared.global [%0], [%1], 16;\n" :: "r"(smem), "l"(gmem));
}
#define CP_COMMIT() asm volatile("cp.async.commit_group;\n" ::: "memory")
#define CP_WAIT(n)  asm volatile("cp.async.wait_group %0;\n" :: "n"(n) : "memory")

__device__ __forceinline__ void ldsm4(uint32_t* r, const __nv_bfloat16* p)
{
    uint32_t a = (uint32_t)__cvta_generic_to_shared(p);
    asm volatile("ldmatrix.sync.aligned.m8n8.x4.shared.b16 {%0,%1,%2,%3}, [%4];"
        : "=r"(r[0]), "=r"(r[1]), "=r"(r[2]), "=r"(r[3]) : "r"(a));
}

// ---------------------------------------------------------------------------
// fp32 -> bf16 hi/lo split
// ---------------------------------------------------------------------------
__global__ __launch_bounds__(256) void split_bf16(
    const float4* __restrict__ in, __nv_bfloat16* __restrict__ hi,
    __nv_bfloat16* __restrict__ lo)
{
    const size_t i = (size_t)blockIdx.x * 256 + threadIdx.x;
    float4 x = in[i];
    __nv_bfloat16 h[4], l[4];
    float xs[4] = {x.x, x.y, x.z, x.w};
#pragma unroll
    for (int j = 0; j < 4; j++) {
        h[j] = __float2bfloat16(xs[j]);
        l[j] = __float2bfloat16(xs[j] - __bfloat162float(h[j]));
    }
    *(uint2*)&hi[i * 4] = *(uint2*)h;
    *(uint2*)&lo[i * 4] = *(uint2*)l;
}

// ---------------------------------------------------------------------------
// mma.m16n8k16 bf16 wrapper
// ---------------------------------------------------------------------------
__device__ __forceinline__ void mma16816(float* c, const uint32_t* a, const uint32_t* b)
{
    asm volatile(
        "mma.sync.aligned.m16n8k16.row.col.f32.bf16.bf16.f32 "
        "{%0,%1,%2,%3}, {%4,%5,%6,%7}, {%8,%9}, {%0,%1,%2,%3};"
        : "+f"(c[0]), "+f"(c[1]), "+f"(c[2]), "+f"(c[3])
        : "r"(a[0]), "r"(a[1]), "r"(a[2]), "r"(a[3]), "r"(b[0]), "r"(b[1]));
}

__device__ __forceinline__ uint32_t pack_hilo(float x, float y, uint32_t& lo)
{
    __nv_bfloat162 h = __float22bfloat162_rn(make_float2(x, y));
    float rx = x - __bfloat162float(h.x);
    float ry = y - __bfloat162float(h.y);
    __nv_bfloat162 l = __float22bfloat162_rn(make_float2(rx, ry));
    lo = *(uint32_t*)&l;
    return *(uint32_t*)&h;
}

// ---------------------------------------------------------------------------
// bf16-split tensor-core GEMM: C[M,N] = A[M,K] @ B[N,K]^T   (fp32 accurate)
// BK=64, 2-stage cp.async pipeline, ONE __syncthreads per iteration.
// Block 128x128, 256 threads (8 warps, 32x64 warp tile), 1 CTA/SM.
// ---------------------------------------------------------------------------
constexpr int GPAD = 72;                      // smem row pitch (bf16): 144B, ldsm conflict-free
constexpr int GSTG = 128 * GPAD;              // bf16 per matrix per stage (9216)
constexpr int GEMM_SMEM = 2 * 4 * GSTG * 2;   // 147456 bytes

__global__ __launch_bounds__(256, 1) void gemm_bf16x2(
    const __nv_bfloat16* __restrict__ Ah, const __nv_bfloat16* __restrict__ Al,
    const __nv_bfloat16* __restrict__ Bh, const __nv_bfloat16* __restrict__ Bl,
    float* __restrict__ C, int M, int N, int K)
{
    extern __shared__ __nv_bfloat16 sb[];

    const int tid = threadIdx.x;
    const int bm = blockIdx.y * 128;
    const int bn = blockIdx.x * 128;
    const int lane = tid & 31;
    const int wid  = tid >> 5;
    const int wm = (wid & 3) * 32;
    const int wn = (wid >> 2) * 64;
    const int grp = lane >> 2;
    const int tig = lane & 3;

    // ldmatrix lane->address components
    const int lrow  = lane & 15;
    const int lcoff = (lane >> 4) * 8;
    const int brow  = (lane & 7) + ((lane >> 4) << 3);
    const int bcoff = ((lane >> 3) & 1) * 8;

    // copy geometry: per stage, per matrix: 128 rows x 8 chunks (16B).
    // 1024 chunks / 256 threads = 4 chunks each (c = tid + j*256).
    uint32_t soff[4];
    int grow[4], gcol[4];
#pragma unroll
    for (int j = 0; j < 4; j++) {
        int c = tid + j * 256;
        grow[j] = c >> 3;
        gcol[j] = (c & 7) * 8;
        soff[j] = (uint32_t)(grow[j] * GPAD + gcol[j]);
    }

    float acc[2][8][4];
#pragma unroll
    for (int mt = 0; mt < 2; mt++)
#pragma unroll
        for (int nt = 0; nt < 8; nt++)
#pragma unroll
            for (int e = 0; e < 4; e++) acc[mt][nt][e] = 0.f;

    uint32_t sbase = (uint32_t)__cvta_generic_to_shared(sb);
    const int nk = K / 64;

    // prologue: stage 0
#pragma unroll
    for (int j = 0; j < 4; j++) {
        cp16(sbase + (0 * GSTG + soff[j]) * 2, Ah + (size_t)(bm + grow[j]) * K + gcol[j]);
        cp16(sbase + (1 * GSTG + soff[j]) * 2, Al + (size_t)(bm + grow[j]) * K + gcol[j]);
        cp16(sbase + (2 * GSTG + soff[j]) * 2, Bh + (size_t)(bn + grow[j]) * K + gcol[j]);
        cp16(sbase + (3 * GSTG + soff[j]) * 2, Bl + (size_t)(bn + grow[j]) * K + gcol[j]);
    }
    CP_COMMIT();

    for (int i = 0; i < nk; i++) {
        const __nv_bfloat16* cur = sb + (size_t)(i & 1) * 4 * GSTG;

        CP_WAIT(0);
        __syncthreads();

        if (i + 1 < nk) {
            const uint32_t nxt = sbase + (uint32_t)(((i + 1) & 1) * 4 * GSTG) * 2;
            const int k0 = (i + 1) * 64;
#pragma unroll
            for (int j = 0; j < 4; j++) {
                cp16(nxt + (0 * GSTG + soff[j]) * 2, Ah + (size_t)(bm + grow[j]) * K + k0 + gcol[j]);
                cp16(nxt + (1 * GSTG + soff[j]) * 2, Al + (size_t)(bm + grow[j]) * K + k0 + gcol[j]);
                cp16(nxt + (2 * GSTG + soff[j]) * 2, Bh + (size_t)(bn + grow[j]) * K + k0 + gcol[j]);
                cp16(nxt + (3 * GSTG + soff[j]) * 2, Bl + (size_t)(bn + grow[j]) * K + k0 + gcol[j]);
            }
            CP_COMMIT();
        }

        const __nv_bfloat16* sAh = cur;
        const __nv_bfloat16* sAl = cur + 1 * GSTG;
        const __nv_bfloat16* sBh = cur + 2 * GSTG;
        const __nv_bfloat16* sBl = cur + 3 * GSTG;

#pragma unroll
        for (int kk = 0; kk < 64; kk += 16) {
            uint32_t afh[2][4], afl[2][4];
            const int acol = kk + lcoff;
            ldsm4(afh[0], &sAh[(wm + lrow     ) * GPAD + acol]);
            ldsm4(afh[1], &sAh[(wm + 16 + lrow) * GPAD + acol]);
            ldsm4(afl[0], &sAl[(wm + lrow     ) * GPAD + acol]);
            ldsm4(afl[1], &sAl[(wm + 16 + lrow) * GPAD + acol]);
#pragma unroll
            for (int np = 0; np < 4; np++) {
                const int br = wn + np * 16 + brow;
                const int bc = kk + bcoff;
                uint32_t bh[4], bl[4];
                ldsm4(bh, &sBh[br * GPAD + bc]);
                ldsm4(bl, &sBl[br * GPAD + bc]);
#pragma unroll
                for (int mt = 0; mt < 2; mt++) {
                    mma16816(acc[mt][2 * np    ], afh[mt], bh);
                    mma16816(acc[mt][2 * np    ], afh[mt], bl);
                    mma16816(acc[mt][2 * np    ], afl[mt], bh);
                    mma16816(acc[mt][2 * np + 1], afh[mt], bh + 2);
                    mma16816(acc[mt][2 * np + 1], afh[mt], bl + 2);
                    mma16816(acc[mt][2 * np + 1], afl[mt], bh + 2);
                }
            }
        }
    }

#pragma unroll
    for (int mt = 0; mt < 2; mt++) {
        const int row = bm + wm + mt * 16 + grp;
#pragma unroll
        for (int nt = 0; nt < 8; nt++) {
            const int col = bn + wn + nt * 8 + tig * 2;
            *(float2*)&C[(size_t)row * N + col]       = make_float2(acc[mt][nt][0], acc[mt][nt][1]);
            *(float2*)&C[(size_t)(row + 8) * N + col] = make_float2(acc[mt][nt][2], acc[mt][nt][3]);
        }
    }
}

// ---------------------------------------------------------------------------
// RMSNorm + RoPE for Q: reads qkv fp32, writes bf16 hi/lo to (b,H,s,D),
// pre-scaled by 1/sqrt(D). One warp per row.
// ---------------------------------------------------------------------------
__global__ __launch_bounds__(256) void norm_rope_q(
    const float* __restrict__ qkv,
    __nv_bfloat16* __restrict__ oh, __nv_bfloat16* __restrict__ ol,
    const float* __restrict__ cs, const float* __restrict__ sn,
    const float* __restrict__ gamma)
{
    const int warp = (blockIdx.x * 256 + threadIdx.x) >> 5;
    const int lane = threadIdx.x & 31;
    const int h  = warp % NH;
    const int bs = warp / NH;
    const int sp = bs % SEQ;
    const int bi = bs / SEQ;

    const float* x = qkv + (size_t)bs * NQKV + h * HD;
    float e0 = x[lane], e1 = x[lane + 32], e2 = x[lane + 64], e3 = x[lane + 96];

    float ssq = e0 * e0 + e1 * e1 + e2 * e2 + e3 * e3;
#pragma unroll
    for (int o = 16; o; o >>= 1) ssq += __shfl_xor_sync(0xffffffffu, ssq, o);
    const float r = rsqrtf(ssq * (1.0f / HD) + 1e-6f);

    e0 *= r * gamma[lane];      e1 *= r * gamma[lane + 32];
    e2 *= r * gamma[lane + 64]; e3 *= r * gamma[lane + 96];

    const float* cp = cs + (size_t)bs * HD;
    const float* sg = sn + (size_t)bs * HD;
    float o4[4];
    o4[0] = (e0 * cp[lane]      - e2 * sg[lane])      * SM_SCALE;
    o4[1] = (e1 * cp[lane + 32] - e3 * sg[lane + 32]) * SM_SCALE;
    o4[2] = (e2 * cp[lane + 64] + e0 * sg[lane + 64]) * SM_SCALE;
    o4[3] = (e3 * cp[lane + 96] + e1 * sg[lane + 96]) * SM_SCALE;

    const size_t ob = (((size_t)bi * NH + h) * SEQ + sp) * HD;
#pragma unroll
    for (int j = 0; j < 4; j++) {
        __nv_bfloat16 hv = __float2bfloat16(o4[j]);
        oh[ob + lane + 32 * j] = hv;
        ol[ob + lane + 32 * j] = __float2bfloat16(o4[j] - __bfloat162float(hv));
    }
}

// ---------------------------------------------------------------------------
// RMSNorm + RoPE for K: writes fp32 (b,KV,s,D) into d_out AND bf16 hi/lo.
// ---------------------------------------------------------------------------
__global__ __launch_bounds__(256) void norm_rope_k(
    const float* __restrict__ qkv, float* __restrict__ kout,
    __nv_bfloat16* __restrict__ oh, __nv_bfloat16* __restrict__ ol,
    const float* __restrict__ cs, const float* __restrict__ sn,
    const float* __restrict__ gamma)
{
    const int warp = (blockIdx.x * 256 + threadIdx.x) >> 5;
    const int lane = threadIdx.x & 31;
    const int h  = warp % NKV;
    const int bs = warp / NKV;
    const int sp = bs % SEQ;
    const int bi = bs / SEQ;

    const float* x = qkv + (size_t)bs * NQKV + KOFF + h * HD;
    float e0 = x[lane], e1 = x[lane + 32], e2 = x[lane + 64], e3 = x[lane + 96];

    float ssq = e0 * e0 + e1 * e1 + e2 * e2 + e3 * e3;
#pragma unroll
    for (int o = 16; o; o >>= 1) ssq += __shfl_xor_sync(0xffffffffu, ssq, o);
    const float r = rsqrtf(ssq * (1.0f / HD) + 1e-6f);

    e0 *= r * gamma[lane];      e1 *= r * gamma[lane + 32];
    e2 *= r * gamma[lane + 64]; e3 *= r * gamma[lane + 96];

    const float* cp = cs + (size_t)bs * HD;
    const float* sg = sn + (size_t)bs * HD;
    float o4[4];
    o4[0] = e0 * cp[lane]      - e2 * sg[lane];
    o4[1] = e1 * cp[lane + 32] - e3 * sg[lane + 32];
    o4[2] = e2 * cp[lane + 64] + e0 * sg[lane + 64];
    o4[3] = e3 * cp[lane + 96] + e1 * sg[lane + 96];

    const size_t ob = (((size_t)bi * NKV + h) * SEQ + sp) * HD;
#pragma unroll
    for (int j = 0; j < 4; j++) {
        kout[ob + lane + 32 * j] = o4[j];
        __nv_bfloat16 hv = __float2bfloat16(o4[j]);
        oh[ob + lane + 32 * j] = hv;
        ol[ob + lane + 32 * j] = __float2bfloat16(o4[j] - __bfloat162float(hv));
    }
}

// ---------------------------------------------------------------------------
// V transpose (fp32): qkv V region -> (b,KV,s,D) in d_out
// ---------------------------------------------------------------------------
__global__ __launch_bounds__(256) void v_transpose(
    const float4* __restrict__ qkv4, float4* __restrict__ out)
{
    const size_t i = (size_t)blockIdx.x * 256 + threadIdx.x;
    const int d4 = (int)(i & 31);
    const int kh = (int)((i >> 5) & (NKV - 1));
    const int sp = (int)((i >> 8) & (SEQ - 1));
    const int bi = (int)(i >> 19);
    const size_t src = ((size_t)(bi * SEQ + sp) * NQKV + VOFF + kh * HD) / 4 + d4;
    const size_t dst = (((size_t)bi * NKV + kh) * SEQ + sp) * 32 + d4;
    out[dst] = qkv4[src];
}

// ---------------------------------------------------------------------------
// V transpose + split (bf16): qkv V region -> (b,KV,D,s) hi/lo
// ---------------------------------------------------------------------------
__global__ void vtrans_split(
    const float* __restrict__ qkv,
    __nv_bfloat16* __restrict__ vh, __nv_bfloat16* __restrict__ vl)
{
    __shared__ float t[32][33];
    const int s0 = blockIdx.x * 32, d0 = blockIdx.y * 32;
    const int bz = blockIdx.z;                 // bi*NKV + kh
    const int bi = bz / NKV, kh = bz % NKV;
    const int tx = threadIdx.x, ty = threadIdx.y;

#pragma unroll
    for (int j = 0; j < 4; j++) {
        int s = s0 + ty + j * 8;
        t[ty + j * 8][tx] =
            qkv[(size_t)(bi * SEQ + s) * NQKV + VOFF + kh * HD + d0 + tx];
    }
    __syncthreads();
#pragma unroll
    for (int j = 0; j < 4; j++) {
        int d = d0 + ty + j * 8;
        float v = t[tx][ty + j * 8];
        __nv_bfloat16 hv = __float2bfloat16(v);
        size_t idx = ((size_t)bz * HD + d) * SEQ + s0 + tx;
        vh[idx] = hv;
        vl[idx] = __float2bfloat16(v - __bfloat162float(hv));
    }
}

// ---------------------------------------------------------------------------
// Tensor-core causal flash attention, bf16 hi/lo split, ldmatrix loads.
// BM=BN=64, 128 threads (4 warps, 16 Q rows each).
// ---------------------------------------------------------------------------
constexpr int FQP = 136;  // pitch (bf16) for Q/K tiles
constexpr int FVP = 72;   // pitch (bf16) for Vt tiles
constexpr int FLASH_SMEM = (4 * 64 * FQP + 2 * 128 * FVP) * 2;  // 106496 B

__global__ __launch_bounds__(128, 2) void flash_mma(
    const __nv_bfloat16* __restrict__ Qh, const __nv_bfloat16* __restrict__ Ql,
    const __nv_bfloat16* __restrict__ Kh, const __nv_bfloat16* __restrict__ Kl,
    const __nv_bfloat16* __restrict__ Vh, const __nv_bfloat16* __restrict__ Vl,
    __nv_bfloat16* __restrict__ Oh, __nv_bfloat16* __restrict__ Ol)
{
    extern __shared__ __nv_bfloat16 sm[];
    __nv_bfloat16* sQh = sm;
    __nv_bfloat16* sQl = sQh + 64 * FQP;
    __nv_bfloat16* sKh = sQl + 64 * FQP;
    __nv_bfloat16* sKl = sKh + 64 * FQP;
    __nv_bfloat16* sVh = sKl + 64 * FQP;
    __nv_bfloat16* sVl = sVh + 128 * FVP;

    const int qtile = blockIdx.x;
    const int h     = blockIdx.y;
    const int bi    = blockIdx.z;
    const int kh    = h / GQ;
    const int tid   = threadIdx.x;
    const int lane  = tid & 31;
    const int wid   = tid >> 5;
    const int grp   = lane >> 2;
    const int tig   = lane & 3;
    const int q0    = qtile * 64;

    const int lrow  = lane & 15;
    const int lcoff = (lane >> 4) * 8;
    const int brow  = (lane & 7) + ((lane >> 4) << 3);
    const int bcoff = ((lane >> 3) & 1) * 8;

    {
        const __nv_bfloat16* qgh = Qh + (((size_t)bi * NH + h) * SEQ + q0) * HD;
        const __nv_bfloat16* qgl = Ql + (((size_t)bi * NH + h) * SEQ + q0) * HD;
        for (int i = tid; i < 64 * 16; i += 128) {
            int r = i >> 4, c = (i & 15) * 8;
            *(uint4*)&sQh[r * FQP + c] = *(const uint4*)&qgh[(size_t)r * HD + c];
            *(uint4*)&sQl[r * FQP + c] = *(const uint4*)&qgl[(size_t)r * HD + c];
        }
    }

    const __nv_bfloat16* kgh = Kh + (((size_t)bi * NKV + kh) * SEQ) * HD;
    const __nv_bfloat16* kgl = Kl + (((size_t)bi * NKV + kh) * SEQ) * HD;
    const __nv_bfloat16* vgh = Vh + (((size_t)bi * NKV + kh) * HD) * SEQ;
    const __nv_bfloat16* vgl = Vl + (((size_t)bi * NKV + kh) * HD) * SEQ;

    float o[16][4];
#pragma unroll
    for (int nt = 0; nt < 16; nt++)
#pragma unroll
        for (int e = 0; e < 4; e++) o[nt][e] = 0.f;
    float m0 = -1e30f, m1 = -1e30f, l0 = 0.f, l1 = 0.f;

    const int ntiles = qtile + 1;
    for (int t = 0; t < ntiles; ++t) {
        const int k0 = t * 64;
        __syncthreads();
        for (int i = tid; i < 64 * 16; i += 128) {
            int r = i >> 4, c = (i & 15) * 8;
            *(uint4*)&sKh[r * FQP + c] = *(const uint4*)&kgh[(size_t)(k0 + r) * HD + c];
            *(uint4*)&sKl[r * FQP + c] = *(const uint4*)&kgl[(size_t)(k0 + r) * HD + c];
        }
        for (int i = tid; i < 128 * 8; i += 128) {
            int r = i >> 3, c = (i & 7) * 8;
            *(uint4*)&sVh[r * FVP + c] = *(const uint4*)&vgh[(size_t)r * SEQ + k0 + c];
            *(uint4*)&sVl[r * FVP + c] = *(const uint4*)&vgl[(size_t)r * SEQ + k0 + c];
        }
        __syncthreads();

        float s[8][4];
#pragma unroll
        for (int nt = 0; nt < 8; nt++)
#pragma unroll
            for (int e = 0; e < 4; e++) s[nt][e] = 0.f;

#pragma unroll
        for (int kk = 0; kk < 128; kk += 16) {
            uint32_t ah[4], al[4];
            const int acol = kk + lcoff;
            ldsm4(ah, &sQh[(wid * 16 + lrow) * FQP + acol]);
            ldsm4(al, &sQl[(wid * 16 + lrow) * FQP + acol]);
#pragma unroll
            for (int np = 0; np < 4; np++) {
                const int br = np * 16 + brow;
                const int bc = kk + bcoff;
                uint32_t bh[4], bl[4];
                ldsm4(bh, &sKh[br * FQP + bc]);
                ldsm4(bl, &sKl[br * FQP + bc]);
                mma16816(s[2 * np    ], ah, bh);
                mma16816(s[2 * np    ], al, bh);
                mma16816(s[2 * np    ], ah, bl);
                mma16816(s[2 * np + 1], ah, bh + 2);
                mma16816(s[2 * np + 1], al, bh + 2);
                mma16816(s[2 * np + 1], ah, bl + 2);
            }
        }

        if (t == qtile) {
            const int r0 = q0 + wid * 16 + grp;
#pragma unroll
            for (int nt = 0; nt < 8; nt++) {
                const int c = k0 + nt * 8 + tig * 2;
                if (c     > r0)     s[nt][0] = -1e30f;
                if (c + 1 > r0)     s[nt][1] = -1e30f;
                if (c     > r0 + 8) s[nt][2] = -1e30f;
                if (c + 1 > r0 + 8) s[nt][3] = -1e30f;
            }
        }

        float mx0 = -1e30f, mx1 = -1e30f;
#pragma unroll
        for (int nt = 0; nt < 8; nt++) {
            mx0 = fmaxf(mx0, fmaxf(s[nt][0], s[nt][1]));
            mx1 = fmaxf(mx1, fmaxf(s[nt][2], s[nt][3]));
        }
        mx0 = fmaxf(mx0, __shfl_xor_sync(0xffffffffu, mx0, 1));
        mx0 = fmaxf(mx0, __shfl_xor_sync(0xffffffffu, mx0, 2));
        mx1 = fmaxf(mx1, __shfl_xor_sync(0xffffffffu, mx1, 1));
        mx1 = fmaxf(mx1, __shfl_xor_sync(0xffffffffu, mx1, 2));

        const float nm0 = fmaxf(m0, mx0);
        const float nm1 = fmaxf(m1, mx1);
        const float a0 = __expf(m0 - nm0);
        const float a1 = __expf(m1 - nm1);
        m0 = nm0; m1 = nm1;

        float rs0 = 0.f, rs1 = 0.f;
#pragma unroll
        for (int nt = 0; nt < 8; nt++) {
            s[nt][0] = __expf(s[nt][0] - m0);
            s[nt][1] = __expf(s[nt][1] - m0);
            s[nt][2] = __expf(s[nt][2] - m1);
            s[nt][3] = __expf(s[nt][3] - m1);
            rs0 += s[nt][0] + s[nt][1];
            rs1 += s[nt][2] + s[nt][3];
        }
        rs0 += __shfl_xor_sync(0xffffffffu, rs0, 1);
        rs0 += __shfl_xor_sync(0xffffffffu, rs0, 2);
        rs1 += __shfl_xor_sync(0xffffffffu, rs1, 1);
        rs1 += __shfl_xor_sync(0xffffffffu, rs1, 2);
        l0 = l0 * a0 + rs0;
        l1 = l1 * a1 + rs1;

#pragma unroll
        for (int nt = 0; nt < 16; nt++) {
            o[nt][0] *= a0; o[nt][1] *= a0;
            o[nt][2] *= a1; o[nt][3] *= a1;
        }

#pragma unroll
        for (int ks = 0; ks < 4; ks++) {
            uint32_t ph[4], pl[4];
            ph[0] = pack_hilo(s[2 * ks][0],     s[2 * ks][1],     pl[0]);
            ph[1] = pack_hilo(s[2 * ks][2],     s[2 * ks][3],     pl[1]);
            ph[2] = pack_hilo(s[2 * ks + 1][0], s[2 * ks + 1][1], pl[2]);
            ph[3] = pack_hilo(s[2 * ks + 1][2], s[2 * ks + 1][3], pl[3]);
            const int bc = ks * 16 + bcoff;
#pragma unroll
            for (int np = 0; np < 8; np++) {
                const int br = np * 16 + brow;
                uint32_t vh4[4], vl4[4];
                ldsm4(vh4, &sVh[br * FVP + bc]);
                ldsm4(vl4, &sVl[br * FVP + bc]);
                mma16816(o[2 * np    ], ph, vh4);
                mma16816(o[2 * np    ], pl, vh4);
                mma16816(o[2 * np    ], ph, vl4);
                mma16816(o[2 * np + 1], ph, vh4 + 2);
                mma16816(o[2 * np + 1], pl, vh4 + 2);
                mma16816(o[2 * np + 1], ph, vl4 + 2);
            }
        }
    }

    const float i0 = 1.0f / l0;
    const float i1 = 1.0f / l1;
    const size_t row0 = (size_t)bi * SEQ + q0 + wid * 16 + grp;
    const size_t row1 = row0 + 8;
    const int colb = h * HD + tig * 2;
#pragma unroll
    for (int nt = 0; nt < 16; nt++) {
        uint32_t lo;
        uint32_t hi = pack_hilo(o[nt][0] * i0, o[nt][1] * i0, lo);
        *(uint32_t*)&Oh[row0 * (NH * HD) + colb + nt * 8] = hi;
        *(uint32_t*)&Ol[row0 * (NH * HD) + colb + nt * 8] = lo;
        hi = pack_hilo(o[nt][2] * i1, o[nt][3] * i1, lo);
        *(uint32_t*)&Oh[row1 * (NH * HD) + colb + nt * 8] = hi;
        *(uint32_t*)&Ol[row1 * (NH * HD) + colb + nt * 8] = lo;
    }
}

// ---------------------------------------------------------------------------
// kernel_launch
// ---------------------------------------------------------------------------
extern "C" void kernel_launch(void* const* d_in, const int* in_sizes, int n_in,
                              void* d_out, int out_size)
{
    const float* hidden = (const float*)d_in[0];
    const float* cosb   = (const float*)d_in[1];
    const float* sinb   = (const float*)d_in[2];
    const float* wq     = (const float*)d_in[3];
    const float* wk     = (const float*)d_in[4];
    const float* wv     = (const float*)d_in[5];
    const float* wo     = (const float*)d_in[6];
    const float* qg     = (const float*)d_in[7];
    const float* kg     = (const float*)d_in[8];

    float* out  = (float*)d_out;
    float* kout = out  + (size_t)NB * SEQ * HDIM;
    float* vout = kout + (size_t)NB * NKV * SEQ * HD;

    __nv_bfloat16 *hidh, *hidl, *wqkvh, *wqkvl, *woh, *wol, *aoh, *aol;
    __nv_bfloat16 *qh, *ql, *kh, *kl, *vh, *vl;
    float *qkv;
    cudaGetSymbolAddress((void**)&hidh,  g_hid_h);
    cudaGetSymbolAddress((void**)&hidl,  g_hid_l);
    cudaGetSymbolAddress((void**)&wqkvh, g_wqkv_h);
    cudaGetSymbolAddress((void**)&wqkvl, g_wqkv_l);
    cudaGetSymbolAddress((void**)&woh,   g_wo_h);
    cudaGetSymbolAddress((void**)&wol,   g_wo_l);
    cudaGetSymbolAddress((void**)&aoh,   g_ao_h);
    cudaGetSymbolAddress((void**)&aol,   g_ao_l);
    cudaGetSymbolAddress((void**)&qkv,   g_qkv);
    cudaGetSymbolAddress((void**)&qh,    g_qh);
    cudaGetSymbolAddress((void**)&ql,    g_ql);
    cudaGetSymbolAddress((void**)&kh,    g_kh);
    cudaGetSymbolAddress((void**)&kl,    g_kl);
    cudaGetSymbolAddress((void**)&vh,    g_vh);
    cudaGetSymbolAddress((void**)&vl,    g_vl);

    cudaFuncSetAttribute(flash_mma, cudaFuncAttributeMaxDynamicSharedMemorySize, FLASH_SMEM);
    cudaFuncSetAttribute(gemm_bf16x2, cudaFuncAttributeMaxDynamicSharedMemorySize, GEMM_SMEM);

    // fp32 -> bf16 hi/lo splits
    const size_t nHid = (size_t)MROWS * HDIM;
    const size_t nWq  = (size_t)NH  * HD * HDIM;
    const size_t nWk  = (size_t)NKV * HD * HDIM;
    split_bf16<<<(int)(nHid / 1024), 256>>>((const float4*)hidden, hidh, hidl);
    split_bf16<<<(int)(nWq  / 1024), 256>>>((const float4*)wq, wqkvh, wqkvl);
    split_bf16<<<(int)(nWk  / 1024), 256>>>((const float4*)wk, wqkvh + nWq, wqkvl + nWq);
    split_bf16<<<(int)(nWk  / 1024), 256>>>((const float4*)wv, wqkvh + nWq + nWk, wqkvl + nWq + nWk);
    split_bf16<<<(int)(nWq  / 1024), 256>>>((const float4*)wo, woh, wol);

    // Fused QKV projection
    gemm_bf16x2<<<dim3(NQKV / 128, MROWS / 128), 256, GEMM_SMEM>>>(
        hidh, hidl, wqkvh, wqkvl, qkv, MROWS, NQKV, HDIM);

    // RMSNorm + RoPE -> bf16 hi/lo operands (+ fp32 K into d_out)
    norm_rope_q<<<(MROWS * NH ) / 8, 256>>>(qkv, qh, ql, cosb, sinb, qg);
    norm_rope_k<<<(MROWS * NKV) / 8, 256>>>(qkv, kout, kh, kl, cosb, sinb, kg);

    // V: fp32 into d_out's new_v; bf16 hi/lo transposed (b,KV,D,s)
    v_transpose<<<(NB * SEQ * NKV * HD / 4) / 256, 256>>>((const float4*)qkv, (float4*)vout);
    vtrans_split<<<dim3(SEQ / 32, HD / 32, NB * NKV), dim3(32, 8)>>>(qkv, vh, vl);

    // Tensor-core causal GQA flash attention -> bf16 hi/lo O
    flash_mma<<<dim3(SEQ / 64, NH, NB), 128, FLASH_SMEM>>>(
        qh, ql, kh, kl, vh, vl, aoh, aol);

    // Output projection
    gemm_bf16x2<<<dim3(HDIM / 128, MROWS / 128), 256, GEMM_SMEM>>>(
        aoh, aol, woh, wol, out, MROWS, HDIM, NH * HD);
}

// round 8
// speedup vs baseline: 3.8240x; 1.0062x over previous
#include <cuda_runtime.h>
#include <cuda_bf16.h>
#include <cstdint>

// Problem constants
constexpr int NB   = 2;      // batch
constexpr int SEQ  = 2048;   // sequence
constexpr int HDIM = 2560;   // hidden
constexpr int NH   = 32;     // q heads
constexpr int NKV  = 8;      // kv heads
constexpr int HD   = 128;    // head dim
constexpr int GQ   = NH / NKV;
constexpr int MROWS = NB * SEQ;            // 4096
constexpr int NQKV  = (NH + 2 * NKV) * HD; // 6144
constexpr int KOFF  = NH * HD;             // 4096
constexpr int VOFF  = (NH + NKV) * HD;     // 5120
constexpr float SM_SCALE = 0.08838834764831845f;  // 1/sqrt(128)

// ---------------- device scratch (no allocation allowed) ----------------
__device__ __nv_bfloat16 g_hid_h [(size_t)MROWS * HDIM];
__device__ __nv_bfloat16 g_hid_l [(size_t)MROWS * HDIM];
__device__ __nv_bfloat16 g_wqkv_h[(size_t)NQKV * HDIM];
__device__ __nv_bfloat16 g_wqkv_l[(size_t)NQKV * HDIM];
__device__ __nv_bfloat16 g_wo_h  [(size_t)HDIM * NH * HD];
__device__ __nv_bfloat16 g_wo_l  [(size_t)HDIM * NH * HD];
__device__ __nv_bfloat16 g_ao_h  [(size_t)MROWS * NH * HD];
__device__ __nv_bfloat16 g_ao_l  [(size_t)MROWS * NH * HD];
__device__ float g_qkv[(size_t)MROWS * NQKV];       // 96MB
// bf16 hi/lo attention operands
__device__ __nv_bfloat16 g_qh[(size_t)NB * NH  * SEQ * HD];  // (b,H,s,D), pre-scaled
__device__ __nv_bfloat16 g_ql[(size_t)NB * NH  * SEQ * HD];
__device__ __nv_bfloat16 g_kh[(size_t)NB * NKV * SEQ * HD];  // (b,KV,s,D)
__device__ __nv_bfloat16 g_kl[(size_t)NB * NKV * SEQ * HD];
__device__ __nv_bfloat16 g_vh[(size_t)NB * NKV * HD * SEQ];  // (b,KV,D,s) transposed
__device__ __nv_bfloat16 g_vl[(size_t)NB * NKV * HD * SEQ];

// ---------------------------------------------------------------------------
// cp.async / ldmatrix helpers
// ---------------------------------------------------------------------------
__device__ __forceinline__ void cp16(uint32_t smem, const __nv_bfloat16* gmem)
{
    asm volatile("cp.async.cg.shared.global [%0], [%1], 16;\n" :: "r"(smem), "l"(gmem));
}
#define CP_COMMIT() asm volatile("cp.async.commit_group;\n" ::: "memory")
#define CP_WAIT(n)  asm volatile("cp.async.wait_group %0;\n" :: "n"(n) : "memory")

__device__ __forceinline__ void ldsm4(uint32_t* r, const __nv_bfloat16* p)
{
    uint32_t a = (uint32_t)__cvta_generic_to_shared(p);
    asm volatile("ldmatrix.sync.aligned.m8n8.x4.shared.b16 {%0,%1,%2,%3}, [%4];"
        : "=r"(r[0]), "=r"(r[1]), "=r"(r[2]), "=r"(r[3]) : "r"(a));
}

// ---------------------------------------------------------------------------
// fp32 -> bf16 hi/lo split
// ---------------------------------------------------------------------------
__global__ __launch_bounds__(256) void split_bf16(
    const float4* __restrict__ in, __nv_bfloat16* __restrict__ hi,
    __nv_bfloat16* __restrict__ lo)
{
    const size_t i = (size_t)blockIdx.x * 256 + threadIdx.x;
    float4 x = in[i];
    __nv_bfloat16 h[4], l[4];
    float xs[4] = {x.x, x.y, x.z, x.w};
#pragma unroll
    for (int j = 0; j < 4; j++) {
        h[j] = __float2bfloat16(xs[j]);
        l[j] = __float2bfloat16(xs[j] - __bfloat162float(h[j]));
    }
    *(uint2*)&hi[i * 4] = *(uint2*)h;
    *(uint2*)&lo[i * 4] = *(uint2*)l;
}

// ---------------------------------------------------------------------------
// mma.m16n8k16 bf16 wrapper
// ---------------------------------------------------------------------------
__device__ __forceinline__ void mma16816(float* c, const uint32_t* a, const uint32_t* b)
{
    asm volatile(
        "mma.sync.aligned.m16n8k16.row.col.f32.bf16.bf16.f32 "
        "{%0,%1,%2,%3}, {%4,%5,%6,%7}, {%8,%9}, {%0,%1,%2,%3};"
        : "+f"(c[0]), "+f"(c[1]), "+f"(c[2]), "+f"(c[3])
        : "r"(a[0]), "r"(a[1]), "r"(a[2]), "r"(a[3]), "r"(b[0]), "r"(b[1]));
}

__device__ __forceinline__ uint32_t pack_hilo(float x, float y, uint32_t& lo)
{
    __nv_bfloat162 h = __float22bfloat162_rn(make_float2(x, y));
    float rx = x - __bfloat162float(h.x);
    float ry = y - __bfloat162float(h.y);
    __nv_bfloat162 l = __float22bfloat162_rn(make_float2(rx, ry));
    lo = *(uint32_t*)&l;
    return *(uint32_t*)&h;
}

// ---------------------------------------------------------------------------
// bf16-split tensor-core GEMM: C[M,N] = A[M,K] @ B[N,K]^T   (fp32 accurate)
// BK=32, 2-stage cp.async pipeline, ONE __syncthreads per iteration,
// 2 CTAs/SM for barrier overlap (flash-style residency).
// Block 128x128, 256 threads (8 warps, 32x64 warp tile).
// ---------------------------------------------------------------------------
constexpr int GPAD = 40;                      // smem row pitch (bf16): 80B, ldsm conflict-free
constexpr int GSTG = 128 * GPAD;              // bf16 per matrix per stage (5120)
constexpr int GEMM_SMEM = 2 * 4 * GSTG * 2;   // 81920 bytes

__global__ __launch_bounds__(256, 2) void gemm_bf16x2(
    const __nv_bfloat16* __restrict__ Ah, const __nv_bfloat16* __restrict__ Al,
    const __nv_bfloat16* __restrict__ Bh, const __nv_bfloat16* __restrict__ Bl,
    float* __restrict__ C, int M, int N, int K)
{
    extern __shared__ __nv_bfloat16 sb[];

    const int tid = threadIdx.x;
    const int bm = blockIdx.y * 128;
    const int bn = blockIdx.x * 128;
    const int lane = tid & 31;
    const int wid  = tid >> 5;
    const int wm = (wid & 3) * 32;
    const int wn = (wid >> 2) * 64;
    const int grp = lane >> 2;
    const int tig = lane & 3;

    // ldmatrix lane->address components
    const int lrow  = lane & 15;
    const int lcoff = (lane >> 4) * 8;
    const int brow  = (lane & 7) + ((lane >> 4) << 3);
    const int bcoff = ((lane >> 3) & 1) * 8;

    // copy geometry: per stage, per matrix: 128 rows x 4 chunks (16B) = 512
    // chunks / 256 threads = 2 chunks each (c = tid + j*256).
    uint32_t soff[2];
    int grow[2], gcol[2];
#pragma unroll
    for (int j = 0; j < 2; j++) {
        int c = tid + j * 256;
        grow[j] = c >> 2;
        gcol[j] = (c & 3) * 8;
        soff[j] = (uint32_t)(grow[j] * GPAD + gcol[j]);
    }

    float acc[2][8][4];
#pragma unroll
    for (int mt = 0; mt < 2; mt++)
#pragma unroll
        for (int nt = 0; nt < 8; nt++)
#pragma unroll
            for (int e = 0; e < 4; e++) acc[mt][nt][e] = 0.f;

    uint32_t sbase = (uint32_t)__cvta_generic_to_shared(sb);
    const int nk = K / 32;

    // prologue: stage 0
#pragma unroll
    for (int j = 0; j < 2; j++) {
        cp16(sbase + (0 * GSTG + soff[j]) * 2, Ah + (size_t)(bm + grow[j]) * K + gcol[j]);
        cp16(sbase + (1 * GSTG + soff[j]) * 2, Al + (size_t)(bm + grow[j]) * K + gcol[j]);
        cp16(sbase + (2 * GSTG + soff[j]) * 2, Bh + (size_t)(bn + grow[j]) * K + gcol[j]);
        cp16(sbase + (3 * GSTG + soff[j]) * 2, Bl + (size_t)(bn + grow[j]) * K + gcol[j]);
    }
    CP_COMMIT();

    for (int i = 0; i < nk; i++) {
        const __nv_bfloat16* cur = sb + (size_t)(i & 1) * 4 * GSTG;

        CP_WAIT(0);
        __syncthreads();

        if (i + 1 < nk) {
            const uint32_t nxt = sbase + (uint32_t)(((i + 1) & 1) * 4 * GSTG) * 2;
            const int k0 = (i + 1) * 32;
#pragma unroll
            for (int j = 0; j < 2; j++) {
                cp16(nxt + (0 * GSTG + soff[j]) * 2, Ah + (size_t)(bm + grow[j]) * K + k0 + gcol[j]);
                cp16(nxt + (1 * GSTG + soff[j]) * 2, Al + (size_t)(bm + grow[j]) * K + k0 + gcol[j]);
                cp16(nxt + (2 * GSTG + soff[j]) * 2, Bh + (size_t)(bn + grow[j]) * K + k0 + gcol[j]);
                cp16(nxt + (3 * GSTG + soff[j]) * 2, Bl + (size_t)(bn + grow[j]) * K + k0 + gcol[j]);
            }
            CP_COMMIT();
        }

        const __nv_bfloat16* sAh = cur;
        const __nv_bfloat16* sAl = cur + 1 * GSTG;
        const __nv_bfloat16* sBh = cur + 2 * GSTG;
        const __nv_bfloat16* sBl = cur + 3 * GSTG;

#pragma unroll
        for (int kk = 0; kk < 32; kk += 16) {
            uint32_t afh[2][4], afl[2][4];
            const int acol = kk + lcoff;
            ldsm4(afh[0], &sAh[(wm + lrow     ) * GPAD + acol]);
            ldsm4(afh[1], &sAh[(wm + 16 + lrow) * GPAD + acol]);
            ldsm4(afl[0], &sAl[(wm + lrow     ) * GPAD + acol]);
            ldsm4(afl[1], &sAl[(wm + 16 + lrow) * GPAD + acol]);
#pragma unroll
            for (int np = 0; np < 4; np++) {
                const int br = wn + np * 16 + brow;
                const int bc = kk + bcoff;
                uint32_t bh[4], bl[4];
                ldsm4(bh, &sBh[br * GPAD + bc]);
                ldsm4(bl, &sBl[br * GPAD + bc]);
#pragma unroll
                for (int mt = 0; mt < 2; mt++) {
                    mma16816(acc[mt][2 * np    ], afh[mt], bh);
                    mma16816(acc[mt][2 * np    ], afh[mt], bl);
                    mma16816(acc[mt][2 * np    ], afl[mt], bh);
                    mma16816(acc[mt][2 * np + 1], afh[mt], bh + 2);
                    mma16816(acc[mt][2 * np + 1], afh[mt], bl + 2);
                    mma16816(acc[mt][2 * np + 1], afl[mt], bh + 2);
                }
            }
        }
    }

#pragma unroll
    for (int mt = 0; mt < 2; mt++) {
        const int row = bm + wm + mt * 16 + grp;
#pragma unroll
        for (int nt = 0; nt < 8; nt++) {
            const int col = bn + wn + nt * 8 + tig * 2;
            *(float2*)&C[(size_t)row * N + col]       = make_float2(acc[mt][nt][0], acc[mt][nt][1]);
            *(float2*)&C[(size_t)(row + 8) * N + col] = make_float2(acc[mt][nt][2], acc[mt][nt][3]);
        }
    }
}

// ---------------------------------------------------------------------------
// RMSNorm + RoPE for Q: reads qkv fp32, writes bf16 hi/lo to (b,H,s,D),
// pre-scaled by 1/sqrt(D). One warp per row.
// ---------------------------------------------------------------------------
__global__ __launch_bounds__(256) void norm_rope_q(
    const float* __restrict__ qkv,
    __nv_bfloat16* __restrict__ oh, __nv_bfloat16* __restrict__ ol,
    const float* __restrict__ cs, const float* __restrict__ sn,
    const float* __restrict__ gamma)
{
    const int warp = (blockIdx.x * 256 + threadIdx.x) >> 5;
    const int lane = threadIdx.x & 31;
    const int h  = warp % NH;
    const int bs = warp / NH;
    const int sp = bs % SEQ;
    const int bi = bs / SEQ;

    const float* x = qkv + (size_t)bs * NQKV + h * HD;
    float e0 = x[lane], e1 = x[lane + 32], e2 = x[lane + 64], e3 = x[lane + 96];

    float ssq = e0 * e0 + e1 * e1 + e2 * e2 + e3 * e3;
#pragma unroll
    for (int o = 16; o; o >>= 1) ssq += __shfl_xor_sync(0xffffffffu, ssq, o);
    const float r = rsqrtf(ssq * (1.0f / HD) + 1e-6f);

    e0 *= r * gamma[lane];      e1 *= r * gamma[lane + 32];
    e2 *= r * gamma[lane + 64]; e3 *= r * gamma[lane + 96];

    const float* cp = cs + (size_t)bs * HD;
    const float* sg = sn + (size_t)bs * HD;
    float o4[4];
    o4[0] = (e0 * cp[lane]      - e2 * sg[lane])      * SM_SCALE;
    o4[1] = (e1 * cp[lane + 32] - e3 * sg[lane + 32]) * SM_SCALE;
    o4[2] = (e2 * cp[lane + 64] + e0 * sg[lane + 64]) * SM_SCALE;
    o4[3] = (e3 * cp[lane + 96] + e1 * sg[lane + 96]) * SM_SCALE;

    const size_t ob = (((size_t)bi * NH + h) * SEQ + sp) * HD;
#pragma unroll
    for (int j = 0; j < 4; j++) {
        __nv_bfloat16 hv = __float2bfloat16(o4[j]);
        oh[ob + lane + 32 * j] = hv;
        ol[ob + lane + 32 * j] = __float2bfloat16(o4[j] - __bfloat162float(hv));
    }
}

// ---------------------------------------------------------------------------
// RMSNorm + RoPE for K: writes fp32 (b,KV,s,D) into d_out AND bf16 hi/lo.
// ---------------------------------------------------------------------------
__global__ __launch_bounds__(256) void norm_rope_k(
    const float* __restrict__ qkv, float* __restrict__ kout,
    __nv_bfloat16* __restrict__ oh, __nv_bfloat16* __restrict__ ol,
    const float* __restrict__ cs, const float* __restrict__ sn,
    const float* __restrict__ gamma)
{
    const int warp = (blockIdx.x * 256 + threadIdx.x) >> 5;
    const int lane = threadIdx.x & 31;
    const int h  = warp % NKV;
    const int bs = warp / NKV;
    const int sp = bs % SEQ;
    const int bi = bs / SEQ;

    const float* x = qkv + (size_t)bs * NQKV + KOFF + h * HD;
    float e0 = x[lane], e1 = x[lane + 32], e2 = x[lane + 64], e3 = x[lane + 96];

    float ssq = e0 * e0 + e1 * e1 + e2 * e2 + e3 * e3;
#pragma unroll
    for (int o = 16; o; o >>= 1) ssq += __shfl_xor_sync(0xffffffffu, ssq, o);
    const float r = rsqrtf(ssq * (1.0f / HD) + 1e-6f);

    e0 *= r * gamma[lane];      e1 *= r * gamma[lane + 32];
    e2 *= r * gamma[lane + 64]; e3 *= r * gamma[lane + 96];

    const float* cp = cs + (size_t)bs * HD;
    const float* sg = sn + (size_t)bs * HD;
    float o4[4];
    o4[0] = e0 * cp[lane]      - e2 * sg[lane];
    o4[1] = e1 * cp[lane + 32] - e3 * sg[lane + 32];
    o4[2] = e2 * cp[lane + 64] + e0 * sg[lane + 64];
    o4[3] = e3 * cp[lane + 96] + e1 * sg[lane + 96];

    const size_t ob = (((size_t)bi * NKV + h) * SEQ + sp) * HD;
#pragma unroll
    for (int j = 0; j < 4; j++) {
        kout[ob + lane + 32 * j] = o4[j];
        __nv_bfloat16 hv = __float2bfloat16(o4[j]);
        oh[ob + lane + 32 * j] = hv;
        ol[ob + lane + 32 * j] = __float2bfloat16(o4[j] - __bfloat162float(hv));
    }
}

// ---------------------------------------------------------------------------
// V transpose (fp32): qkv V region -> (b,KV,s,D) in d_out
// ---------------------------------------------------------------------------
__global__ __launch_bounds__(256) void v_transpose(
    const float4* __restrict__ qkv4, float4* __restrict__ out)
{
    const size_t i = (size_t)blockIdx.x * 256 + threadIdx.x;
    const int d4 = (int)(i & 31);
    const int kh = (int)((i >> 5) & (NKV - 1));
    const int sp = (int)((i >> 8) & (SEQ - 1));
    const int bi = (int)(i >> 19);
    const size_t src = ((size_t)(bi * SEQ + sp) * NQKV + VOFF + kh * HD) / 4 + d4;
    const size_t dst = (((size_t)bi * NKV + kh) * SEQ + sp) * 32 + d4;
    out[dst] = qkv4[src];
}

// ---------------------------------------------------------------------------
// V transpose + split (bf16): qkv V region -> (b,KV,D,s) hi/lo
// ---------------------------------------------------------------------------
__global__ void vtrans_split(
    const float* __restrict__ qkv,
    __nv_bfloat16* __restrict__ vh, __nv_bfloat16* __restrict__ vl)
{
    __shared__ float t[32][33];
    const int s0 = blockIdx.x * 32, d0 = blockIdx.y * 32;
    const int bz = blockIdx.z;                 // bi*NKV + kh
    const int bi = bz / NKV, kh = bz % NKV;
    const int tx = threadIdx.x, ty = threadIdx.y;

#pragma unroll
    for (int j = 0; j < 4; j++) {
        int s = s0 + ty + j * 8;
        t[ty + j * 8][tx] =
            qkv[(size_t)(bi * SEQ + s) * NQKV + VOFF + kh * HD + d0 + tx];
    }
    __syncthreads();
#pragma unroll
    for (int j = 0; j < 4; j++) {
        int d = d0 + ty + j * 8;
        float v = t[tx][ty + j * 8];
        __nv_bfloat16 hv = __float2bfloat16(v);
        size_t idx = ((size_t)bz * HD + d) * SEQ + s0 + tx;
        vh[idx] = hv;
        vl[idx] = __float2bfloat16(v - __bfloat162float(hv));
    }
}

// ---------------------------------------------------------------------------
// Tensor-core causal flash attention, bf16 hi/lo split, ldmatrix loads.
// BM=BN=64, 128 threads (4 warps, 16 Q rows each).
// ---------------------------------------------------------------------------
constexpr int FQP = 136;  // pitch (bf16) for Q/K tiles
constexpr int FVP = 72;   // pitch (bf16) for Vt tiles
constexpr int FLASH_SMEM = (4 * 64 * FQP + 2 * 128 * FVP) * 2;  // 106496 B

__global__ __launch_bounds__(128, 2) void flash_mma(
    const __nv_bfloat16* __restrict__ Qh, const __nv_bfloat16* __restrict__ Ql,
    const __nv_bfloat16* __restrict__ Kh, const __nv_bfloat16* __restrict__ Kl,
    const __nv_bfloat16* __restrict__ Vh, const __nv_bfloat16* __restrict__ Vl,
    __nv_bfloat16* __restrict__ Oh, __nv_bfloat16* __restrict__ Ol)
{
    extern __shared__ __nv_bfloat16 sm[];
    __nv_bfloat16* sQh = sm;
    __nv_bfloat16* sQl = sQh + 64 * FQP;
    __nv_bfloat16* sKh = sQl + 64 * FQP;
    __nv_bfloat16* sKl = sKh + 64 * FQP;
    __nv_bfloat16* sVh = sKl + 64 * FQP;
    __nv_bfloat16* sVl = sVh + 128 * FVP;

    const int qtile = blockIdx.x;
    const int h     = blockIdx.y;
    const int bi    = blockIdx.z;
    const int kh    = h / GQ;
    const int tid   = threadIdx.x;
    const int lane  = tid & 31;
    const int wid   = tid >> 5;
    const int grp   = lane >> 2;
    const int tig   = lane & 3;
    const int q0    = qtile * 64;

    const int lrow  = lane & 15;
    const int lcoff = (lane >> 4) * 8;
    const int brow  = (lane & 7) + ((lane >> 4) << 3);
    const int bcoff = ((lane >> 3) & 1) * 8;

    {
        const __nv_bfloat16* qgh = Qh + (((size_t)bi * NH + h) * SEQ + q0) * HD;
        const __nv_bfloat16* qgl = Ql + (((size_t)bi * NH + h) * SEQ + q0) * HD;
        for (int i = tid; i < 64 * 16; i += 128) {
            int r = i >> 4, c = (i & 15) * 8;
            *(uint4*)&sQh[r * FQP + c] = *(const uint4*)&qgh[(size_t)r * HD + c];
            *(uint4*)&sQl[r * FQP + c] = *(const uint4*)&qgl[(size_t)r * HD + c];
        }
    }

    const __nv_bfloat16* kgh = Kh + (((size_t)bi * NKV + kh) * SEQ) * HD;
    const __nv_bfloat16* kgl = Kl + (((size_t)bi * NKV + kh) * SEQ) * HD;
    const __nv_bfloat16* vgh = Vh + (((size_t)bi * NKV + kh) * HD) * SEQ;
    const __nv_bfloat16* vgl = Vl + (((size_t)bi * NKV + kh) * HD) * SEQ;

    float o[16][4];
#pragma unroll
    for (int nt = 0; nt < 16; nt++)
#pragma unroll
        for (int e = 0; e < 4; e++) o[nt][e] = 0.f;
    float m0 = -1e30f, m1 = -1e30f, l0 = 0.f, l1 = 0.f;

    const int ntiles = qtile + 1;
    for (int t = 0; t < ntiles; ++t) {
        const int k0 = t * 64;
        __syncthreads();
        for (int i = tid; i < 64 * 16; i += 128) {
            int r = i >> 4, c = (i & 15) * 8;
            *(uint4*)&sKh[r * FQP + c] = *(const uint4*)&kgh[(size_t)(k0 + r) * HD + c];
            *(uint4*)&sKl[r * FQP + c] = *(const uint4*)&kgl[(size_t)(k0 + r) * HD + c];
        }
        for (int i = tid; i < 128 * 8; i += 128) {
            int r = i >> 3, c = (i & 7) * 8;
            *(uint4*)&sVh[r * FVP + c] = *(const uint4*)&vgh[(size_t)r * SEQ + k0 + c];
            *(uint4*)&sVl[r * FVP + c] = *(const uint4*)&vgl[(size_t)r * SEQ + k0 + c];
        }
        __syncthreads();

        float s[8][4];
#pragma unroll
        for (int nt = 0; nt < 8; nt++)
#pragma unroll
            for (int e = 0; e < 4; e++) s[nt][e] = 0.f;

#pragma unroll
        for (int kk = 0; kk < 128; kk += 16) {
            uint32_t ah[4], al[4];
            const int acol = kk + lcoff;
            ldsm4(ah, &sQh[(wid * 16 + lrow) * FQP + acol]);
            ldsm4(al, &sQl[(wid * 16 + lrow) * FQP + acol]);
#pragma unroll
            for (int np = 0; np < 4; np++) {
                const int br = np * 16 + brow;
                const int bc = kk + bcoff;
                uint32_t bh[4], bl[4];
                ldsm4(bh, &sKh[br * FQP + bc]);
                ldsm4(bl, &sKl[br * FQP + bc]);
                mma16816(s[2 * np    ], ah, bh);
                mma16816(s[2 * np    ], al, bh);
                mma16816(s[2 * np    ], ah, bl);
                mma16816(s[2 * np + 1], ah, bh + 2);
                mma16816(s[2 * np + 1], al, bh + 2);
                mma16816(s[2 * np + 1], ah, bl + 2);
            }
        }

        if (t == qtile) {
            const int r0 = q0 + wid * 16 + grp;
#pragma unroll
            for (int nt = 0; nt < 8; nt++) {
                const int c = k0 + nt * 8 + tig * 2;
                if (c     > r0)     s[nt][0] = -1e30f;
                if (c + 1 > r0)     s[nt][1] = -1e30f;
                if (c     > r0 + 8) s[nt][2] = -1e30f;
                if (c + 1 > r0 + 8) s[nt][3] = -1e30f;
            }
        }

        float mx0 = -1e30f, mx1 = -1e30f;
#pragma unroll
        for (int nt = 0; nt < 8; nt++) {
            mx0 = fmaxf(mx0, fmaxf(s[nt][0], s[nt][1]));
            mx1 = fmaxf(mx1, fmaxf(s[nt][2], s[nt][3]));
        }
        mx0 = fmaxf(mx0, __shfl_xor_sync(0xffffffffu, mx0, 1));
        mx0 = fmaxf(mx0, __shfl_xor_sync(0xffffffffu, mx0, 2));
        mx1 = fmaxf(mx1, __shfl_xor_sync(0xffffffffu, mx1, 1));
        mx1 = fmaxf(mx1, __shfl_xor_sync(0xffffffffu, mx1, 2));

        const float nm0 = fmaxf(m0, mx0);
        const float nm1 = fmaxf(m1, mx1);
        const float a0 = __expf(m0 - nm0);
        const float a1 = __expf(m1 - nm1);
        m0 = nm0; m1 = nm1;

        float rs0 = 0.f, rs1 = 0.f;
#pragma unroll
        for (int nt = 0; nt < 8; nt++) {
            s[nt][0] = __expf(s[nt][0] - m0);
            s[nt][1] = __expf(s[nt][1] - m0);
            s[nt][2] = __expf(s[nt][2] - m1);
            s[nt][3] = __expf(s[nt][3] - m1);
            rs0 += s[nt][0] + s[nt][1];
            rs1 += s[nt][2] + s[nt][3];
        }
        rs0 += __shfl_xor_sync(0xffffffffu, rs0, 1);
        rs0 += __shfl_xor_sync(0xffffffffu, rs0, 2);
        rs1 += __shfl_xor_sync(0xffffffffu, rs1, 1);
        rs1 += __shfl_xor_sync(0xffffffffu, rs1, 2);
        l0 = l0 * a0 + rs0;
        l1 = l1 * a1 + rs1;

#pragma unroll
        for (int nt = 0; nt < 16; nt++) {
            o[nt][0] *= a0; o[nt][1] *= a0;
            o[nt][2] *= a1; o[nt][3] *= a1;
        }

#pragma unroll
        for (int ks = 0; ks < 4; ks++) {
            uint32_t ph[4], pl[4];
            ph[0] = pack_hilo(s[2 * ks][0],     s[2 * ks][1],     pl[0]);
            ph[1] = pack_hilo(s[2 * ks][2],     s[2 * ks][3],     pl[1]);
            ph[2] = pack_hilo(s[2 * ks + 1][0], s[2 * ks + 1][1], pl[2]);
            ph[3] = pack_hilo(s[2 * ks + 1][2], s[2 * ks + 1][3], pl[3]);
            const int bc = ks * 16 + bcoff;
#pragma unroll
            for (int np = 0; np < 8; np++) {
                const int br = np * 16 + brow;
                uint32_t vh4[4], vl4[4];
                ldsm4(vh4, &sVh[br * FVP + bc]);
                ldsm4(vl4, &sVl[br * FVP + bc]);
                mma16816(o[2 * np    ], ph, vh4);
                mma16816(o[2 * np    ], pl, vh4);
                mma16816(o[2 * np    ], ph, vl4);
                mma16816(o[2 * np + 1], ph, vh4 + 2);
                mma16816(o[2 * np + 1], pl, vh4 + 2);
                mma16816(o[2 * np + 1], ph, vl4 + 2);
            }
        }
    }

    const float i0 = 1.0f / l0;
    const float i1 = 1.0f / l1;
    const size_t row0 = (size_t)bi * SEQ + q0 + wid * 16 + grp;
    const size_t row1 = row0 + 8;
    const int colb = h * HD + tig * 2;
#pragma unroll
    for (int nt = 0; nt < 16; nt++) {
        uint32_t lo;
        uint32_t hi = pack_hilo(o[nt][0] * i0, o[nt][1] * i0, lo);
        *(uint32_t*)&Oh[row0 * (NH * HD) + colb + nt * 8] = hi;
        *(uint32_t*)&Ol[row0 * (NH * HD) + colb + nt * 8] = lo;
        hi = pack_hilo(o[nt][2] * i1, o[nt][3] * i1, lo);
        *(uint32_t*)&Oh[row1 * (NH * HD) + colb + nt * 8] = hi;
        *(uint32_t*)&Ol[row1 * (NH * HD) + colb + nt * 8] = lo;
    }
}

// ---------------------------------------------------------------------------
// kernel_launch
// ---------------------------------------------------------------------------
extern "C" void kernel_launch(void* const* d_in, const int* in_sizes, int n_in,
                              void* d_out, int out_size)
{
    const float* hidden = (const float*)d_in[0];
    const float* cosb   = (const float*)d_in[1];
    const float* sinb   = (const float*)d_in[2];
    const float* wq     = (const float*)d_in[3];
    const float* wk     = (const float*)d_in[4];
    const float* wv     = (const float*)d_in[5];
    const float* wo     = (const float*)d_in[6];
    const float* qg     = (const float*)d_in[7];
    const float* kg     = (const float*)d_in[8];

    float* out  = (float*)d_out;
    float* kout = out  + (size_t)NB * SEQ * HDIM;
    float* vout = kout + (size_t)NB * NKV * SEQ * HD;

    __nv_bfloat16 *hidh, *hidl, *wqkvh, *wqkvl, *woh, *wol, *aoh, *aol;
    __nv_bfloat16 *qh, *ql, *kh, *kl, *vh, *vl;
    float *qkv;
    cudaGetSymbolAddress((void**)&hidh,  g_hid_h);
    cudaGetSymbolAddress((void**)&hidl,  g_hid_l);
    cudaGetSymbolAddress((void**)&wqkvh, g_wqkv_h);
    cudaGetSymbolAddress((void**)&wqkvl, g_wqkv_l);
    cudaGetSymbolAddress((void**)&woh,   g_wo_h);
    cudaGetSymbolAddress((void**)&wol,   g_wo_l);
    cudaGetSymbolAddress((void**)&aoh,   g_ao_h);
    cudaGetSymbolAddress((void**)&aol,   g_ao_l);
    cudaGetSymbolAddress((void**)&qkv,   g_qkv);
    cudaGetSymbolAddress((void**)&qh,    g_qh);
    cudaGetSymbolAddress((void**)&ql,    g_ql);
    cudaGetSymbolAddress((void**)&kh,    g_kh);
    cudaGetSymbolAddress((void**)&kl,    g_kl);
    cudaGetSymbolAddress((void**)&vh,    g_vh);
    cudaGetSymbolAddress((void**)&vl,    g_vl);

    cudaFuncSetAttribute(flash_mma, cudaFuncAttributeMaxDynamicSharedMemorySize, FLASH_SMEM);
    cudaFuncSetAttribute(gemm_bf16x2, cudaFuncAttributeMaxDynamicSharedMemorySize, GEMM_SMEM);

    // fp32 -> bf16 hi/lo splits
    const size_t nHid = (size_t)MROWS * HDIM;
    const size_t nWq  = (size_t)NH  * HD * HDIM;
    const size_t nWk  = (size_t)NKV * HD * HDIM;
    split_bf16<<<(int)(nHid / 1024), 256>>>((const float4*)hidden, hidh, hidl);
    split_bf16<<<(int)(nWq  / 1024), 256>>>((const float4*)wq, wqkvh, wqkvl);
    split_bf16<<<(int)(nWk  / 1024), 256>>>((const float4*)wk, wqkvh + nWq, wqkvl + nWq);
    split_bf16<<<(int)(nWk  / 1024), 256>>>((const float4*)wv, wqkvh + nWq + nWk, wqkvl + nWq + nWk);
    split_bf16<<<(int)(nWq  / 1024), 256>>>((const float4*)wo, woh, wol);

    // Fused QKV projection
    gemm_bf16x2<<<dim3(NQKV / 128, MROWS / 128), 256, GEMM_SMEM>>>(
        hidh, hidl, wqkvh, wqkvl, qkv, MROWS, NQKV, HDIM);

    // RMSNorm + RoPE -> bf16 hi/lo operands (+ fp32 K into d_out)
    norm_rope_q<<<(MROWS * NH ) / 8, 256>>>(qkv, qh, ql, cosb, sinb, qg);
    norm_rope_k<<<(MROWS * NKV) / 8, 256>>>(qkv, kout, kh, kl, cosb, sinb, kg);

    // V: fp32 into d_out's new_v; bf16 hi/lo transposed (b,KV,D,s)
    v_transpose<<<(NB * SEQ * NKV * HD / 4) / 256, 256>>>((const float4*)qkv, (float4*)vout);
    vtrans_split<<<dim3(SEQ / 32, HD / 32, NB * NKV), dim3(32, 8)>>>(qkv, vh, vl);

    // Tensor-core causal GQA flash attention -> bf16 hi/lo O
    flash_mma<<<dim3(SEQ / 64, NH, NB), 128, FLASH_SMEM>>>(
        qh, ql, kh, kl, vh, vl, aoh, aol);

    // Output projection
    gemm_bf16x2<<<dim3(HDIM / 128, MROWS / 128), 256, GEMM_SMEM>>>(
        aoh, aol, woh, wol, out, MROWS, HDIM, NH * HD);
}